// round 1
// baseline (speedup 1.0000x reference)
#include <cuda_runtime.h>
#include <cstddef>

// Problem constants
#define BT      16384      // B*T tokens
#define DMODEL  1024
#define NH      8
#define DHD     128        // head dim
#define CHUNKL  64
#define NCHUNK  128        // chunks per sequence (8192/64)
#define NBATCH  2
#define QSCALE  0.08838834764831843f   // 128^-0.5
#define RMSEPS  1e-5f

// Scratch (device globals; no allocation allowed)
__device__ float g_q[(size_t)BT * DMODEL];
__device__ float g_k[(size_t)BT * DMODEL];
__device__ float g_v[(size_t)BT * DMODEL];
__device__ float g_kv[(size_t)NBATCH * NCHUNK * NH * DHD * DHD]; // becomes S_excl in-place
__device__ float g_o[(size_t)BT * DMODEL];

// ---------------------------------------------------------------------------
// NT GEMM: C[M,N] = A[M,K] @ B[N,K]^T, all row-major, M%128==0, N%128==0, K%16==0
// 128x128 block tile, BK=16, 256 threads, 8x8 per thread (4+4 split).
// ---------------------------------------------------------------------------
__global__ __launch_bounds__(256) void gemm_nt(const float* __restrict__ A,
                                               const float* __restrict__ Bw,
                                               float* __restrict__ C,
                                               int M, int N, int K) {
    __shared__ float As[16 * 128];
    __shared__ float Bs[16 * 128];
    const int tid = threadIdx.x;
    const int m0 = blockIdx.y * 128;
    const int n0 = blockIdx.x * 128;
    const int ty = tid >> 4, tx = tid & 15;

    float acc[8][8];
#pragma unroll
    for (int i = 0; i < 8; i++)
#pragma unroll
        for (int j = 0; j < 8; j++) acc[i][j] = 0.f;

    for (int k0 = 0; k0 < K; k0 += 16) {
#pragma unroll
        for (int l = 0; l < 2; l++) {
            int f = tid + l * 256;          // 0..511 float4 slots
            int row = f >> 2;               // 0..127
            int kq = (f & 3) * 4;           // 0,4,8,12
            float4 va = *(const float4*)(A + (size_t)(m0 + row) * K + k0 + kq);
            As[(kq + 0) * 128 + row] = va.x;
            As[(kq + 1) * 128 + row] = va.y;
            As[(kq + 2) * 128 + row] = va.z;
            As[(kq + 3) * 128 + row] = va.w;
            float4 vb = *(const float4*)(Bw + (size_t)(n0 + row) * K + k0 + kq);
            Bs[(kq + 0) * 128 + row] = vb.x;
            Bs[(kq + 1) * 128 + row] = vb.y;
            Bs[(kq + 2) * 128 + row] = vb.z;
            Bs[(kq + 3) * 128 + row] = vb.w;
        }
        __syncthreads();
#pragma unroll
        for (int kk = 0; kk < 16; kk++) {
            float a[8], b[8];
            *(float4*)&a[0] = *(float4*)&As[kk * 128 + ty * 4];
            *(float4*)&a[4] = *(float4*)&As[kk * 128 + ty * 4 + 64];
            *(float4*)&b[0] = *(float4*)&Bs[kk * 128 + tx * 4];
            *(float4*)&b[4] = *(float4*)&Bs[kk * 128 + tx * 4 + 64];
#pragma unroll
            for (int i = 0; i < 8; i++)
#pragma unroll
                for (int j = 0; j < 8; j++) acc[i][j] = fmaf(a[i], b[j], acc[i][j]);
        }
        __syncthreads();
    }

#pragma unroll
    for (int iq = 0; iq < 2; iq++)
#pragma unroll
        for (int i = 0; i < 4; i++) {
            int m = m0 + iq * 64 + ty * 4 + i;
#pragma unroll
            for (int jq = 0; jq < 2; jq++) {
                float4 v;
                v.x = acc[iq * 4 + i][jq * 4 + 0];
                v.y = acc[iq * 4 + i][jq * 4 + 1];
                v.z = acc[iq * 4 + i][jq * 4 + 2];
                v.w = acc[iq * 4 + i][jq * 4 + 3];
                *(float4*)(C + (size_t)m * N + n0 + jq * 64 + tx * 4) = v;
            }
        }
}

// ---------------------------------------------------------------------------
// Per-head Hadamard feature map, in-place on X (layout [BT][DMODEL]):
//   X[t, h*128+n] = (x@W1^T + b1)[n] * (x@W2^T + b2)[n] * scale
// grid: (BT/64, NH); block tile 64 tokens x 128 out features, BK=16.
// ---------------------------------------------------------------------------
__global__ __launch_bounds__(256) void featmap(float* __restrict__ X,
                                               const float* __restrict__ W1,
                                               const float* __restrict__ B1,
                                               const float* __restrict__ W2,
                                               const float* __restrict__ B2,
                                               float scale) {
    __shared__ float qs[16 * 64];     // [k][token]
    __shared__ float w1s[16 * 128];   // [k][n]
    __shared__ float w2s[16 * 128];
    const int tid = threadIdx.x;
    const int h = blockIdx.y;
    const int t0 = blockIdx.x * 64;
    const int ty = tid >> 4, tx = tid & 15;
    const int colbase = h * DHD;

    float acc1[4][8], acc2[4][8];
#pragma unroll
    for (int i = 0; i < 4; i++)
#pragma unroll
        for (int j = 0; j < 8; j++) { acc1[i][j] = 0.f; acc2[i][j] = 0.f; }

    for (int k0 = 0; k0 < DHD; k0 += 16) {
        {   // q tile: 64x16 = 256 float4, 1 per thread, transpose into qs[k][t]
            int f = tid;
            int row = f >> 2;
            int kq = (f & 3) * 4;
            float4 v = *(const float4*)(X + (size_t)(t0 + row) * DMODEL + colbase + k0 + kq);
            qs[(kq + 0) * 64 + row] = v.x;
            qs[(kq + 1) * 64 + row] = v.y;
            qs[(kq + 2) * 64 + row] = v.z;
            qs[(kq + 3) * 64 + row] = v.w;
        }
#pragma unroll
        for (int l = 0; l < 2; l++) {  // weight tiles: 128x16 = 512 float4
            int f = tid + l * 256;
            int row = f >> 2;
            int kq = (f & 3) * 4;
            float4 v1 = *(const float4*)(W1 + (size_t)row * DHD + k0 + kq);
            w1s[(kq + 0) * 128 + row] = v1.x;
            w1s[(kq + 1) * 128 + row] = v1.y;
            w1s[(kq + 2) * 128 + row] = v1.z;
            w1s[(kq + 3) * 128 + row] = v1.w;
            float4 v2 = *(const float4*)(W2 + (size_t)row * DHD + k0 + kq);
            w2s[(kq + 0) * 128 + row] = v2.x;
            w2s[(kq + 1) * 128 + row] = v2.y;
            w2s[(kq + 2) * 128 + row] = v2.z;
            w2s[(kq + 3) * 128 + row] = v2.w;
        }
        __syncthreads();
#pragma unroll
        for (int kk = 0; kk < 16; kk++) {
            float a[4], b1v[8], b2v[8];
            *(float4*)&a[0] = *(float4*)&qs[kk * 64 + ty * 4];
            *(float4*)&b1v[0] = *(float4*)&w1s[kk * 128 + tx * 8];
            *(float4*)&b1v[4] = *(float4*)&w1s[kk * 128 + tx * 8 + 4];
            *(float4*)&b2v[0] = *(float4*)&w2s[kk * 128 + tx * 8];
            *(float4*)&b2v[4] = *(float4*)&w2s[kk * 128 + tx * 8 + 4];
#pragma unroll
            for (int i = 0; i < 4; i++)
#pragma unroll
                for (int j = 0; j < 8; j++) {
                    acc1[i][j] = fmaf(a[i], b1v[j], acc1[i][j]);
                    acc2[i][j] = fmaf(a[i], b2v[j], acc2[i][j]);
                }
        }
        __syncthreads();
    }

    float bb1[8], bb2[8];
#pragma unroll
    for (int j = 0; j < 8; j++) {
        bb1[j] = B1[tx * 8 + j];
        bb2[j] = B2[tx * 8 + j];
    }
#pragma unroll
    for (int i = 0; i < 4; i++) {
        int t = t0 + ty * 4 + i;
        float out[8];
#pragma unroll
        for (int j = 0; j < 8; j++)
            out[j] = (acc1[i][j] + bb1[j]) * (acc2[i][j] + bb2[j]) * scale;
        *(float4*)(X + (size_t)t * DMODEL + colbase + tx * 8)     = *(float4*)&out[0];
        *(float4*)(X + (size_t)t * DMODEL + colbase + tx * 8 + 4) = *(float4*)&out[4];
    }
}

// ---------------------------------------------------------------------------
// Per-chunk kv: KV[b,n,h,dk,dv] = sum_s phik[s,dk]*v[s,dv], s over 64.
// grid: NBATCH*NCHUNK*NH blocks; 128x128 output, 8x8 per thread.
// ---------------------------------------------------------------------------
__global__ __launch_bounds__(256) void chunk_kv(const float* __restrict__ Kf,
                                                const float* __restrict__ V,
                                                float* __restrict__ KV) {
    __shared__ float ks[16 * 128];
    __shared__ float vs[16 * 128];
    const int tid = threadIdx.x;
    int idx = blockIdx.x;
    int h = idx % NH;
    int n = (idx / NH) % NCHUNK;
    int b = idx / (NH * NCHUNK);
    const int ty = tid >> 4, tx = tid & 15;
    const size_t tokenbase = (size_t)b * 8192 + (size_t)n * CHUNKL;
    const int col = h * DHD;

    float acc[8][8];
#pragma unroll
    for (int i = 0; i < 8; i++)
#pragma unroll
        for (int j = 0; j < 8; j++) acc[i][j] = 0.f;

    for (int s0 = 0; s0 < CHUNKL; s0 += 16) {
#pragma unroll
        for (int l = 0; l < 2; l++) {
            int f = tid + l * 256;
            int ss = f >> 5;
            int d4 = (f & 31) * 4;
            *(float4*)&ks[ss * 128 + d4] =
                *(const float4*)(Kf + (tokenbase + s0 + ss) * DMODEL + col + d4);
            *(float4*)&vs[ss * 128 + d4] =
                *(const float4*)(V + (tokenbase + s0 + ss) * DMODEL + col + d4);
        }
        __syncthreads();
#pragma unroll
        for (int ss = 0; ss < 16; ss++) {
            float a[8], bv[8];
            *(float4*)&a[0] = *(float4*)&ks[ss * 128 + ty * 4];
            *(float4*)&a[4] = *(float4*)&ks[ss * 128 + ty * 4 + 64];
            *(float4*)&bv[0] = *(float4*)&vs[ss * 128 + tx * 4];
            *(float4*)&bv[4] = *(float4*)&vs[ss * 128 + tx * 4 + 64];
#pragma unroll
            for (int i = 0; i < 8; i++)
#pragma unroll
                for (int j = 0; j < 8; j++) acc[i][j] = fmaf(a[i], bv[j], acc[i][j]);
        }
        __syncthreads();
    }

    size_t base = ((size_t)(b * NCHUNK + n) * NH + h) * (DHD * DHD);
#pragma unroll
    for (int iq = 0; iq < 2; iq++)
#pragma unroll
        for (int i = 0; i < 4; i++) {
            int dk = iq * 64 + ty * 4 + i;
#pragma unroll
            for (int jq = 0; jq < 2; jq++) {
                float4 v;
                v.x = acc[iq * 4 + i][jq * 4 + 0];
                v.y = acc[iq * 4 + i][jq * 4 + 1];
                v.z = acc[iq * 4 + i][jq * 4 + 2];
                v.w = acc[iq * 4 + i][jq * 4 + 3];
                *(float4*)(KV + base + (size_t)dk * DHD + jq * 64 + tx * 4) = v;
            }
        }
}

// ---------------------------------------------------------------------------
// In-place exclusive cumsum over chunk axis n: KV[b,n,h,:,:] <- sum_{m<n} KV[b,m,h,:,:]
// grid: (NBATCH*NH, DHD*DHD/256), 256 threads.
// ---------------------------------------------------------------------------
__global__ void cumsum_excl(float* __restrict__ KV) {
    int bh = blockIdx.x;
    int b = bh / NH, h = bh % NH;
    int i = blockIdx.y * 256 + threadIdx.x;  // 0..16383
    float acc = 0.f;
    for (int n = 0; n < NCHUNK; n++) {
        size_t idx = ((size_t)(b * NCHUNK + n) * NH + h) * (DHD * DHD) + i;
        float v = KV[idx];
        KV[idx] = acc;
        acc += v;
    }
}

// ---------------------------------------------------------------------------
// Per-chunk attention: O[c,v] = sum_{s<=c} (q_c . k_s) * V[s,v] + sum_k q[c,k]*S[k,v]
// grid: NBATCH*NCHUNK*NH blocks, 256 threads.
// ---------------------------------------------------------------------------
__global__ __launch_bounds__(256) void chunk_attn(const float* __restrict__ Q,
                                                  const float* __restrict__ Kf,
                                                  const float* __restrict__ V,
                                                  const float* __restrict__ S,
                                                  float* __restrict__ O) {
    __shared__ float sA[64 * 64];   // masked attention scores
    __shared__ float sQ[16 * 64];   // [k][c]
    __shared__ float sT[16 * 128];  // k tile (16x64 used) / v tile / S tile
    const int tid = threadIdx.x;
    int idx = blockIdx.x;
    int h = idx % NH;
    int n = (idx / NH) % NCHUNK;
    int b = idx / (NH * NCHUNK);
    const int ty = tid >> 4, tx = tid & 15;
    const size_t tokenbase = (size_t)b * 8192 + (size_t)n * CHUNKL;
    const int col = h * DHD;

    // ---- Step A: A[c,s] = sum_k q[c,k]*k[s,k]
    float accA[4][4];
#pragma unroll
    for (int i = 0; i < 4; i++)
#pragma unroll
        for (int j = 0; j < 4; j++) accA[i][j] = 0.f;

    for (int k0 = 0; k0 < DHD; k0 += 16) {
        {
            int f = tid;
            int row = f >> 2;
            int kq = (f & 3) * 4;
            float4 vq = *(const float4*)(Q + (tokenbase + row) * DMODEL + col + k0 + kq);
            sQ[(kq + 0) * 64 + row] = vq.x;
            sQ[(kq + 1) * 64 + row] = vq.y;
            sQ[(kq + 2) * 64 + row] = vq.z;
            sQ[(kq + 3) * 64 + row] = vq.w;
            float4 vk = *(const float4*)(Kf + (tokenbase + row) * DMODEL + col + k0 + kq);
            sT[(kq + 0) * 64 + row] = vk.x;
            sT[(kq + 1) * 64 + row] = vk.y;
            sT[(kq + 2) * 64 + row] = vk.z;
            sT[(kq + 3) * 64 + row] = vk.w;
        }
        __syncthreads();
#pragma unroll
        for (int kk = 0; kk < 16; kk++) {
            float a[4], bk[4];
            *(float4*)a = *(float4*)&sQ[kk * 64 + ty * 4];
            *(float4*)bk = *(float4*)&sT[kk * 64 + tx * 4];
#pragma unroll
            for (int i = 0; i < 4; i++)
#pragma unroll
                for (int j = 0; j < 4; j++) accA[i][j] = fmaf(a[i], bk[j], accA[i][j]);
        }
        __syncthreads();
    }
#pragma unroll
    for (int i = 0; i < 4; i++) {
        int c = ty * 4 + i;
#pragma unroll
        for (int j = 0; j < 4; j++) {
            int s = tx * 4 + j;
            sA[c * 64 + s] = (s <= c) ? accA[i][j] : 0.f;
        }
    }
    __syncthreads();

    // ---- Step B: O = A@V + Q@S
    float acc[4][8];
#pragma unroll
    for (int i = 0; i < 4; i++)
#pragma unroll
        for (int j = 0; j < 8; j++) acc[i][j] = 0.f;

    // B1: A @ V   (K = 64)
    for (int s0 = 0; s0 < CHUNKL; s0 += 16) {
#pragma unroll
        for (int l = 0; l < 2; l++) {
            int f = tid + l * 256;
            int ss = f >> 5;
            int d4 = (f & 31) * 4;
            *(float4*)&sT[ss * 128 + d4] =
                *(const float4*)(V + (tokenbase + s0 + ss) * DMODEL + col + d4);
        }
        __syncthreads();
#pragma unroll
        for (int ss = 0; ss < 16; ss++) {
            float bb[8];
            *(float4*)&bb[0] = *(float4*)&sT[ss * 128 + tx * 8];
            *(float4*)&bb[4] = *(float4*)&sT[ss * 128 + tx * 8 + 4];
#pragma unroll
            for (int i = 0; i < 4; i++) {
                float aa = sA[(ty * 4 + i) * 64 + s0 + ss];
#pragma unroll
                for (int j = 0; j < 8; j++) acc[i][j] = fmaf(aa, bb[j], acc[i][j]);
            }
        }
        __syncthreads();
    }

    // B2: Q @ S_excl  (K = 128)
    size_t Sbase = ((size_t)(b * NCHUNK + n) * NH + h) * (DHD * DHD);
    for (int k0 = 0; k0 < DHD; k0 += 16) {
        {
            int f = tid;
            int row = f >> 2;
            int kq = (f & 3) * 4;
            float4 vq = *(const float4*)(Q + (tokenbase + row) * DMODEL + col + k0 + kq);
            sQ[(kq + 0) * 64 + row] = vq.x;
            sQ[(kq + 1) * 64 + row] = vq.y;
            sQ[(kq + 2) * 64 + row] = vq.z;
            sQ[(kq + 3) * 64 + row] = vq.w;
        }
#pragma unroll
        for (int l = 0; l < 2; l++) {
            int f = tid + l * 256;
            int kk = f >> 5;
            int d4 = (f & 31) * 4;
            *(float4*)&sT[kk * 128 + d4] =
                *(const float4*)(S + Sbase + (size_t)(k0 + kk) * DHD + d4);
        }
        __syncthreads();
#pragma unroll
        for (int kk = 0; kk < 16; kk++) {
            float a[4], bb[8];
            *(float4*)a = *(float4*)&sQ[kk * 64 + ty * 4];
            *(float4*)&bb[0] = *(float4*)&sT[kk * 128 + tx * 8];
            *(float4*)&bb[4] = *(float4*)&sT[kk * 128 + tx * 8 + 4];
#pragma unroll
            for (int i = 0; i < 4; i++)
#pragma unroll
                for (int j = 0; j < 8; j++) acc[i][j] = fmaf(a[i], bb[j], acc[i][j]);
        }
        __syncthreads();
    }

#pragma unroll
    for (int i = 0; i < 4; i++) {
        size_t t = tokenbase + ty * 4 + i;
        *(float4*)(O + t * DMODEL + col + tx * 8)     = *(float4*)&acc[i][0];
        *(float4*)(O + t * DMODEL + col + tx * 8 + 4) = *(float4*)&acc[i][4];
    }
}

// ---------------------------------------------------------------------------
// RMSNorm per (token, head) row of 128, in-place. One warp per row.
// grid: BT*NH/8 blocks of (32,8).
// ---------------------------------------------------------------------------
__global__ void rmsnorm_kernel(float* __restrict__ O, const float* __restrict__ W) {
    int row = blockIdx.x * 8 + threadIdx.y;   // 0 .. BT*NH-1
    int t = row / NH, h = row % NH;
    int lane = threadIdx.x;
    float* p = O + (size_t)t * DMODEL + h * DHD + lane * 4;
    float4 x = *(float4*)p;
    float ss = x.x * x.x + x.y * x.y + x.z * x.z + x.w * x.w;
#pragma unroll
    for (int off = 16; off > 0; off >>= 1)
        ss += __shfl_xor_sync(0xffffffffu, ss, off);
    float r = rsqrtf(ss * (1.0f / 128.0f) + RMSEPS);
    float4 w = *(const float4*)(W + lane * 4);
    x.x *= r * w.x; x.y *= r * w.y; x.z *= r * w.z; x.w *= r * w.w;
    *(float4*)p = x;
}

// ---------------------------------------------------------------------------
extern "C" void kernel_launch(void* const* d_in, const int* in_sizes, int n_in,
                              void* d_out, int out_size) {
    const float* hidden = (const float*)d_in[0];
    // d_in[1] = output_attentions (ignored)
    const float* q_w    = (const float*)d_in[2];
    const float* k_w    = (const float*)d_in[3];
    const float* v_w    = (const float*)d_in[4];
    const float* o_w    = (const float*)d_in[5];
    const float* fmq_w1 = (const float*)d_in[6];
    const float* fmq_b1 = (const float*)d_in[7];
    const float* fmq_w2 = (const float*)d_in[8];
    const float* fmq_b2 = (const float*)d_in[9];
    const float* fmk_w1 = (const float*)d_in[10];
    const float* fmk_b1 = (const float*)d_in[11];
    const float* fmk_w2 = (const float*)d_in[12];
    const float* fmk_b2 = (const float*)d_in[13];
    const float* rms_w  = (const float*)d_in[14];
    float* out = (float*)d_out;

    float *q, *k, *v, *kv, *o;
    cudaGetSymbolAddress((void**)&q,  g_q);
    cudaGetSymbolAddress((void**)&k,  g_k);
    cudaGetSymbolAddress((void**)&v,  g_v);
    cudaGetSymbolAddress((void**)&kv, g_kv);
    cudaGetSymbolAddress((void**)&o,  g_o);

    dim3 gemm_grid(DMODEL / 128, BT / 128);   // (8, 128)
    gemm_nt<<<gemm_grid, 256>>>(hidden, q_w, q, BT, DMODEL, DMODEL);
    gemm_nt<<<gemm_grid, 256>>>(hidden, k_w, k, BT, DMODEL, DMODEL);
    gemm_nt<<<gemm_grid, 256>>>(hidden, v_w, v, BT, DMODEL, DMODEL);

    dim3 fm_grid(BT / 64, NH);                // (256, 8)
    featmap<<<fm_grid, 256>>>(q, fmq_w1, fmq_b1, fmq_w2, fmq_b2, QSCALE);
    featmap<<<fm_grid, 256>>>(k, fmk_w1, fmk_b1, fmk_w2, fmk_b2, 1.0f);

    chunk_kv<<<NBATCH * NCHUNK * NH, 256>>>(k, v, kv);

    dim3 cs_grid(NBATCH * NH, (DHD * DHD) / 256);   // (16, 64)
    cumsum_excl<<<cs_grid, 256>>>(kv);

    chunk_attn<<<NBATCH * NCHUNK * NH, 256>>>(q, k, v, kv, o);

    rmsnorm_kernel<<<(BT * NH) / 8, dim3(32, 8)>>>(o, rms_w);

    gemm_nt<<<gemm_grid, 256>>>(o, o_w, out, BT, DMODEL, DMODEL);
}

// round 3
// speedup vs baseline: 1.5393x; 1.5393x over previous
#include <cuda_runtime.h>
#include <cuda_bf16.h>
#include <cstdint>
#include <cstddef>

// Problem constants
#define BT      16384
#define DMODEL  1024
#define NH      8
#define DHD     128
#define CHUNKL  64
#define NCHUNK  128
#define NBATCH  2
#define QSCALE  0.08838834764831843f
#define RMSEPS  1e-5f

// Scratch
__device__ float g_q[(size_t)BT * DMODEL];
__device__ float g_k[(size_t)BT * DMODEL];
__device__ float g_v[(size_t)BT * DMODEL];
__device__ float g_kv[(size_t)NBATCH * NCHUNK * NH * DHD * DHD];
__device__ float g_o[(size_t)BT * DMODEL];
__device__ __nv_bfloat16 g_ahi[(size_t)BT * DMODEL];
__device__ __nv_bfloat16 g_alo[(size_t)BT * DMODEL];
__device__ __nv_bfloat16 g_whi[(size_t)DMODEL * DMODEL];
__device__ __nv_bfloat16 g_wlo[(size_t)DMODEL * DMODEL];

#define SMEM_SWIZZLE_128B(off) ((off) ^ (((off) >> 3) & 0x70))

__device__ __forceinline__ uint32_t smem_u32(const void* p) {
    uint32_t a;
    asm("{ .reg .u64 t; cvta.to.shared.u64 t, %1; cvt.u32.u64 %0, t; }" : "=r"(a) : "l"(p));
    return a;
}

__device__ __forceinline__ void ldsm_x4(uint32_t addr, uint32_t& r0, uint32_t& r1,
                                        uint32_t& r2, uint32_t& r3) {
    asm volatile("ldmatrix.sync.aligned.m8n8.x4.shared.b16 {%0,%1,%2,%3}, [%4];"
                 : "=r"(r0), "=r"(r1), "=r"(r2), "=r"(r3) : "r"(addr));
}

__device__ __forceinline__ void mma_bf16(float* d, const uint32_t* a, const uint32_t* b) {
    asm volatile(
        "mma.sync.aligned.m16n8k16.row.col.f32.bf16.bf16.f32 "
        "{%0,%1,%2,%3}, {%4,%5,%6,%7}, {%8,%9}, {%0,%1,%2,%3};"
        : "+f"(d[0]), "+f"(d[1]), "+f"(d[2]), "+f"(d[3])
        : "r"(a[0]), "r"(a[1]), "r"(a[2]), "r"(a[3]), "r"(b[0]), "r"(b[1]));
}

// ---------------------------------------------------------------------------
// fp32 -> (hi, lo) bf16 split
// ---------------------------------------------------------------------------
__global__ void split_f32(const float* __restrict__ x, __nv_bfloat16* __restrict__ hi,
                          __nv_bfloat16* __restrict__ lo, int n) {
    int i = (blockIdx.x * blockDim.x + threadIdx.x) * 4;
    if (i >= n) return;
    float4 v = *(const float4*)(x + i);
    __nv_bfloat16 h0 = __float2bfloat16(v.x);
    __nv_bfloat16 h1 = __float2bfloat16(v.y);
    __nv_bfloat16 h2 = __float2bfloat16(v.z);
    __nv_bfloat16 h3 = __float2bfloat16(v.w);
    __nv_bfloat16 l0 = __float2bfloat16(v.x - __bfloat162float(h0));
    __nv_bfloat16 l1 = __float2bfloat16(v.y - __bfloat162float(h1));
    __nv_bfloat16 l2 = __float2bfloat16(v.z - __bfloat162float(h2));
    __nv_bfloat16 l3 = __float2bfloat16(v.w - __bfloat162float(h3));
    __nv_bfloat162 hp0 = __halves2bfloat162(h0, h1), hp1 = __halves2bfloat162(h2, h3);
    __nv_bfloat162 lp0 = __halves2bfloat162(l0, l1), lp1 = __halves2bfloat162(l2, l3);
    *(uint2*)(hi + i) = make_uint2(*(uint32_t*)&hp0, *(uint32_t*)&hp1);
    *(uint2*)(lo + i) = make_uint2(*(uint32_t*)&lp0, *(uint32_t*)&lp1);
}

// ---------------------------------------------------------------------------
// HMMA GEMM: C[M,N] = (Ahi+Alo)[M,K] @ (Bhi+Blo)[N,K]^T, fp32 accumulate.
// 128x128 CTA tile, BK=64, 8 warps (warp tile 32x64), SW128 smem + ldmatrix.
// ---------------------------------------------------------------------------
#define GEMM_SMEM_BYTES (65536 + 1024)

__global__ __launch_bounds__(256) void gemm_mma(const __nv_bfloat16* __restrict__ Ahi,
                                                const __nv_bfloat16* __restrict__ Alo,
                                                const __nv_bfloat16* __restrict__ Bhi,
                                                const __nv_bfloat16* __restrict__ Blo,
                                                float* __restrict__ C,
                                                int M, int N, int K) {
    extern __shared__ char dynraw[];
    char* smem = (char*)(((uintptr_t)dynraw + 1023) & ~(uintptr_t)1023);

    const int tid = threadIdx.x;
    const int wid = tid >> 5;
    const int lane = tid & 31;
    const int n0 = blockIdx.x * 128;
    const int m0 = blockIdx.y * 128;
    const int wm = (wid & 3) * 32;        // warp row origin in CTA tile
    const int wn = (wid >> 2) * 64;       // warp col origin

    const uint32_t sAh = smem_u32(smem);
    const uint32_t sAl = sAh + 16384;
    const uint32_t sBh = sAh + 32768;
    const uint32_t sBl = sAh + 49152;

    float acc[2][8][4];
#pragma unroll
    for (int i = 0; i < 2; i++)
#pragma unroll
        for (int j = 0; j < 8; j++)
#pragma unroll
            for (int r = 0; r < 4; r++) acc[i][j][r] = 0.f;

    const char* srcA_h = (const char*)(Ahi + (size_t)m0 * K);
    const char* srcA_l = (const char*)(Alo + (size_t)m0 * K);
    const char* srcB_h = (const char*)(Bhi + (size_t)n0 * K);
    const char* srcB_l = (const char*)(Blo + (size_t)n0 * K);
    const size_t rowbytes = (size_t)K * 2;

    // ldmatrix lane addressing precompute
    const int mat = lane >> 3;            // 0..3
    const int mrow = lane & 7;            // row within 8x8 tile

    const int nkt = K >> 6;
    for (int kt = 0; kt < nkt; kt++) {
        const size_t kbyte = (size_t)(kt << 6) * 2;
        // load 4 tiles of 128 rows x 128B
#pragma unroll
        for (int l = 0; l < 4; l++) {
            int u = tid + 256 * l;
            int row = u >> 3;
            int cb = (u & 7) * 16;
            uint32_t dsw = SMEM_SWIZZLE_128B((uint32_t)(row * 128 + cb));
            size_t src_off = (size_t)row * rowbytes + kbyte + cb;
            *(uint4*)(smem + 0     + dsw) = *(const uint4*)(srcA_h + src_off);
            *(uint4*)(smem + 16384 + dsw) = *(const uint4*)(srcA_l + src_off);
            *(uint4*)(smem + 32768 + dsw) = *(const uint4*)(srcB_h + src_off);
            *(uint4*)(smem + 49152 + dsw) = *(const uint4*)(srcB_l + src_off);
        }
        __syncthreads();

#pragma unroll
        for (int kc = 0; kc < 4; kc++) {
            const int kb0 = kc * 32;   // byte offset of this k16 within 128B row

            // A fragments: 2 m16 tiles, hi + lo
            uint32_t ah[2][4], al[2][4];
#pragma unroll
            for (int i = 0; i < 2; i++) {
                int arow = wm + i * 16 + (mat & 1) * 8 + mrow;
                int akb = kb0 + (mat >> 1) * 16;
                uint32_t off = SMEM_SWIZZLE_128B((uint32_t)(arow * 128 + akb));
                ldsm_x4(sAh + off, ah[i][0], ah[i][1], ah[i][2], ah[i][3]);
                ldsm_x4(sAl + off, al[i][0], al[i][1], al[i][2], al[i][3]);
            }

            // B: 4 n16 pairs
#pragma unroll
            for (int p = 0; p < 4; p++) {
                int brow = wn + p * 16 + (mat >> 1) * 8 + mrow;
                int bkb = kb0 + (mat & 1) * 16;
                uint32_t off = SMEM_SWIZZLE_128B((uint32_t)(brow * 128 + bkb));
                uint32_t bh[4], bl[4];
                ldsm_x4(sBh + off, bh[0], bh[1], bh[2], bh[3]);
                ldsm_x4(sBl + off, bl[0], bl[1], bl[2], bl[3]);
#pragma unroll
                for (int i = 0; i < 2; i++) {
                    mma_bf16(acc[i][2 * p],     ah[i], &bh[0]);   // hi*hi
                    mma_bf16(acc[i][2 * p],     al[i], &bh[0]);   // lo*hi
                    mma_bf16(acc[i][2 * p],     ah[i], &bl[0]);   // hi*lo
                    mma_bf16(acc[i][2 * p + 1], ah[i], &bh[2]);
                    mma_bf16(acc[i][2 * p + 1], al[i], &bh[2]);
                    mma_bf16(acc[i][2 * p + 1], ah[i], &bl[2]);
                }
            }
        }
        __syncthreads();
    }

    // Epilogue: direct global stores (float2 per fragment row)
    const int crow = lane >> 2;
    const int ccol = (lane & 3) * 2;
#pragma unroll
    for (int i = 0; i < 2; i++) {
        int m = m0 + wm + i * 16 + crow;
#pragma unroll
        for (int j = 0; j < 8; j++) {
            int n = n0 + wn + j * 8 + ccol;
            *(float2*)(C + (size_t)m * N + n) = make_float2(acc[i][j][0], acc[i][j][1]);
            *(float2*)(C + (size_t)(m + 8) * N + n) = make_float2(acc[i][j][2], acc[i][j][3]);
        }
    }
}

// ---------------------------------------------------------------------------
// Per-head Hadamard feature map (SIMT fp32, unchanged)
// ---------------------------------------------------------------------------
__global__ __launch_bounds__(256) void featmap(float* __restrict__ X,
                                               const float* __restrict__ W1,
                                               const float* __restrict__ B1,
                                               const float* __restrict__ W2,
                                               const float* __restrict__ B2,
                                               float scale) {
    __shared__ float qs[16 * 64];
    __shared__ float w1s[16 * 128];
    __shared__ float w2s[16 * 128];
    const int tid = threadIdx.x;
    const int h = blockIdx.y;
    const int t0 = blockIdx.x * 64;
    const int ty = tid >> 4, tx = tid & 15;
    const int colbase = h * DHD;

    float acc1[4][8], acc2[4][8];
#pragma unroll
    for (int i = 0; i < 4; i++)
#pragma unroll
        for (int j = 0; j < 8; j++) { acc1[i][j] = 0.f; acc2[i][j] = 0.f; }

    for (int k0 = 0; k0 < DHD; k0 += 16) {
        {
            int f = tid;
            int row = f >> 2;
            int kq = (f & 3) * 4;
            float4 v = *(const float4*)(X + (size_t)(t0 + row) * DMODEL + colbase + k0 + kq);
            qs[(kq + 0) * 64 + row] = v.x;
            qs[(kq + 1) * 64 + row] = v.y;
            qs[(kq + 2) * 64 + row] = v.z;
            qs[(kq + 3) * 64 + row] = v.w;
        }
#pragma unroll
        for (int l = 0; l < 2; l++) {
            int f = tid + l * 256;
            int row = f >> 2;
            int kq = (f & 3) * 4;
            float4 v1 = *(const float4*)(W1 + (size_t)row * DHD + k0 + kq);
            w1s[(kq + 0) * 128 + row] = v1.x;
            w1s[(kq + 1) * 128 + row] = v1.y;
            w1s[(kq + 2) * 128 + row] = v1.z;
            w1s[(kq + 3) * 128 + row] = v1.w;
            float4 v2 = *(const float4*)(W2 + (size_t)row * DHD + k0 + kq);
            w2s[(kq + 0) * 128 + row] = v2.x;
            w2s[(kq + 1) * 128 + row] = v2.y;
            w2s[(kq + 2) * 128 + row] = v2.z;
            w2s[(kq + 3) * 128 + row] = v2.w;
        }
        __syncthreads();
#pragma unroll
        for (int kk = 0; kk < 16; kk++) {
            float a[4], b1v[8], b2v[8];
            *(float4*)&a[0] = *(float4*)&qs[kk * 64 + ty * 4];
            *(float4*)&b1v[0] = *(float4*)&w1s[kk * 128 + tx * 8];
            *(float4*)&b1v[4] = *(float4*)&w1s[kk * 128 + tx * 8 + 4];
            *(float4*)&b2v[0] = *(float4*)&w2s[kk * 128 + tx * 8];
            *(float4*)&b2v[4] = *(float4*)&w2s[kk * 128 + tx * 8 + 4];
#pragma unroll
            for (int i = 0; i < 4; i++)
#pragma unroll
                for (int j = 0; j < 8; j++) {
                    acc1[i][j] = fmaf(a[i], b1v[j], acc1[i][j]);
                    acc2[i][j] = fmaf(a[i], b2v[j], acc2[i][j]);
                }
        }
        __syncthreads();
    }

    float bb1[8], bb2[8];
#pragma unroll
    for (int j = 0; j < 8; j++) {
        bb1[j] = B1[tx * 8 + j];
        bb2[j] = B2[tx * 8 + j];
    }
#pragma unroll
    for (int i = 0; i < 4; i++) {
        int t = t0 + ty * 4 + i;
        float out[8];
#pragma unroll
        for (int j = 0; j < 8; j++)
            out[j] = (acc1[i][j] + bb1[j]) * (acc2[i][j] + bb2[j]) * scale;
        *(float4*)(X + (size_t)t * DMODEL + colbase + tx * 8)     = *(float4*)&out[0];
        *(float4*)(X + (size_t)t * DMODEL + colbase + tx * 8 + 4) = *(float4*)&out[4];
    }
}

// ---------------------------------------------------------------------------
__global__ __launch_bounds__(256) void chunk_kv(const float* __restrict__ Kf,
                                                const float* __restrict__ V,
                                                float* __restrict__ KV) {
    __shared__ float ks[16 * 128];
    __shared__ float vs[16 * 128];
    const int tid = threadIdx.x;
    int idx = blockIdx.x;
    int h = idx % NH;
    int n = (idx / NH) % NCHUNK;
    int b = idx / (NH * NCHUNK);
    const int ty = tid >> 4, tx = tid & 15;
    const size_t tokenbase = (size_t)b * 8192 + (size_t)n * CHUNKL;
    const int col = h * DHD;

    float acc[8][8];
#pragma unroll
    for (int i = 0; i < 8; i++)
#pragma unroll
        for (int j = 0; j < 8; j++) acc[i][j] = 0.f;

    for (int s0 = 0; s0 < CHUNKL; s0 += 16) {
#pragma unroll
        for (int l = 0; l < 2; l++) {
            int f = tid + l * 256;
            int ss = f >> 5;
            int d4 = (f & 31) * 4;
            *(float4*)&ks[ss * 128 + d4] =
                *(const float4*)(Kf + (tokenbase + s0 + ss) * DMODEL + col + d4);
            *(float4*)&vs[ss * 128 + d4] =
                *(const float4*)(V + (tokenbase + s0 + ss) * DMODEL + col + d4);
        }
        __syncthreads();
#pragma unroll
        for (int ss = 0; ss < 16; ss++) {
            float a[8], bv[8];
            *(float4*)&a[0] = *(float4*)&ks[ss * 128 + ty * 4];
            *(float4*)&a[4] = *(float4*)&ks[ss * 128 + ty * 4 + 64];
            *(float4*)&bv[0] = *(float4*)&vs[ss * 128 + tx * 4];
            *(float4*)&bv[4] = *(float4*)&vs[ss * 128 + tx * 4 + 64];
#pragma unroll
            for (int i = 0; i < 8; i++)
#pragma unroll
                for (int j = 0; j < 8; j++) acc[i][j] = fmaf(a[i], bv[j], acc[i][j]);
        }
        __syncthreads();
    }

    size_t base = ((size_t)(b * NCHUNK + n) * NH + h) * (DHD * DHD);
#pragma unroll
    for (int iq = 0; iq < 2; iq++)
#pragma unroll
        for (int i = 0; i < 4; i++) {
            int dk = iq * 64 + ty * 4 + i;
#pragma unroll
            for (int jq = 0; jq < 2; jq++) {
                float4 v;
                v.x = acc[iq * 4 + i][jq * 4 + 0];
                v.y = acc[iq * 4 + i][jq * 4 + 1];
                v.z = acc[iq * 4 + i][jq * 4 + 2];
                v.w = acc[iq * 4 + i][jq * 4 + 3];
                *(float4*)(KV + base + (size_t)dk * DHD + jq * 64 + tx * 4) = v;
            }
        }
}

// ---------------------------------------------------------------------------
__global__ void cumsum_excl(float* __restrict__ KV) {
    int bh = blockIdx.x;
    int b = bh / NH, h = bh % NH;
    int i = blockIdx.y * 256 + threadIdx.x;
    float acc = 0.f;
    for (int n = 0; n < NCHUNK; n++) {
        size_t idx = ((size_t)(b * NCHUNK + n) * NH + h) * (DHD * DHD) + i;
        float v = KV[idx];
        KV[idx] = acc;
        acc += v;
    }
}

// ---------------------------------------------------------------------------
__global__ __launch_bounds__(256) void chunk_attn(const float* __restrict__ Q,
                                                  const float* __restrict__ Kf,
                                                  const float* __restrict__ V,
                                                  const float* __restrict__ S,
                                                  float* __restrict__ O) {
    __shared__ float sA[64 * 64];
    __shared__ float sQ[16 * 64];
    __shared__ float sT[16 * 128];
    const int tid = threadIdx.x;
    int idx = blockIdx.x;
    int h = idx % NH;
    int n = (idx / NH) % NCHUNK;
    int b = idx / (NH * NCHUNK);
    const int ty = tid >> 4, tx = tid & 15;
    const size_t tokenbase = (size_t)b * 8192 + (size_t)n * CHUNKL;
    const int col = h * DHD;

    float accA[4][4];
#pragma unroll
    for (int i = 0; i < 4; i++)
#pragma unroll
        for (int j = 0; j < 4; j++) accA[i][j] = 0.f;

    for (int k0 = 0; k0 < DHD; k0 += 16) {
        {
            int f = tid;
            int row = f >> 2;
            int kq = (f & 3) * 4;
            float4 vq = *(const float4*)(Q + (tokenbase + row) * DMODEL + col + k0 + kq);
            sQ[(kq + 0) * 64 + row] = vq.x;
            sQ[(kq + 1) * 64 + row] = vq.y;
            sQ[(kq + 2) * 64 + row] = vq.z;
            sQ[(kq + 3) * 64 + row] = vq.w;
            float4 vk = *(const float4*)(Kf + (tokenbase + row) * DMODEL + col + k0 + kq);
            sT[(kq + 0) * 64 + row] = vk.x;
            sT[(kq + 1) * 64 + row] = vk.y;
            sT[(kq + 2) * 64 + row] = vk.z;
            sT[(kq + 3) * 64 + row] = vk.w;
        }
        __syncthreads();
#pragma unroll
        for (int kk = 0; kk < 16; kk++) {
            float a[4], bk[4];
            *(float4*)a = *(float4*)&sQ[kk * 64 + ty * 4];
            *(float4*)bk = *(float4*)&sT[kk * 64 + tx * 4];
#pragma unroll
            for (int i = 0; i < 4; i++)
#pragma unroll
                for (int j = 0; j < 4; j++) accA[i][j] = fmaf(a[i], bk[j], accA[i][j]);
        }
        __syncthreads();
    }
#pragma unroll
    for (int i = 0; i < 4; i++) {
        int c = ty * 4 + i;
#pragma unroll
        for (int j = 0; j < 4; j++) {
            int s = tx * 4 + j;
            sA[c * 64 + s] = (s <= c) ? accA[i][j] : 0.f;
        }
    }
    __syncthreads();

    float acc[4][8];
#pragma unroll
    for (int i = 0; i < 4; i++)
#pragma unroll
        for (int j = 0; j < 8; j++) acc[i][j] = 0.f;

    for (int s0 = 0; s0 < CHUNKL; s0 += 16) {
#pragma unroll
        for (int l = 0; l < 2; l++) {
            int f = tid + l * 256;
            int ss = f >> 5;
            int d4 = (f & 31) * 4;
            *(float4*)&sT[ss * 128 + d4] =
                *(const float4*)(V + (tokenbase + s0 + ss) * DMODEL + col + d4);
        }
        __syncthreads();
#pragma unroll
        for (int ss = 0; ss < 16; ss++) {
            float bb[8];
            *(float4*)&bb[0] = *(float4*)&sT[ss * 128 + tx * 8];
            *(float4*)&bb[4] = *(float4*)&sT[ss * 128 + tx * 8 + 4];
#pragma unroll
            for (int i = 0; i < 4; i++) {
                float aa = sA[(ty * 4 + i) * 64 + s0 + ss];
#pragma unroll
                for (int j = 0; j < 8; j++) acc[i][j] = fmaf(aa, bb[j], acc[i][j]);
            }
        }
        __syncthreads();
    }

    size_t Sbase = ((size_t)(b * NCHUNK + n) * NH + h) * (DHD * DHD);
    for (int k0 = 0; k0 < DHD; k0 += 16) {
        {
            int f = tid;
            int row = f >> 2;
            int kq = (f & 3) * 4;
            float4 vq = *(const float4*)(Q + (tokenbase + row) * DMODEL + col + k0 + kq);
            sQ[(kq + 0) * 64 + row] = vq.x;
            sQ[(kq + 1) * 64 + row] = vq.y;
            sQ[(kq + 2) * 64 + row] = vq.z;
            sQ[(kq + 3) * 64 + row] = vq.w;
        }
#pragma unroll
        for (int l = 0; l < 2; l++) {
            int f = tid + l * 256;
            int kk = f >> 5;
            int d4 = (f & 31) * 4;
            *(float4*)&sT[kk * 128 + d4] =
                *(const float4*)(S + Sbase + (size_t)(k0 + kk) * DHD + d4);
        }
        __syncthreads();
#pragma unroll
        for (int kk = 0; kk < 16; kk++) {
            float a[4], bb[8];
            *(float4*)a = *(float4*)&sQ[kk * 64 + ty * 4];
            *(float4*)&bb[0] = *(float4*)&sT[kk * 128 + tx * 8];
            *(float4*)&bb[4] = *(float4*)&sT[kk * 128 + tx * 8 + 4];
#pragma unroll
            for (int i = 0; i < 4; i++)
#pragma unroll
                for (int j = 0; j < 8; j++) acc[i][j] = fmaf(a[i], bb[j], acc[i][j]);
        }
        __syncthreads();
    }

#pragma unroll
    for (int i = 0; i < 4; i++) {
        size_t t = tokenbase + ty * 4 + i;
        *(float4*)(O + t * DMODEL + col + tx * 8)     = *(float4*)&acc[i][0];
        *(float4*)(O + t * DMODEL + col + tx * 8 + 4) = *(float4*)&acc[i][4];
    }
}

// ---------------------------------------------------------------------------
__global__ void rmsnorm_kernel(float* __restrict__ O, const float* __restrict__ W) {
    int row = blockIdx.x * 8 + threadIdx.y;
    int t = row / NH, h = row % NH;
    int lane = threadIdx.x;
    float* p = O + (size_t)t * DMODEL + h * DHD + lane * 4;
    float4 x = *(float4*)p;
    float ss = x.x * x.x + x.y * x.y + x.z * x.z + x.w * x.w;
#pragma unroll
    for (int off = 16; off > 0; off >>= 1)
        ss += __shfl_xor_sync(0xffffffffu, ss, off);
    float r = rsqrtf(ss * (1.0f / 128.0f) + RMSEPS);
    float4 w = *(const float4*)(W + lane * 4);
    x.x *= r * w.x; x.y *= r * w.y; x.z *= r * w.z; x.w *= r * w.w;
    *(float4*)p = x;
}

// ---------------------------------------------------------------------------
extern "C" void kernel_launch(void* const* d_in, const int* in_sizes, int n_in,
                              void* d_out, int out_size) {
    const float* hidden = (const float*)d_in[0];
    const float* q_w    = (const float*)d_in[2];
    const float* k_w    = (const float*)d_in[3];
    const float* v_w    = (const float*)d_in[4];
    const float* o_w    = (const float*)d_in[5];
    const float* fmq_w1 = (const float*)d_in[6];
    const float* fmq_b1 = (const float*)d_in[7];
    const float* fmq_w2 = (const float*)d_in[8];
    const float* fmq_b2 = (const float*)d_in[9];
    const float* fmk_w1 = (const float*)d_in[10];
    const float* fmk_b1 = (const float*)d_in[11];
    const float* fmk_w2 = (const float*)d_in[12];
    const float* fmk_b2 = (const float*)d_in[13];
    const float* rms_w  = (const float*)d_in[14];
    float* out = (float*)d_out;

    float *q, *k, *v, *kv, *o;
    __nv_bfloat16 *ahi, *alo, *whi, *wlo;
    cudaGetSymbolAddress((void**)&q,   g_q);
    cudaGetSymbolAddress((void**)&k,   g_k);
    cudaGetSymbolAddress((void**)&v,   g_v);
    cudaGetSymbolAddress((void**)&kv,  g_kv);
    cudaGetSymbolAddress((void**)&o,   g_o);
    cudaGetSymbolAddress((void**)&ahi, g_ahi);
    cudaGetSymbolAddress((void**)&alo, g_alo);
    cudaGetSymbolAddress((void**)&whi, g_whi);
    cudaGetSymbolAddress((void**)&wlo, g_wlo);

    cudaFuncSetAttribute(gemm_mma, cudaFuncAttributeMaxDynamicSharedMemorySize,
                         GEMM_SMEM_BYTES);

    const int nA = BT * DMODEL;
    const int nW = DMODEL * DMODEL;
    dim3 gemm_grid(DMODEL / 128, BT / 128);  // (8, 128)

    split_f32<<<nA / 1024, 256>>>(hidden, ahi, alo, nA);

    split_f32<<<nW / 1024, 256>>>(q_w, whi, wlo, nW);
    gemm_mma<<<gemm_grid, 256, GEMM_SMEM_BYTES>>>(ahi, alo, whi, wlo, q, BT, DMODEL, DMODEL);
    split_f32<<<nW / 1024, 256>>>(k_w, whi, wlo, nW);
    gemm_mma<<<gemm_grid, 256, GEMM_SMEM_BYTES>>>(ahi, alo, whi, wlo, k, BT, DMODEL, DMODEL);
    split_f32<<<nW / 1024, 256>>>(v_w, whi, wlo, nW);
    gemm_mma<<<gemm_grid, 256, GEMM_SMEM_BYTES>>>(ahi, alo, whi, wlo, v, BT, DMODEL, DMODEL);

    dim3 fm_grid(BT / 64, NH);
    featmap<<<fm_grid, 256>>>(q, fmq_w1, fmq_b1, fmq_w2, fmq_b2, QSCALE);
    featmap<<<fm_grid, 256>>>(k, fmk_w1, fmk_b1, fmk_w2, fmk_b2, 1.0f);

    chunk_kv<<<NBATCH * NCHUNK * NH, 256>>>(k, v, kv);

    dim3 cs_grid(NBATCH * NH, (DHD * DHD) / 256);
    cumsum_excl<<<cs_grid, 256>>>(kv);

    chunk_attn<<<NBATCH * NCHUNK * NH, 256>>>(q, k, v, kv, o);

    rmsnorm_kernel<<<(BT * NH) / 8, dim3(32, 8)>>>(o, rms_w);

    split_f32<<<nA / 1024, 256>>>(o, ahi, alo, nA);
    split_f32<<<nW / 1024, 256>>>(o_w, whi, wlo, nW);
    gemm_mma<<<gemm_grid, 256, GEMM_SMEM_BYTES>>>(ahi, alo, whi, wlo, out, BT, DMODEL, DMODEL);
}

// round 4
// speedup vs baseline: 1.8170x; 1.1804x over previous
#include <cuda_runtime.h>
#include <cuda_bf16.h>
#include <cstdint>
#include <cstddef>

// Problem constants
#define BT      16384
#define DMODEL  1024
#define NH      8
#define DHD     128
#define CHUNKL  64
#define NCHUNK  128
#define NBATCH  2
#define QSCALE  0.08838834764831843f
#define RMSEPS  1e-5f

// Scratch buffers
__device__ float g_q[(size_t)BT * DMODEL];   // phi_q (scaled)
__device__ float g_k[(size_t)BT * DMODEL];   // phi_k
__device__ float g_v[(size_t)BT * DMODEL];
__device__ float g_o[(size_t)BT * DMODEL];
__device__ float g_kv[(size_t)NBATCH * NCHUNK * NH * DHD * DHD];
__device__ __nv_bfloat16 g_ahi[(size_t)BT * DMODEL];
__device__ __nv_bfloat16 g_alo[(size_t)BT * DMODEL];
__device__ __nv_bfloat16 g_whi[(size_t)3 * DMODEL * DMODEL];
__device__ __nv_bfloat16 g_wlo[(size_t)3 * DMODEL * DMODEL];
__device__ __nv_bfloat16 g_qhi[(size_t)BT * DMODEL];
__device__ __nv_bfloat16 g_qlo[(size_t)BT * DMODEL];
__device__ __nv_bfloat16 g_khi[(size_t)BT * DMODEL];
__device__ __nv_bfloat16 g_klo[(size_t)BT * DMODEL];
__device__ __nv_bfloat16 g_fwhi[4 * DHD * DHD];
__device__ __nv_bfloat16 g_fwlo[4 * DHD * DHD];

#define SWZ(off) ((off) ^ (((off) >> 3) & 0x70))

__device__ __forceinline__ uint32_t smem_u32(const void* p) {
    uint32_t a;
    asm("{ .reg .u64 t; cvta.to.shared.u64 t, %1; cvt.u32.u64 %0, t; }" : "=r"(a) : "l"(p));
    return a;
}

__device__ __forceinline__ void ldsm_x4(uint32_t addr, uint32_t& r0, uint32_t& r1,
                                        uint32_t& r2, uint32_t& r3) {
    asm volatile("ldmatrix.sync.aligned.m8n8.x4.shared.b16 {%0,%1,%2,%3}, [%4];"
                 : "=r"(r0), "=r"(r1), "=r"(r2), "=r"(r3) : "r"(addr));
}

__device__ __forceinline__ void mma_bf16(float* d, const uint32_t* a, const uint32_t* b) {
    asm volatile(
        "mma.sync.aligned.m16n8k16.row.col.f32.bf16.bf16.f32 "
        "{%0,%1,%2,%3}, {%4,%5,%6,%7}, {%8,%9}, {%0,%1,%2,%3};"
        : "+f"(d[0]), "+f"(d[1]), "+f"(d[2]), "+f"(d[3])
        : "r"(a[0]), "r"(a[1]), "r"(a[2]), "r"(a[3]), "r"(b[0]), "r"(b[1]));
}

__device__ __forceinline__ void cp_async16(uint32_t saddr, const void* gaddr) {
    asm volatile("cp.async.cg.shared.global [%0], [%1], 16;" :: "r"(saddr), "l"(gaddr));
}
#define CP_COMMIT() asm volatile("cp.async.commit_group;" ::: "memory")
#define CP_WAIT0()  asm volatile("cp.async.wait_group 0;" ::: "memory")

// split two adjacent fp32 into packed bf16 hi/lo words
__device__ __forceinline__ void split2(float a, float b, uint32_t& hi, uint32_t& lo) {
    __nv_bfloat16 ha = __float2bfloat16(a), hb = __float2bfloat16(b);
    __nv_bfloat16 la = __float2bfloat16(a - __bfloat162float(ha));
    __nv_bfloat16 lb = __float2bfloat16(b - __bfloat162float(hb));
    __nv_bfloat162 hp = __halves2bfloat162(ha, hb);
    __nv_bfloat162 lp = __halves2bfloat162(la, lb);
    hi = *(uint32_t*)&hp; lo = *(uint32_t*)&lp;
}

// ---------------------------------------------------------------------------
// fp32 -> (hi, lo) bf16 split (standalone)
// ---------------------------------------------------------------------------
__global__ void split_f32(const float* __restrict__ x, __nv_bfloat16* __restrict__ hi,
                          __nv_bfloat16* __restrict__ lo, int n) {
    int i = (blockIdx.x * blockDim.x + threadIdx.x) * 4;
    if (i >= n) return;
    float4 v = *(const float4*)(x + i);
    uint32_t h0, l0, h1, l1;
    split2(v.x, v.y, h0, l0);
    split2(v.z, v.w, h1, l1);
    *(uint2*)(hi + i) = make_uint2(h0, h1);
    *(uint2*)(lo + i) = make_uint2(l0, l1);
}

// ---------------------------------------------------------------------------
// HMMA GEMM: C[M,1024] tile = (Ahi+Alo)[M,1024] @ (Whi+Wlo)[n,1024]^T
// 128x128 CTA tile, BK=64, 8 warps, warp tile 32x64.
// mode 0: packed qkv output -> q/k as bf16 hi/lo splits, v as f32
// mode 1: plain f32 output to Cout
// ---------------------------------------------------------------------------
#define GEMM_SMEM_BYTES (65536 + 1024)

__global__ __launch_bounds__(256) void gemm_mma2(
    const __nv_bfloat16* __restrict__ Ahi, const __nv_bfloat16* __restrict__ Alo,
    const __nv_bfloat16* __restrict__ Whi, const __nv_bfloat16* __restrict__ Wlo,
    __nv_bfloat16* __restrict__ Qhi, __nv_bfloat16* __restrict__ Qlo,
    __nv_bfloat16* __restrict__ Khi, __nv_bfloat16* __restrict__ Klo,
    float* __restrict__ Vout, float* __restrict__ Cout, int mode) {
    extern __shared__ char dynraw[];
    char* smem = (char*)(((uintptr_t)dynraw + 1023) & ~(uintptr_t)1023);

    const int tid = threadIdx.x;
    const int wid = tid >> 5;
    const int lane = tid & 31;
    const int n0 = blockIdx.x * 128;
    const int m0 = blockIdx.y * 128;
    const int wm = (wid & 3) * 32;
    const int wn = (wid >> 2) * 64;

    const uint32_t sAh = smem_u32(smem);
    const uint32_t sAl = sAh + 16384;
    const uint32_t sBh = sAh + 32768;
    const uint32_t sBl = sAh + 49152;

    float acc[2][8][4];
#pragma unroll
    for (int i = 0; i < 2; i++)
#pragma unroll
        for (int j = 0; j < 8; j++)
#pragma unroll
            for (int r = 0; r < 4; r++) acc[i][j][r] = 0.f;

    const char* srcA_h = (const char*)(Ahi + (size_t)m0 * 1024);
    const char* srcA_l = (const char*)(Alo + (size_t)m0 * 1024);
    const char* srcB_h = (const char*)(Whi + (size_t)n0 * 1024);
    const char* srcB_l = (const char*)(Wlo + (size_t)n0 * 1024);

    const int mat = lane >> 3;
    const int mrow = lane & 7;

    for (int kt = 0; kt < 16; kt++) {
        const size_t kbyte = (size_t)kt * 128;
#pragma unroll
        for (int l = 0; l < 4; l++) {
            int u = tid + 256 * l;
            int row = u >> 3;
            int cb = (u & 7) * 16;
            uint32_t dsw = SWZ((uint32_t)(row * 128 + cb));
            size_t src_off = (size_t)row * 2048 + kbyte + cb;
            *(uint4*)(smem + 0     + dsw) = *(const uint4*)(srcA_h + src_off);
            *(uint4*)(smem + 16384 + dsw) = *(const uint4*)(srcA_l + src_off);
            *(uint4*)(smem + 32768 + dsw) = *(const uint4*)(srcB_h + src_off);
            *(uint4*)(smem + 49152 + dsw) = *(const uint4*)(srcB_l + src_off);
        }
        __syncthreads();

#pragma unroll
        for (int kc = 0; kc < 4; kc++) {
            const int kb0 = kc * 32;
            uint32_t ah[2][4], al[2][4];
#pragma unroll
            for (int i = 0; i < 2; i++) {
                int arow = wm + i * 16 + (mat & 1) * 8 + mrow;
                int akb = kb0 + (mat >> 1) * 16;
                uint32_t off = SWZ((uint32_t)(arow * 128 + akb));
                ldsm_x4(sAh + off, ah[i][0], ah[i][1], ah[i][2], ah[i][3]);
                ldsm_x4(sAl + off, al[i][0], al[i][1], al[i][2], al[i][3]);
            }
#pragma unroll
            for (int p = 0; p < 4; p++) {
                int brow = wn + p * 16 + (mat >> 1) * 8 + mrow;
                int bkb = kb0 + (mat & 1) * 16;
                uint32_t off = SWZ((uint32_t)(brow * 128 + bkb));
                uint32_t bh[4], bl[4];
                ldsm_x4(sBh + off, bh[0], bh[1], bh[2], bh[3]);
                ldsm_x4(sBl + off, bl[0], bl[1], bl[2], bl[3]);
#pragma unroll
                for (int i = 0; i < 2; i++) {
                    mma_bf16(acc[i][2 * p],     ah[i], &bh[0]);
                    mma_bf16(acc[i][2 * p],     al[i], &bh[0]);
                    mma_bf16(acc[i][2 * p],     ah[i], &bl[0]);
                    mma_bf16(acc[i][2 * p + 1], ah[i], &bh[2]);
                    mma_bf16(acc[i][2 * p + 1], al[i], &bh[2]);
                    mma_bf16(acc[i][2 * p + 1], ah[i], &bl[2]);
                }
            }
        }
        __syncthreads();
    }

    const int crow = lane >> 2;
    const int ccol = (lane & 3) * 2;
    if (mode == 1) {
#pragma unroll
        for (int i = 0; i < 2; i++) {
            int m = m0 + wm + i * 16 + crow;
#pragma unroll
            for (int j = 0; j < 8; j++) {
                int n = n0 + wn + j * 8 + ccol;
                *(float2*)(Cout + (size_t)m * 1024 + n) = make_float2(acc[i][j][0], acc[i][j][1]);
                *(float2*)(Cout + (size_t)(m + 8) * 1024 + n) = make_float2(acc[i][j][2], acc[i][j][3]);
            }
        }
    } else {
        int buf = n0 >> 10;
        int ncol0 = n0 & 1023;
        if (buf == 2) {
#pragma unroll
            for (int i = 0; i < 2; i++) {
                int m = m0 + wm + i * 16 + crow;
#pragma unroll
                for (int j = 0; j < 8; j++) {
                    int n = ncol0 + wn + j * 8 + ccol;
                    *(float2*)(Vout + (size_t)m * 1024 + n) = make_float2(acc[i][j][0], acc[i][j][1]);
                    *(float2*)(Vout + (size_t)(m + 8) * 1024 + n) = make_float2(acc[i][j][2], acc[i][j][3]);
                }
            }
        } else {
            __nv_bfloat16* H = buf ? Khi : Qhi;
            __nv_bfloat16* L = buf ? Klo : Qlo;
#pragma unroll
            for (int i = 0; i < 2; i++) {
                int m = m0 + wm + i * 16 + crow;
#pragma unroll
                for (int j = 0; j < 8; j++) {
                    int n = ncol0 + wn + j * 8 + ccol;
                    uint32_t hi, lo;
                    split2(acc[i][j][0], acc[i][j][1], hi, lo);
                    *(uint32_t*)(H + (size_t)m * 1024 + n) = hi;
                    *(uint32_t*)(L + (size_t)m * 1024 + n) = lo;
                    split2(acc[i][j][2], acc[i][j][3], hi, lo);
                    *(uint32_t*)(H + (size_t)(m + 8) * 1024 + n) = hi;
                    *(uint32_t*)(L + (size_t)(m + 8) * 1024 + n) = lo;
                }
            }
        }
    }
}

// ---------------------------------------------------------------------------
// Feature map via HMMA: Out[t, h*128 + z*64 + n] =
//   (X_h @ W1^T + b1)[n'] * (X_h @ W2^T + b2)[n'] * scale,  n' = z*64+n
// CTA: 128 tokens x 64 outputs, one head, one n-half. 256 threads, 8 warps
// (warp grid 4Mx2N, warp tile 32x32). K=128 loaded in one shot (two 64-halves).
// ---------------------------------------------------------------------------
#define FM_SMEM (131072 + 1024)

__global__ __launch_bounds__(256) void featmap_mma(
    const __nv_bfloat16* __restrict__ Xhi, const __nv_bfloat16* __restrict__ Xlo,
    const __nv_bfloat16* __restrict__ W1hi, const __nv_bfloat16* __restrict__ W1lo,
    const __nv_bfloat16* __restrict__ W2hi, const __nv_bfloat16* __restrict__ W2lo,
    const float* __restrict__ B1, const float* __restrict__ B2,
    float* __restrict__ Out, float scale) {
    extern __shared__ char dynraw[];
    char* smem = (char*)(((uintptr_t)dynraw + 1023) & ~(uintptr_t)1023);
    const uint32_t sbase = smem_u32(smem);

    const int tid = threadIdx.x;
    const int wid = tid >> 5;
    const int lane = tid & 31;
    const int t0 = blockIdx.x * 128;
    const int h = blockIdx.y;
    const int z = blockIdx.z;             // n-half: 0 or 1
    const int wm = (wid & 3) * 32;
    const int wn = (wid >> 2) * 32;

    // X tiles: [half][hi/lo] 4 x 16KB at sbase + (half*2+hl)*16384
    // W tiles: [half][w][hi/lo] 8 x 8KB at sbase + 65536 + (half*4+w*2+hl)*8192
    const __nv_bfloat16* wsel[4] = {W1hi, W1lo, W2hi, W2lo};

#pragma unroll
    for (int t = 0; t < 4; t++) {
        int half = t >> 1, hl = t & 1;
        const char* sp = (const char*)((hl ? Xlo : Xhi) +
                          (size_t)t0 * 1024 + h * 128 + half * 64);
#pragma unroll
        for (int l = 0; l < 4; l++) {
            int s = tid + 256 * l;
            int row = s >> 3, cb = (s & 7) * 16;
            cp_async16(sbase + t * 16384 + SWZ((uint32_t)(row * 128 + cb)),
                       sp + (size_t)row * 2048 + cb);
        }
    }
#pragma unroll
    for (int t = 0; t < 8; t++) {
        int half = t >> 2, wsub = (t >> 1) & 1, hl = t & 1;
        const char* sp = (const char*)wsel[wsub * 2 + hl] +
                         ((size_t)(z * 64) * 128 + half * 64) * 2;
#pragma unroll
        for (int l = 0; l < 2; l++) {
            int s = tid + 256 * l;
            int row = s >> 3, cb = (s & 7) * 16;
            cp_async16(sbase + 65536 + t * 8192 + SWZ((uint32_t)(row * 128 + cb)),
                       sp + (size_t)row * 256 + cb);
        }
    }
    CP_COMMIT();
    CP_WAIT0();
    __syncthreads();

    float acc1[2][4][4], acc2[2][4][4];
#pragma unroll
    for (int i = 0; i < 2; i++)
#pragma unroll
        for (int j = 0; j < 4; j++)
#pragma unroll
            for (int r = 0; r < 4; r++) { acc1[i][j][r] = 0.f; acc2[i][j][r] = 0.f; }

    const int mat = lane >> 3;
    const int mrow = lane & 7;

#pragma unroll
    for (int half = 0; half < 2; half++) {
        const uint32_t sXh = sbase + (half * 2 + 0) * 16384;
        const uint32_t sXl = sbase + (half * 2 + 1) * 16384;
        const uint32_t sW1h = sbase + 65536 + (half * 4 + 0) * 8192;
        const uint32_t sW1l = sbase + 65536 + (half * 4 + 1) * 8192;
        const uint32_t sW2h = sbase + 65536 + (half * 4 + 2) * 8192;
        const uint32_t sW2l = sbase + 65536 + (half * 4 + 3) * 8192;
#pragma unroll
        for (int kc = 0; kc < 4; kc++) {
            const int kb0 = kc * 32;
            uint32_t ah[2][4], al[2][4];
#pragma unroll
            for (int i = 0; i < 2; i++) {
                int arow = wm + i * 16 + (mat & 1) * 8 + mrow;
                int akb = kb0 + (mat >> 1) * 16;
                uint32_t off = SWZ((uint32_t)(arow * 128 + akb));
                ldsm_x4(sXh + off, ah[i][0], ah[i][1], ah[i][2], ah[i][3]);
                ldsm_x4(sXl + off, al[i][0], al[i][1], al[i][2], al[i][3]);
            }
#pragma unroll
            for (int p = 0; p < 2; p++) {
                int brow = wn + p * 16 + (mat >> 1) * 8 + mrow;
                int bkb = kb0 + (mat & 1) * 16;
                uint32_t off = SWZ((uint32_t)(brow * 128 + bkb));
                uint32_t b1h[4], b1l[4], b2h[4], b2l[4];
                ldsm_x4(sW1h + off, b1h[0], b1h[1], b1h[2], b1h[3]);
                ldsm_x4(sW1l + off, b1l[0], b1l[1], b1l[2], b1l[3]);
                ldsm_x4(sW2h + off, b2h[0], b2h[1], b2h[2], b2h[3]);
                ldsm_x4(sW2l + off, b2l[0], b2l[1], b2l[2], b2l[3]);
#pragma unroll
                for (int i = 0; i < 2; i++) {
                    mma_bf16(acc1[i][2 * p],     ah[i], &b1h[0]);
                    mma_bf16(acc1[i][2 * p],     al[i], &b1h[0]);
                    mma_bf16(acc1[i][2 * p],     ah[i], &b1l[0]);
                    mma_bf16(acc1[i][2 * p + 1], ah[i], &b1h[2]);
                    mma_bf16(acc1[i][2 * p + 1], al[i], &b1h[2]);
                    mma_bf16(acc1[i][2 * p + 1], ah[i], &b1l[2]);
                    mma_bf16(acc2[i][2 * p],     ah[i], &b2h[0]);
                    mma_bf16(acc2[i][2 * p],     al[i], &b2h[0]);
                    mma_bf16(acc2[i][2 * p],     ah[i], &b2l[0]);
                    mma_bf16(acc2[i][2 * p + 1], ah[i], &b2h[2]);
                    mma_bf16(acc2[i][2 * p + 1], al[i], &b2h[2]);
                    mma_bf16(acc2[i][2 * p + 1], ah[i], &b2l[2]);
                }
            }
        }
    }

    // Epilogue: Hadamard product + bias + scale
    const int crow = lane >> 2;
    const int ccol = (lane & 3) * 2;
#pragma unroll
    for (int j = 0; j < 4; j++) {
        int nl = z * 64 + wn + j * 8 + ccol;       // 0..127 within head
        float b1a = B1[nl], b1b = B1[nl + 1];
        float b2a = B2[nl], b2b = B2[nl + 1];
#pragma unroll
        for (int i = 0; i < 2; i++) {
            int m = t0 + wm + i * 16 + crow;
            float o0 = (acc1[i][j][0] + b1a) * (acc2[i][j][0] + b2a) * scale;
            float o1 = (acc1[i][j][1] + b1b) * (acc2[i][j][1] + b2b) * scale;
            *(float2*)(Out + (size_t)m * 1024 + h * 128 + nl) = make_float2(o0, o1);
            float o2 = (acc1[i][j][2] + b1a) * (acc2[i][j][2] + b2a) * scale;
            float o3 = (acc1[i][j][3] + b1b) * (acc2[i][j][3] + b2b) * scale;
            *(float2*)(Out + (size_t)(m + 8) * 1024 + h * 128 + nl) = make_float2(o2, o3);
        }
    }
}

// ---------------------------------------------------------------------------
__global__ __launch_bounds__(256) void chunk_kv(const float* __restrict__ Kf,
                                                const float* __restrict__ V,
                                                float* __restrict__ KV) {
    __shared__ float ks[16 * 128];
    __shared__ float vs[16 * 128];
    const int tid = threadIdx.x;
    int idx = blockIdx.x;
    int h = idx % NH;
    int n = (idx / NH) % NCHUNK;
    int b = idx / (NH * NCHUNK);
    const int ty = tid >> 4, tx = tid & 15;
    const size_t tokenbase = (size_t)b * 8192 + (size_t)n * CHUNKL;
    const int col = h * DHD;

    float acc[8][8];
#pragma unroll
    for (int i = 0; i < 8; i++)
#pragma unroll
        for (int j = 0; j < 8; j++) acc[i][j] = 0.f;

    for (int s0 = 0; s0 < CHUNKL; s0 += 16) {
#pragma unroll
        for (int l = 0; l < 2; l++) {
            int f = tid + l * 256;
            int ss = f >> 5;
            int d4 = (f & 31) * 4;
            *(float4*)&ks[ss * 128 + d4] =
                *(const float4*)(Kf + (tokenbase + s0 + ss) * DMODEL + col + d4);
            *(float4*)&vs[ss * 128 + d4] =
                *(const float4*)(V + (tokenbase + s0 + ss) * DMODEL + col + d4);
        }
        __syncthreads();
#pragma unroll
        for (int ss = 0; ss < 16; ss++) {
            float a[8], bv[8];
            *(float4*)&a[0] = *(float4*)&ks[ss * 128 + ty * 4];
            *(float4*)&a[4] = *(float4*)&ks[ss * 128 + ty * 4 + 64];
            *(float4*)&bv[0] = *(float4*)&vs[ss * 128 + tx * 4];
            *(float4*)&bv[4] = *(float4*)&vs[ss * 128 + tx * 4 + 64];
#pragma unroll
            for (int i = 0; i < 8; i++)
#pragma unroll
                for (int j = 0; j < 8; j++) acc[i][j] = fmaf(a[i], bv[j], acc[i][j]);
        }
        __syncthreads();
    }

    size_t base = ((size_t)(b * NCHUNK + n) * NH + h) * (DHD * DHD);
#pragma unroll
    for (int iq = 0; iq < 2; iq++)
#pragma unroll
        for (int i = 0; i < 4; i++) {
            int dk = iq * 64 + ty * 4 + i;
#pragma unroll
            for (int jq = 0; jq < 2; jq++) {
                float4 v;
                v.x = acc[iq * 4 + i][jq * 4 + 0];
                v.y = acc[iq * 4 + i][jq * 4 + 1];
                v.z = acc[iq * 4 + i][jq * 4 + 2];
                v.w = acc[iq * 4 + i][jq * 4 + 3];
                *(float4*)(KV + base + (size_t)dk * DHD + jq * 64 + tx * 4) = v;
            }
        }
}

// ---------------------------------------------------------------------------
__global__ void cumsum_excl(float* __restrict__ KV) {
    int bh = blockIdx.x;
    int b = bh / NH, h = bh % NH;
    int i = blockIdx.y * 256 + threadIdx.x;
    float acc = 0.f;
    for (int n = 0; n < NCHUNK; n++) {
        size_t idx = ((size_t)(b * NCHUNK + n) * NH + h) * (DHD * DHD) + i;
        float v = KV[idx];
        KV[idx] = acc;
        acc += v;
    }
}

// ---------------------------------------------------------------------------
__global__ __launch_bounds__(256) void chunk_attn(const float* __restrict__ Q,
                                                  const float* __restrict__ Kf,
                                                  const float* __restrict__ V,
                                                  const float* __restrict__ S,
                                                  float* __restrict__ O) {
    __shared__ float sA[64 * 64];
    __shared__ float sQ[16 * 64];
    __shared__ float sT[16 * 128];
    const int tid = threadIdx.x;
    int idx = blockIdx.x;
    int h = idx % NH;
    int n = (idx / NH) % NCHUNK;
    int b = idx / (NH * NCHUNK);
    const int ty = tid >> 4, tx = tid & 15;
    const size_t tokenbase = (size_t)b * 8192 + (size_t)n * CHUNKL;
    const int col = h * DHD;

    float accA[4][4];
#pragma unroll
    for (int i = 0; i < 4; i++)
#pragma unroll
        for (int j = 0; j < 4; j++) accA[i][j] = 0.f;

    for (int k0 = 0; k0 < DHD; k0 += 16) {
        {
            int f = tid;
            int row = f >> 2;
            int kq = (f & 3) * 4;
            float4 vq = *(const float4*)(Q + (tokenbase + row) * DMODEL + col + k0 + kq);
            sQ[(kq + 0) * 64 + row] = vq.x;
            sQ[(kq + 1) * 64 + row] = vq.y;
            sQ[(kq + 2) * 64 + row] = vq.z;
            sQ[(kq + 3) * 64 + row] = vq.w;
            float4 vk = *(const float4*)(Kf + (tokenbase + row) * DMODEL + col + k0 + kq);
            sT[(kq + 0) * 64 + row] = vk.x;
            sT[(kq + 1) * 64 + row] = vk.y;
            sT[(kq + 2) * 64 + row] = vk.z;
            sT[(kq + 3) * 64 + row] = vk.w;
        }
        __syncthreads();
#pragma unroll
        for (int kk = 0; kk < 16; kk++) {
            float a[4], bk[4];
            *(float4*)a = *(float4*)&sQ[kk * 64 + ty * 4];
            *(float4*)bk = *(float4*)&sT[kk * 64 + tx * 4];
#pragma unroll
            for (int i = 0; i < 4; i++)
#pragma unroll
                for (int j = 0; j < 4; j++) accA[i][j] = fmaf(a[i], bk[j], accA[i][j]);
        }
        __syncthreads();
    }
#pragma unroll
    for (int i = 0; i < 4; i++) {
        int c = ty * 4 + i;
#pragma unroll
        for (int j = 0; j < 4; j++) {
            int s = tx * 4 + j;
            sA[c * 64 + s] = (s <= c) ? accA[i][j] : 0.f;
        }
    }
    __syncthreads();

    float acc[4][8];
#pragma unroll
    for (int i = 0; i < 4; i++)
#pragma unroll
        for (int j = 0; j < 8; j++) acc[i][j] = 0.f;

    for (int s0 = 0; s0 < CHUNKL; s0 += 16) {
#pragma unroll
        for (int l = 0; l < 2; l++) {
            int f = tid + l * 256;
            int ss = f >> 5;
            int d4 = (f & 31) * 4;
            *(float4*)&sT[ss * 128 + d4] =
                *(const float4*)(V + (tokenbase + s0 + ss) * DMODEL + col + d4);
        }
        __syncthreads();
#pragma unroll
        for (int ss = 0; ss < 16; ss++) {
            float bb[8];
            *(float4*)&bb[0] = *(float4*)&sT[ss * 128 + tx * 8];
            *(float4*)&bb[4] = *(float4*)&sT[ss * 128 + tx * 8 + 4];
#pragma unroll
            for (int i = 0; i < 4; i++) {
                float aa = sA[(ty * 4 + i) * 64 + s0 + ss];
#pragma unroll
                for (int j = 0; j < 8; j++) acc[i][j] = fmaf(aa, bb[j], acc[i][j]);
            }
        }
        __syncthreads();
    }

    size_t Sbase = ((size_t)(b * NCHUNK + n) * NH + h) * (DHD * DHD);
    for (int k0 = 0; k0 < DHD; k0 += 16) {
        {
            int f = tid;
            int row = f >> 2;
            int kq = (f & 3) * 4;
            float4 vq = *(const float4*)(Q + (tokenbase + row) * DMODEL + col + k0 + kq);
            sQ[(kq + 0) * 64 + row] = vq.x;
            sQ[(kq + 1) * 64 + row] = vq.y;
            sQ[(kq + 2) * 64 + row] = vq.z;
            sQ[(kq + 3) * 64 + row] = vq.w;
        }
#pragma unroll
        for (int l = 0; l < 2; l++) {
            int f = tid + l * 256;
            int kk = f >> 5;
            int d4 = (f & 31) * 4;
            *(float4*)&sT[kk * 128 + d4] =
                *(const float4*)(S + Sbase + (size_t)(k0 + kk) * DHD + d4);
        }
        __syncthreads();
#pragma unroll
        for (int kk = 0; kk < 16; kk++) {
            float a[4], bb[8];
            *(float4*)a = *(float4*)&sQ[kk * 64 + ty * 4];
            *(float4*)&bb[0] = *(float4*)&sT[kk * 128 + tx * 8];
            *(float4*)&bb[4] = *(float4*)&sT[kk * 128 + tx * 8 + 4];
#pragma unroll
            for (int i = 0; i < 4; i++)
#pragma unroll
                for (int j = 0; j < 8; j++) acc[i][j] = fmaf(a[i], bb[j], acc[i][j]);
        }
        __syncthreads();
    }

#pragma unroll
    for (int i = 0; i < 4; i++) {
        size_t t = tokenbase + ty * 4 + i;
        *(float4*)(O + t * DMODEL + col + tx * 8)     = *(float4*)&acc[i][0];
        *(float4*)(O + t * DMODEL + col + tx * 8 + 4) = *(float4*)&acc[i][4];
    }
}

// ---------------------------------------------------------------------------
// RMSNorm fused with bf16 hi/lo split output (for the o-projection GEMM)
// ---------------------------------------------------------------------------
__global__ void rmsnorm_split(const float* __restrict__ O, const float* __restrict__ W,
                              __nv_bfloat16* __restrict__ hi, __nv_bfloat16* __restrict__ lo) {
    int row = blockIdx.x * 8 + threadIdx.y;
    int t = row / NH, h = row % NH;
    int lane = threadIdx.x;
    size_t base = (size_t)t * DMODEL + h * DHD + lane * 4;
    float4 x = *(const float4*)(O + base);
    float ss = x.x * x.x + x.y * x.y + x.z * x.z + x.w * x.w;
#pragma unroll
    for (int off = 16; off > 0; off >>= 1)
        ss += __shfl_xor_sync(0xffffffffu, ss, off);
    float r = rsqrtf(ss * (1.0f / 128.0f) + RMSEPS);
    float4 w = *(const float4*)(W + lane * 4);
    x.x *= r * w.x; x.y *= r * w.y; x.z *= r * w.z; x.w *= r * w.w;
    uint32_t h0, l0, h1, l1;
    split2(x.x, x.y, h0, l0);
    split2(x.z, x.w, h1, l1);
    *(uint2*)(hi + base) = make_uint2(h0, h1);
    *(uint2*)(lo + base) = make_uint2(l0, l1);
}

// ---------------------------------------------------------------------------
extern "C" void kernel_launch(void* const* d_in, const int* in_sizes, int n_in,
                              void* d_out, int out_size) {
    const float* hidden = (const float*)d_in[0];
    const float* q_w    = (const float*)d_in[2];
    const float* k_w    = (const float*)d_in[3];
    const float* v_w    = (const float*)d_in[4];
    const float* o_w    = (const float*)d_in[5];
    const float* fmq_w1 = (const float*)d_in[6];
    const float* fmq_b1 = (const float*)d_in[7];
    const float* fmq_w2 = (const float*)d_in[8];
    const float* fmq_b2 = (const float*)d_in[9];
    const float* fmk_w1 = (const float*)d_in[10];
    const float* fmk_b1 = (const float*)d_in[11];
    const float* fmk_w2 = (const float*)d_in[12];
    const float* fmk_b2 = (const float*)d_in[13];
    const float* rms_w  = (const float*)d_in[14];
    float* out = (float*)d_out;

    float *q, *k, *v, *o, *kv;
    __nv_bfloat16 *ahi, *alo, *whi, *wlo, *qhi, *qlo, *khi, *klo, *fwhi, *fwlo;
    cudaGetSymbolAddress((void**)&q,    g_q);
    cudaGetSymbolAddress((void**)&k,    g_k);
    cudaGetSymbolAddress((void**)&v,    g_v);
    cudaGetSymbolAddress((void**)&o,    g_o);
    cudaGetSymbolAddress((void**)&kv,   g_kv);
    cudaGetSymbolAddress((void**)&ahi,  g_ahi);
    cudaGetSymbolAddress((void**)&alo,  g_alo);
    cudaGetSymbolAddress((void**)&whi,  g_whi);
    cudaGetSymbolAddress((void**)&wlo,  g_wlo);
    cudaGetSymbolAddress((void**)&qhi,  g_qhi);
    cudaGetSymbolAddress((void**)&qlo,  g_qlo);
    cudaGetSymbolAddress((void**)&khi,  g_khi);
    cudaGetSymbolAddress((void**)&klo,  g_klo);
    cudaGetSymbolAddress((void**)&fwhi, g_fwhi);
    cudaGetSymbolAddress((void**)&fwlo, g_fwlo);

    cudaFuncSetAttribute(gemm_mma2, cudaFuncAttributeMaxDynamicSharedMemorySize,
                         GEMM_SMEM_BYTES);
    cudaFuncSetAttribute(featmap_mma, cudaFuncAttributeMaxDynamicSharedMemorySize,
                         FM_SMEM);

    const int nA = BT * DMODEL;       // 16M
    const int nW = DMODEL * DMODEL;   // 1M
    const int nF = DHD * DHD;         // 16K

    // Splits
    split_f32<<<nA / 1024, 256>>>(hidden, ahi, alo, nA);
    split_f32<<<nW / 1024, 256>>>(q_w, whi,          wlo,          nW);
    split_f32<<<nW / 1024, 256>>>(k_w, whi + nW,     wlo + nW,     nW);
    split_f32<<<nW / 1024, 256>>>(v_w, whi + 2 * nW, wlo + 2 * nW, nW);
    split_f32<<<nF / 1024, 256>>>(fmq_w1, fwhi,          fwlo,          nF);
    split_f32<<<nF / 1024, 256>>>(fmq_w2, fwhi + nF,     fwlo + nF,     nF);
    split_f32<<<nF / 1024, 256>>>(fmk_w1, fwhi + 2 * nF, fwlo + 2 * nF, nF);
    split_f32<<<nF / 1024, 256>>>(fmk_w2, fwhi + 3 * nF, fwlo + 3 * nF, nF);

    // QKV projection (one launch): q/k -> bf16 hi/lo, v -> f32
    gemm_mma2<<<dim3(24, 128), 256, GEMM_SMEM_BYTES>>>(
        ahi, alo, whi, wlo, qhi, qlo, khi, klo, v, nullptr, 0);

    // Feature maps via HMMA
    dim3 fm_grid(BT / 128, NH, 2);
    featmap_mma<<<fm_grid, 256, FM_SMEM>>>(qhi, qlo, fwhi, fwlo, fwhi + nF, fwlo + nF,
                                           fmq_b1, fmq_b2, q, QSCALE);
    featmap_mma<<<fm_grid, 256, FM_SMEM>>>(khi, klo, fwhi + 2 * nF, fwlo + 2 * nF,
                                           fwhi + 3 * nF, fwlo + 3 * nF,
                                           fmk_b1, fmk_b2, k, 1.0f);

    // Chunked linear attention
    chunk_kv<<<NBATCH * NCHUNK * NH, 256>>>(k, v, kv);
    dim3 cs_grid(NBATCH * NH, (DHD * DHD) / 256);
    cumsum_excl<<<cs_grid, 256>>>(kv);
    chunk_attn<<<NBATCH * NCHUNK * NH, 256>>>(q, k, v, kv, o);

    // RMSNorm fused with split for o-projection
    rmsnorm_split<<<(BT * NH) / 8, dim3(32, 8)>>>(o, rms_w, ahi, alo);

    // Output projection
    split_f32<<<nW / 1024, 256>>>(o_w, whi, wlo, nW);
    gemm_mma2<<<dim3(8, 128), 256, GEMM_SMEM_BYTES>>>(
        ahi, alo, whi, wlo, nullptr, nullptr, nullptr, nullptr, nullptr, out, 1);
}

// round 5
// speedup vs baseline: 2.0000x; 1.1007x over previous
#include <cuda_runtime.h>
#include <cuda_bf16.h>
#include <cstdint>
#include <cstddef>

// Problem constants
#define BT      16384
#define DMODEL  1024
#define NH      8
#define DHD     128
#define CHUNKL  64
#define NCHUNK  128
#define NBATCH  2
#define NCHTOT  2048          // NBATCH*NH*NCHUNK
#define QSCALE  0.08838834764831843f
#define RMSEPS  1e-5f

// Scratch buffers
__device__ float g_o[(size_t)BT * DMODEL];
__device__ float g_kv[(size_t)NCHTOT * 16384];
__device__ __nv_bfloat16 g_ahi[(size_t)BT * DMODEL];
__device__ __nv_bfloat16 g_alo[(size_t)BT * DMODEL];
__device__ __nv_bfloat16 g_whi[(size_t)3 * DMODEL * DMODEL];
__device__ __nv_bfloat16 g_wlo[(size_t)3 * DMODEL * DMODEL];
__device__ __nv_bfloat16 g_qhi[(size_t)BT * DMODEL];   // q projection (featmap input)
__device__ __nv_bfloat16 g_qlo[(size_t)BT * DMODEL];
__device__ __nv_bfloat16 g_khi[(size_t)BT * DMODEL];   // k projection
__device__ __nv_bfloat16 g_klo[(size_t)BT * DMODEL];
__device__ __nv_bfloat16 g_fwhi[4 * DHD * DHD];
__device__ __nv_bfloat16 g_fwlo[4 * DHD * DHD];
// chunk-tiled buffers: chunk id cid = (b*8+h)*128+n
__device__ __nv_bfloat16 g_qnh[(size_t)BT * DMODEL];   // phi_q natural [cid][hk][c][64]
__device__ __nv_bfloat16 g_qnl[(size_t)BT * DMODEL];
__device__ __nv_bfloat16 g_knh[(size_t)BT * DMODEL];   // phi_k natural
__device__ __nv_bfloat16 g_knl[(size_t)BT * DMODEL];
__device__ __nv_bfloat16 g_kth[(size_t)BT * DMODEL];   // phi_k transposed [cid][dk][t]
__device__ __nv_bfloat16 g_ktl[(size_t)BT * DMODEL];
__device__ __nv_bfloat16 g_vth[(size_t)BT * DMODEL];   // v transposed [cid][dv][t]
__device__ __nv_bfloat16 g_vtl[(size_t)BT * DMODEL];
__device__ __nv_bfloat16 g_sh[(size_t)NCHTOT * 16384]; // S_excl hi [cid][hk][dv][64]
__device__ __nv_bfloat16 g_sl[(size_t)NCHTOT * 16384];

#define SWZ(off) ((off) ^ (((off) >> 3) & 0x70))

__device__ __forceinline__ uint32_t smem_u32(const void* p) {
    uint32_t a;
    asm("{ .reg .u64 t; cvta.to.shared.u64 t, %1; cvt.u32.u64 %0, t; }" : "=r"(a) : "l"(p));
    return a;
}

__device__ __forceinline__ void ldsm_x4(uint32_t addr, uint32_t& r0, uint32_t& r1,
                                        uint32_t& r2, uint32_t& r3) {
    asm volatile("ldmatrix.sync.aligned.m8n8.x4.shared.b16 {%0,%1,%2,%3}, [%4];"
                 : "=r"(r0), "=r"(r1), "=r"(r2), "=r"(r3) : "r"(addr));
}

__device__ __forceinline__ void mma_bf16(float* d, const uint32_t* a, const uint32_t* b) {
    asm volatile(
        "mma.sync.aligned.m16n8k16.row.col.f32.bf16.bf16.f32 "
        "{%0,%1,%2,%3}, {%4,%5,%6,%7}, {%8,%9}, {%0,%1,%2,%3};"
        : "+f"(d[0]), "+f"(d[1]), "+f"(d[2]), "+f"(d[3])
        : "r"(a[0]), "r"(a[1]), "r"(a[2]), "r"(a[3]), "r"(b[0]), "r"(b[1]));
}

__device__ __forceinline__ void cp_async16(uint32_t saddr, const void* gaddr) {
    asm volatile("cp.async.cg.shared.global [%0], [%1], 16;" :: "r"(saddr), "l"(gaddr));
}
#define CP_COMMIT() asm volatile("cp.async.commit_group;" ::: "memory")
#define CP_WAIT0()  asm volatile("cp.async.wait_group 0;" ::: "memory")
#define CP_WAIT1()  asm volatile("cp.async.wait_group 1;" ::: "memory")

__device__ __forceinline__ void split2(float a, float b, uint32_t& hi, uint32_t& lo) {
    __nv_bfloat16 ha = __float2bfloat16(a), hb = __float2bfloat16(b);
    __nv_bfloat16 la = __float2bfloat16(a - __bfloat162float(ha));
    __nv_bfloat16 lb = __float2bfloat16(b - __bfloat162float(hb));
    __nv_bfloat162 hp = __halves2bfloat162(ha, hb);
    __nv_bfloat162 lp = __halves2bfloat162(la, lb);
    hi = *(uint32_t*)&hp; lo = *(uint32_t*)&lp;
}

// async tile copy: 128B rows, linear global source, SW128 smem dest
__device__ __forceinline__ void load_tile_async(uint32_t sdst, const void* gsrc,
                                                int slots, int tid) {
    for (int u = tid; u < slots; u += 256) {
        int row = u >> 3, cb = (u & 7) * 16;
        cp_async16(sdst + SWZ((uint32_t)(row * 128 + cb)),
                   (const char*)gsrc + (size_t)u * 16);
    }
}

// ---------------------------------------------------------------------------
__global__ void split_f32(const float* __restrict__ x, __nv_bfloat16* __restrict__ hi,
                          __nv_bfloat16* __restrict__ lo, int n) {
    int i = (blockIdx.x * blockDim.x + threadIdx.x) * 4;
    if (i >= n) return;
    float4 v = *(const float4*)(x + i);
    uint32_t h0, l0, h1, l1;
    split2(v.x, v.y, h0, l0);
    split2(v.z, v.w, h1, l1);
    *(uint2*)(hi + i) = make_uint2(h0, h1);
    *(uint2*)(lo + i) = make_uint2(l0, l1);
}

// ---------------------------------------------------------------------------
// HMMA GEMM: 128x128 CTA tile, BK=64, 8 warps.
// mode 0 (QKV): buf0 -> Qhi/Qlo, buf1 -> Khi/Klo (natural [t][1024] bf16 splits),
//               buf2 -> VT hi/lo (chunk-transposed [cid][dv][t])
// mode 1: f32 out to Cout.
// ---------------------------------------------------------------------------
#define GEMM_SMEM_BYTES (65536 + 1024)

__global__ __launch_bounds__(256) void gemm_mma2(
    const __nv_bfloat16* __restrict__ Ahi, const __nv_bfloat16* __restrict__ Alo,
    const __nv_bfloat16* __restrict__ Whi, const __nv_bfloat16* __restrict__ Wlo,
    __nv_bfloat16* __restrict__ Qhi, __nv_bfloat16* __restrict__ Qlo,
    __nv_bfloat16* __restrict__ Khi, __nv_bfloat16* __restrict__ Klo,
    __nv_bfloat16* __restrict__ VTh, __nv_bfloat16* __restrict__ VTl,
    float* __restrict__ Cout, int mode) {
    extern __shared__ char dynraw[];
    char* smem = (char*)(((uintptr_t)dynraw + 1023) & ~(uintptr_t)1023);

    const int tid = threadIdx.x;
    const int wid = tid >> 5;
    const int lane = tid & 31;
    const int n0 = blockIdx.x * 128;
    const int m0 = blockIdx.y * 128;
    const int wm = (wid & 3) * 32;
    const int wn = (wid >> 2) * 64;

    const uint32_t sAh = smem_u32(smem);
    const uint32_t sAl = sAh + 16384;
    const uint32_t sBh = sAh + 32768;
    const uint32_t sBl = sAh + 49152;

    float acc[2][8][4];
#pragma unroll
    for (int i = 0; i < 2; i++)
#pragma unroll
        for (int j = 0; j < 8; j++)
#pragma unroll
            for (int r = 0; r < 4; r++) acc[i][j][r] = 0.f;

    const char* srcA_h = (const char*)(Ahi + (size_t)m0 * 1024);
    const char* srcA_l = (const char*)(Alo + (size_t)m0 * 1024);
    const char* srcB_h = (const char*)(Whi + (size_t)n0 * 1024);
    const char* srcB_l = (const char*)(Wlo + (size_t)n0 * 1024);

    const int mat = lane >> 3;
    const int mrow = lane & 7;

    for (int kt = 0; kt < 16; kt++) {
        const size_t kbyte = (size_t)kt * 128;
#pragma unroll
        for (int l = 0; l < 4; l++) {
            int u = tid + 256 * l;
            int row = u >> 3;
            int cb = (u & 7) * 16;
            uint32_t dsw = SWZ((uint32_t)(row * 128 + cb));
            size_t src_off = (size_t)row * 2048 + kbyte + cb;
            *(uint4*)(smem + 0     + dsw) = *(const uint4*)(srcA_h + src_off);
            *(uint4*)(smem + 16384 + dsw) = *(const uint4*)(srcA_l + src_off);
            *(uint4*)(smem + 32768 + dsw) = *(const uint4*)(srcB_h + src_off);
            *(uint4*)(smem + 49152 + dsw) = *(const uint4*)(srcB_l + src_off);
        }
        __syncthreads();

#pragma unroll
        for (int kc = 0; kc < 4; kc++) {
            const int kb0 = kc * 32;
            uint32_t ah[2][4], al[2][4];
#pragma unroll
            for (int i = 0; i < 2; i++) {
                int arow = wm + i * 16 + (mat & 1) * 8 + mrow;
                int akb = kb0 + (mat >> 1) * 16;
                uint32_t off = SWZ((uint32_t)(arow * 128 + akb));
                ldsm_x4(sAh + off, ah[i][0], ah[i][1], ah[i][2], ah[i][3]);
                ldsm_x4(sAl + off, al[i][0], al[i][1], al[i][2], al[i][3]);
            }
#pragma unroll
            for (int p = 0; p < 4; p++) {
                int brow = wn + p * 16 + (mat >> 1) * 8 + mrow;
                int bkb = kb0 + (mat & 1) * 16;
                uint32_t off = SWZ((uint32_t)(brow * 128 + bkb));
                uint32_t bh[4], bl[4];
                ldsm_x4(sBh + off, bh[0], bh[1], bh[2], bh[3]);
                ldsm_x4(sBl + off, bl[0], bl[1], bl[2], bl[3]);
#pragma unroll
                for (int i = 0; i < 2; i++) {
                    mma_bf16(acc[i][2 * p],     ah[i], &bh[0]);
                    mma_bf16(acc[i][2 * p],     al[i], &bh[0]);
                    mma_bf16(acc[i][2 * p],     ah[i], &bl[0]);
                    mma_bf16(acc[i][2 * p + 1], ah[i], &bh[2]);
                    mma_bf16(acc[i][2 * p + 1], al[i], &bh[2]);
                    mma_bf16(acc[i][2 * p + 1], ah[i], &bl[2]);
                }
            }
        }
        __syncthreads();
    }

    const int crow = lane >> 2;
    const int ccol = (lane & 3) * 2;
    if (mode == 1) {
#pragma unroll
        for (int i = 0; i < 2; i++) {
            int m = m0 + wm + i * 16 + crow;
#pragma unroll
            for (int j = 0; j < 8; j++) {
                int n = n0 + wn + j * 8 + ccol;
                *(float2*)(Cout + (size_t)m * 1024 + n) = make_float2(acc[i][j][0], acc[i][j][1]);
                *(float2*)(Cout + (size_t)(m + 8) * 1024 + n) = make_float2(acc[i][j][2], acc[i][j][3]);
            }
        }
        return;
    }
    int buf = n0 >> 10;
    int ncol0 = n0 & 1023;
    if (buf == 2) {
        // v -> chunk-transposed bf16 hi/lo: VT[cid][dv][t]
#pragma unroll
        for (int i = 0; i < 2; i++) {
            int m = m0 + wm + i * 16 + crow;
            int bb = m >> 13, nn = (m >> 6) & 127, cc = m & 63;
#pragma unroll
            for (int j = 0; j < 8; j++) {
                int ng = ncol0 + wn + j * 8 + ccol;
                int h = ng >> 7, dv = ng & 127;
                size_t base = (((size_t)(bb * 8 + h) * 128 + nn) << 13) + (size_t)dv * 64 + cc;
                uint32_t hi, lo;
                split2(acc[i][j][0], acc[i][j][1], hi, lo);
                __nv_bfloat162 hp = *(__nv_bfloat162*)&hi;
                __nv_bfloat162 lp = *(__nv_bfloat162*)&lo;
                VTh[base] = hp.x; VTh[base + 64] = hp.y;
                VTl[base] = lp.x; VTl[base + 64] = lp.y;
                split2(acc[i][j][2], acc[i][j][3], hi, lo);
                hp = *(__nv_bfloat162*)&hi;
                lp = *(__nv_bfloat162*)&lo;
                VTh[base + 8] = hp.x; VTh[base + 72] = hp.y;
                VTl[base + 8] = lp.x; VTl[base + 72] = lp.y;
            }
        }
    } else {
        __nv_bfloat16* H = buf ? Khi : Qhi;
        __nv_bfloat16* L = buf ? Klo : Qlo;
#pragma unroll
        for (int i = 0; i < 2; i++) {
            int m = m0 + wm + i * 16 + crow;
#pragma unroll
            for (int j = 0; j < 8; j++) {
                int n = ncol0 + wn + j * 8 + ccol;
                uint32_t hi, lo;
                split2(acc[i][j][0], acc[i][j][1], hi, lo);
                *(uint32_t*)(H + (size_t)m * 1024 + n) = hi;
                *(uint32_t*)(L + (size_t)m * 1024 + n) = lo;
                split2(acc[i][j][2], acc[i][j][3], hi, lo);
                *(uint32_t*)(H + (size_t)(m + 8) * 1024 + n) = hi;
                *(uint32_t*)(L + (size_t)(m + 8) * 1024 + n) = lo;
            }
        }
    }
}

// ---------------------------------------------------------------------------
// Feature map via HMMA. Outputs chunk-tiled bf16 hi/lo:
//   natural: ON[cid][z][c][64]  (z = dk half)
//   if isK:  also OT[cid][dk][t]
// ---------------------------------------------------------------------------
#define FM_SMEM (131072 + 1024)

__global__ __launch_bounds__(256) void featmap_mma(
    const __nv_bfloat16* __restrict__ Xhi, const __nv_bfloat16* __restrict__ Xlo,
    const __nv_bfloat16* __restrict__ W1hi, const __nv_bfloat16* __restrict__ W1lo,
    const __nv_bfloat16* __restrict__ W2hi, const __nv_bfloat16* __restrict__ W2lo,
    const float* __restrict__ B1, const float* __restrict__ B2,
    __nv_bfloat16* __restrict__ ONh, __nv_bfloat16* __restrict__ ONl,
    __nv_bfloat16* __restrict__ OTh, __nv_bfloat16* __restrict__ OTl,
    float scale, int isK) {
    extern __shared__ char dynraw[];
    char* smem = (char*)(((uintptr_t)dynraw + 1023) & ~(uintptr_t)1023);
    const uint32_t sbase = smem_u32(smem);

    const int tid = threadIdx.x;
    const int wid = tid >> 5;
    const int lane = tid & 31;
    const int t0 = blockIdx.x * 128;
    const int h = blockIdx.y;
    const int z = blockIdx.z;
    const int wm = (wid & 3) * 32;
    const int wn = (wid >> 2) * 32;

    const __nv_bfloat16* wsel[4] = {W1hi, W1lo, W2hi, W2lo};

#pragma unroll
    for (int t = 0; t < 4; t++) {
        int half = t >> 1, hl = t & 1;
        const char* sp = (const char*)((hl ? Xlo : Xhi) +
                          (size_t)t0 * 1024 + h * 128 + half * 64);
#pragma unroll
        for (int l = 0; l < 4; l++) {
            int s = tid + 256 * l;
            int row = s >> 3, cb = (s & 7) * 16;
            cp_async16(sbase + t * 16384 + SWZ((uint32_t)(row * 128 + cb)),
                       sp + (size_t)row * 2048 + cb);
        }
    }
#pragma unroll
    for (int t = 0; t < 8; t++) {
        int half = t >> 2, wsub = (t >> 1) & 1, hl = t & 1;
        const char* sp = (const char*)wsel[wsub * 2 + hl] +
                         ((size_t)(z * 64) * 128 + half * 64) * 2;
#pragma unroll
        for (int l = 0; l < 2; l++) {
            int s = tid + 256 * l;
            int row = s >> 3, cb = (s & 7) * 16;
            cp_async16(sbase + 65536 + t * 8192 + SWZ((uint32_t)(row * 128 + cb)),
                       sp + (size_t)row * 256 + cb);
        }
    }
    CP_COMMIT();
    CP_WAIT0();
    __syncthreads();

    float acc1[2][4][4], acc2[2][4][4];
#pragma unroll
    for (int i = 0; i < 2; i++)
#pragma unroll
        for (int j = 0; j < 4; j++)
#pragma unroll
            for (int r = 0; r < 4; r++) { acc1[i][j][r] = 0.f; acc2[i][j][r] = 0.f; }

    const int mat = lane >> 3;
    const int mrow = lane & 7;

#pragma unroll
    for (int half = 0; half < 2; half++) {
        const uint32_t sXh = sbase + (half * 2 + 0) * 16384;
        const uint32_t sXl = sbase + (half * 2 + 1) * 16384;
        const uint32_t sW1h = sbase + 65536 + (half * 4 + 0) * 8192;
        const uint32_t sW1l = sbase + 65536 + (half * 4 + 1) * 8192;
        const uint32_t sW2h = sbase + 65536 + (half * 4 + 2) * 8192;
        const uint32_t sW2l = sbase + 65536 + (half * 4 + 3) * 8192;
#pragma unroll
        for (int kc = 0; kc < 4; kc++) {
            const int kb0 = kc * 32;
            uint32_t ah[2][4], al[2][4];
#pragma unroll
            for (int i = 0; i < 2; i++) {
                int arow = wm + i * 16 + (mat & 1) * 8 + mrow;
                int akb = kb0 + (mat >> 1) * 16;
                uint32_t off = SWZ((uint32_t)(arow * 128 + akb));
                ldsm_x4(sXh + off, ah[i][0], ah[i][1], ah[i][2], ah[i][3]);
                ldsm_x4(sXl + off, al[i][0], al[i][1], al[i][2], al[i][3]);
            }
#pragma unroll
            for (int p = 0; p < 2; p++) {
                int brow = wn + p * 16 + (mat >> 1) * 8 + mrow;
                int bkb = kb0 + (mat & 1) * 16;
                uint32_t off = SWZ((uint32_t)(brow * 128 + bkb));
                uint32_t b1h[4], b1l[4], b2h[4], b2l[4];
                ldsm_x4(sW1h + off, b1h[0], b1h[1], b1h[2], b1h[3]);
                ldsm_x4(sW1l + off, b1l[0], b1l[1], b1l[2], b1l[3]);
                ldsm_x4(sW2h + off, b2h[0], b2h[1], b2h[2], b2h[3]);
                ldsm_x4(sW2l + off, b2l[0], b2l[1], b2l[2], b2l[3]);
#pragma unroll
                for (int i = 0; i < 2; i++) {
                    mma_bf16(acc1[i][2 * p],     ah[i], &b1h[0]);
                    mma_bf16(acc1[i][2 * p],     al[i], &b1h[0]);
                    mma_bf16(acc1[i][2 * p],     ah[i], &b1l[0]);
                    mma_bf16(acc1[i][2 * p + 1], ah[i], &b1h[2]);
                    mma_bf16(acc1[i][2 * p + 1], al[i], &b1h[2]);
                    mma_bf16(acc1[i][2 * p + 1], ah[i], &b1l[2]);
                    mma_bf16(acc2[i][2 * p],     ah[i], &b2h[0]);
                    mma_bf16(acc2[i][2 * p],     al[i], &b2h[0]);
                    mma_bf16(acc2[i][2 * p],     ah[i], &b2l[0]);
                    mma_bf16(acc2[i][2 * p + 1], ah[i], &b2h[2]);
                    mma_bf16(acc2[i][2 * p + 1], al[i], &b2h[2]);
                    mma_bf16(acc2[i][2 * p + 1], ah[i], &b2l[2]);
                }
            }
        }
    }

    const int crow = lane >> 2;
    const int ccol = (lane & 3) * 2;
#pragma unroll
    for (int j = 0; j < 4; j++) {
        int d64 = wn + j * 8 + ccol;            // 0..63
        int nl = z * 64 + d64;
        float b1a = B1[nl], b1b = B1[nl + 1];
        float b2a = B2[nl], b2b = B2[nl + 1];
#pragma unroll
        for (int i = 0; i < 2; i++) {
#pragma unroll
            for (int rv = 0; rv < 2; rv++) {
                int m = t0 + wm + i * 16 + crow + rv * 8;
                float p0 = (acc1[i][j][rv * 2 + 0] + b1a) * (acc2[i][j][rv * 2 + 0] + b2a) * scale;
                float p1 = (acc1[i][j][rv * 2 + 1] + b1b) * (acc2[i][j][rv * 2 + 1] + b2b) * scale;
                uint32_t hi, lo;
                split2(p0, p1, hi, lo);
                int bb = m >> 13, nn = (m >> 6) & 127, cc = m & 63;
                size_t cidx = (size_t)(bb * 8 + h) * 128 + nn;
                size_t addrN = ((cidx * 2 + z) << 12) + cc * 64 + d64;
                *(uint32_t*)(ONh + addrN) = hi;
                *(uint32_t*)(ONl + addrN) = lo;
                if (isK) {
                    size_t addrT = (cidx << 13) + (size_t)nl * 64 + cc;
                    __nv_bfloat162 hp = *(__nv_bfloat162*)&hi;
                    __nv_bfloat162 lp = *(__nv_bfloat162*)&lo;
                    OTh[addrT] = hp.x; OTh[addrT + 64] = hp.y;
                    OTl[addrT] = lp.x; OTl[addrT + 64] = lp.y;
                }
            }
        }
    }
}

// ---------------------------------------------------------------------------
// chunk_kv via HMMA: KV^T[dv][dk] = sum_t V[t][dv] * K[t][dk]
// A = VT[cid] (rows dv, cols t), B = KT[cid] (rows dk, cols t). f32 out,
// layout KV[cid][hk][dv][64].
// ---------------------------------------------------------------------------
#define CKV_SMEM (65536 + 1024)

__global__ __launch_bounds__(256) void chunk_kv_mma(
    const __nv_bfloat16* __restrict__ VTh, const __nv_bfloat16* __restrict__ VTl,
    const __nv_bfloat16* __restrict__ KTh, const __nv_bfloat16* __restrict__ KTl,
    float* __restrict__ KV) {
    extern __shared__ char dynraw[];
    char* smem = (char*)(((uintptr_t)dynraw + 1023) & ~(uintptr_t)1023);
    const uint32_t sbase = smem_u32(smem);
    const int tid = threadIdx.x;
    const int wid = tid >> 5;
    const int lane = tid & 31;
    const size_t cid = blockIdx.x;
    const int wm = (wid & 3) * 32;       // dv
    const int wn = (wid >> 2) * 64;      // dk

    load_tile_async(sbase + 0,     VTh + (cid << 13), 1024, tid);
    load_tile_async(sbase + 16384, VTl + (cid << 13), 1024, tid);
    load_tile_async(sbase + 32768, KTh + (cid << 13), 1024, tid);
    load_tile_async(sbase + 49152, KTl + (cid << 13), 1024, tid);
    CP_COMMIT();
    CP_WAIT0();
    __syncthreads();

    float acc[2][8][4];
#pragma unroll
    for (int i = 0; i < 2; i++)
#pragma unroll
        for (int j = 0; j < 8; j++)
#pragma unroll
            for (int r = 0; r < 4; r++) acc[i][j][r] = 0.f;

    const int mat = lane >> 3;
    const int mrow = lane & 7;

#pragma unroll
    for (int kc = 0; kc < 4; kc++) {
        const int kb0 = kc * 32;
        uint32_t ah[2][4], al[2][4];
#pragma unroll
        for (int i = 0; i < 2; i++) {
            int arow = wm + i * 16 + (mat & 1) * 8 + mrow;
            int akb = kb0 + (mat >> 1) * 16;
            uint32_t off = SWZ((uint32_t)(arow * 128 + akb));
            ldsm_x4(sbase + off,         ah[i][0], ah[i][1], ah[i][2], ah[i][3]);
            ldsm_x4(sbase + 16384 + off, al[i][0], al[i][1], al[i][2], al[i][3]);
        }
#pragma unroll
        for (int p = 0; p < 4; p++) {
            int brow = wn + p * 16 + (mat >> 1) * 8 + mrow;
            int bkb = kb0 + (mat & 1) * 16;
            uint32_t off = SWZ((uint32_t)(brow * 128 + bkb));
            uint32_t bh[4], bl[4];
            ldsm_x4(sbase + 32768 + off, bh[0], bh[1], bh[2], bh[3]);
            ldsm_x4(sbase + 49152 + off, bl[0], bl[1], bl[2], bl[3]);
#pragma unroll
            for (int i = 0; i < 2; i++) {
                mma_bf16(acc[i][2 * p],     ah[i], &bh[0]);
                mma_bf16(acc[i][2 * p],     al[i], &bh[0]);
                mma_bf16(acc[i][2 * p],     ah[i], &bl[0]);
                mma_bf16(acc[i][2 * p + 1], ah[i], &bh[2]);
                mma_bf16(acc[i][2 * p + 1], al[i], &bh[2]);
                mma_bf16(acc[i][2 * p + 1], ah[i], &bl[2]);
            }
        }
    }

    const int crow = lane >> 2;
    const int ccol = (lane & 3) * 2;
    const int hk = wn >> 6;
#pragma unroll
    for (int i = 0; i < 2; i++) {
#pragma unroll
        for (int rv = 0; rv < 2; rv++) {
            int dv = wm + i * 16 + crow + rv * 8;
#pragma unroll
            for (int j = 0; j < 8; j++) {
                int dk64 = (wn & 63) + j * 8 + ccol;
                size_t addr = (cid << 14) + hk * 8192 + (size_t)dv * 64 + dk64;
                *(float2*)(KV + addr) = make_float2(acc[i][j][rv * 2], acc[i][j][rv * 2 + 1]);
            }
        }
    }
}

// ---------------------------------------------------------------------------
// exclusive cumsum over chunk axis + bf16 hi/lo split output
// ---------------------------------------------------------------------------
__global__ void cumsum_split(const float* __restrict__ KV,
                             __nv_bfloat16* __restrict__ Sh,
                             __nv_bfloat16* __restrict__ Sl) {
    int bh = blockIdx.x;
    size_t i = blockIdx.y * 256 + threadIdx.x;
    float acc = 0.f;
    for (int n = 0; n < NCHUNK; n++) {
        size_t idx = (((size_t)bh * 128 + n) << 14) + i;
        float v = KV[idx];
        __nv_bfloat16 h = __float2bfloat16(acc);
        Sh[idx] = h;
        Sl[idx] = __float2bfloat16(acc - __bfloat162float(h));
        acc += v;
    }
}

// ---------------------------------------------------------------------------
// chunk attention via HMMA:
//   A = Q K^T (masked), O = A V + Q S_excl. One CTA per chunk.
// smem: Q(32K) K(32K) VT(32K) ST(64K) A(16K) = 176KB
// ---------------------------------------------------------------------------
#define CA_SMEM (180224 + 1024)

__global__ __launch_bounds__(256) void chunk_attn_mma(
    const __nv_bfloat16* __restrict__ QNh, const __nv_bfloat16* __restrict__ QNl,
    const __nv_bfloat16* __restrict__ KNh, const __nv_bfloat16* __restrict__ KNl,
    const __nv_bfloat16* __restrict__ VTh, const __nv_bfloat16* __restrict__ VTl,
    const __nv_bfloat16* __restrict__ Sh,  const __nv_bfloat16* __restrict__ Sl,
    float* __restrict__ O) {
    extern __shared__ char dynraw[];
    char* smem = (char*)(((uintptr_t)dynraw + 1023) & ~(uintptr_t)1023);
    const uint32_t sQh = smem_u32(smem);
    const uint32_t sQl = sQh + 16384;
    const uint32_t sKh = sQh + 32768;
    const uint32_t sKl = sQh + 49152;
    const uint32_t sVh = sQh + 65536;
    const uint32_t sVl = sQh + 81920;
    const uint32_t sSh = sQh + 98304;
    const uint32_t sSl = sQh + 131072;
    const uint32_t sAh = sQh + 163840;
    const uint32_t sAl = sQh + 172032;

    const int tid = threadIdx.x;
    const int wid = tid >> 5;
    const int lane = tid & 31;
    const size_t cid = blockIdx.x;
    const int n = cid & 127;
    const int h = (cid >> 7) & 7;
    const int b = (int)(cid >> 10);

    // group 1: Q, K
    load_tile_async(sQh, QNh + (cid << 13), 1024, tid);
    load_tile_async(sQl, QNl + (cid << 13), 1024, tid);
    load_tile_async(sKh, KNh + (cid << 13), 1024, tid);
    load_tile_async(sKl, KNl + (cid << 13), 1024, tid);
    CP_COMMIT();
    // group 2: VT, ST
    load_tile_async(sVh, VTh + (cid << 13), 1024, tid);
    load_tile_async(sVl, VTl + (cid << 13), 1024, tid);
    load_tile_async(sSh, Sh + (cid << 14), 2048, tid);
    load_tile_async(sSl, Sl + (cid << 14), 2048, tid);
    CP_COMMIT();
    CP_WAIT1();
    __syncthreads();

    const int mat = lane >> 3;
    const int mrow = lane & 7;
    const int crow = lane >> 2;
    const int ccol = (lane & 3) * 2;

    // ---- Step 1: A = Q K^T, warp tile 32x16 (wm1 2x, wn1 4x)
    {
        const int wm1 = (wid & 1) * 32;
        const int wn1 = (wid >> 1) * 16;
        float acc[2][2][4];
#pragma unroll
        for (int i = 0; i < 2; i++)
#pragma unroll
            for (int j = 0; j < 2; j++)
#pragma unroll
                for (int r = 0; r < 4; r++) acc[i][j][r] = 0.f;

#pragma unroll
        for (int kc = 0; kc < 8; kc++) {
            int rbase = (kc >> 2) * 64;
            int kb0 = (kc & 3) * 32;
            uint32_t ah[2][4], al[2][4];
#pragma unroll
            for (int i = 0; i < 2; i++) {
                int arow = rbase + wm1 + i * 16 + (mat & 1) * 8 + mrow;
                int akb = kb0 + (mat >> 1) * 16;
                uint32_t off = SWZ((uint32_t)(arow * 128 + akb));
                ldsm_x4(sQh + off, ah[i][0], ah[i][1], ah[i][2], ah[i][3]);
                ldsm_x4(sQl + off, al[i][0], al[i][1], al[i][2], al[i][3]);
            }
            int brow = rbase + wn1 + (mat >> 1) * 8 + mrow;
            int bkb = kb0 + (mat & 1) * 16;
            uint32_t off = SWZ((uint32_t)(brow * 128 + bkb));
            uint32_t bh[4], bl[4];
            ldsm_x4(sKh + off, bh[0], bh[1], bh[2], bh[3]);
            ldsm_x4(sKl + off, bl[0], bl[1], bl[2], bl[3]);
#pragma unroll
            for (int i = 0; i < 2; i++) {
                mma_bf16(acc[i][0], ah[i], &bh[0]);
                mma_bf16(acc[i][0], al[i], &bh[0]);
                mma_bf16(acc[i][0], ah[i], &bl[0]);
                mma_bf16(acc[i][1], ah[i], &bh[2]);
                mma_bf16(acc[i][1], al[i], &bh[2]);
                mma_bf16(acc[i][1], ah[i], &bl[2]);
            }
        }
        // mask + split + store A
#pragma unroll
        for (int i = 0; i < 2; i++) {
#pragma unroll
            for (int rv = 0; rv < 2; rv++) {
                int c = wm1 + i * 16 + crow + rv * 8;
#pragma unroll
                for (int j = 0; j < 2; j++) {
                    int s = wn1 + j * 8 + ccol;
                    float v0 = (s <= c)     ? acc[i][j][rv * 2 + 0] : 0.f;
                    float v1 = (s + 1 <= c) ? acc[i][j][rv * 2 + 1] : 0.f;
                    uint32_t hi, lo;
                    split2(v0, v1, hi, lo);
                    uint32_t off = SWZ((uint32_t)(c * 128 + s * 2));
                    *(uint32_t*)(uintptr_t)0; // placeholder removed below
                    asm volatile("st.shared.b32 [%0], %1;" :: "r"(sAh + off), "r"(hi));
                    asm volatile("st.shared.b32 [%0], %1;" :: "r"(sAl + off), "r"(lo));
                }
            }
        }
    }
    CP_WAIT0();
    __syncthreads();

    // ---- Step 2: O = A V + Q S, warp tile 32x32 (wm2 2x, wn2 4x)
    const int wm2 = (wid & 1) * 32;
    const int wn2 = (wid >> 1) * 32;
    float acc[2][4][4];
#pragma unroll
    for (int i = 0; i < 2; i++)
#pragma unroll
        for (int j = 0; j < 4; j++)
#pragma unroll
            for (int r = 0; r < 4; r++) acc[i][j][r] = 0.f;

    // 2a: A @ V  (K = 64 over s)
#pragma unroll
    for (int kc = 0; kc < 4; kc++) {
        int kb0 = kc * 32;
        uint32_t ah[2][4], al[2][4];
#pragma unroll
        for (int i = 0; i < 2; i++) {
            int arow = wm2 + i * 16 + (mat & 1) * 8 + mrow;
            int akb = kb0 + (mat >> 1) * 16;
            uint32_t off = SWZ((uint32_t)(arow * 128 + akb));
            ldsm_x4(sAh + off, ah[i][0], ah[i][1], ah[i][2], ah[i][3]);
            ldsm_x4(sAl + off, al[i][0], al[i][1], al[i][2], al[i][3]);
        }
#pragma unroll
        for (int p = 0; p < 2; p++) {
            int brow = wn2 + p * 16 + (mat >> 1) * 8 + mrow;
            int bkb = kb0 + (mat & 1) * 16;
            uint32_t off = SWZ((uint32_t)(brow * 128 + bkb));
            uint32_t bh[4], bl[4];
            ldsm_x4(sVh + off, bh[0], bh[1], bh[2], bh[3]);
            ldsm_x4(sVl + off, bl[0], bl[1], bl[2], bl[3]);
#pragma unroll
            for (int i = 0; i < 2; i++) {
                mma_bf16(acc[i][2 * p],     ah[i], &bh[0]);
                mma_bf16(acc[i][2 * p],     al[i], &bh[0]);
                mma_bf16(acc[i][2 * p],     ah[i], &bl[0]);
                mma_bf16(acc[i][2 * p + 1], ah[i], &bh[2]);
                mma_bf16(acc[i][2 * p + 1], al[i], &bh[2]);
                mma_bf16(acc[i][2 * p + 1], ah[i], &bl[2]);
            }
        }
    }
    // 2b: Q @ S  (K = 128 over dk)
#pragma unroll
    for (int kc = 0; kc < 8; kc++) {
        int qrbase = (kc >> 2) * 64;
        int srbase = (kc >> 2) * 128;
        int kb0 = (kc & 3) * 32;
        uint32_t ah[2][4], al[2][4];
#pragma unroll
        for (int i = 0; i < 2; i++) {
            int arow = qrbase + wm2 + i * 16 + (mat & 1) * 8 + mrow;
            int akb = kb0 + (mat >> 1) * 16;
            uint32_t off = SWZ((uint32_t)(arow * 128 + akb));
            ldsm_x4(sQh + off, ah[i][0], ah[i][1], ah[i][2], ah[i][3]);
            ldsm_x4(sQl + off, al[i][0], al[i][1], al[i][2], al[i][3]);
        }
#pragma unroll
        for (int p = 0; p < 2; p++) {
            int brow = srbase + wn2 + p * 16 + (mat >> 1) * 8 + mrow;
            int bkb = kb0 + (mat & 1) * 16;
            uint32_t off = SWZ((uint32_t)(brow * 128 + bkb));
            uint32_t bh[4], bl[4];
            ldsm_x4(sSh + off, bh[0], bh[1], bh[2], bh[3]);
            ldsm_x4(sSl + off, bl[0], bl[1], bl[2], bl[3]);
#pragma unroll
            for (int i = 0; i < 2; i++) {
                mma_bf16(acc[i][2 * p],     ah[i], &bh[0]);
                mma_bf16(acc[i][2 * p],     al[i], &bh[0]);
                mma_bf16(acc[i][2 * p],     ah[i], &bl[0]);
                mma_bf16(acc[i][2 * p + 1], ah[i], &bh[2]);
                mma_bf16(acc[i][2 * p + 1], al[i], &bh[2]);
                mma_bf16(acc[i][2 * p + 1], ah[i], &bl[2]);
            }
        }
    }

    // write O (f32, [t][1024])
    const size_t tbase = (size_t)b * 8192 + (size_t)n * 64;
#pragma unroll
    for (int i = 0; i < 2; i++) {
#pragma unroll
        for (int rv = 0; rv < 2; rv++) {
            size_t t = tbase + wm2 + i * 16 + crow + rv * 8;
#pragma unroll
            for (int j = 0; j < 4; j++) {
                int dv = wn2 + j * 8 + ccol;
                *(float2*)(O + t * 1024 + h * 128 + dv) =
                    make_float2(acc[i][j][rv * 2], acc[i][j][rv * 2 + 1]);
            }
        }
    }
}

// ---------------------------------------------------------------------------
__global__ void rmsnorm_split(const float* __restrict__ O, const float* __restrict__ W,
                              __nv_bfloat16* __restrict__ hi, __nv_bfloat16* __restrict__ lo) {
    int row = blockIdx.x * 8 + threadIdx.y;
    int t = row / NH, h = row % NH;
    int lane = threadIdx.x;
    size_t base = (size_t)t * DMODEL + h * DHD + lane * 4;
    float4 x = *(const float4*)(O + base);
    float ss = x.x * x.x + x.y * x.y + x.z * x.z + x.w * x.w;
#pragma unroll
    for (int off = 16; off > 0; off >>= 1)
        ss += __shfl_xor_sync(0xffffffffu, ss, off);
    float r = rsqrtf(ss * (1.0f / 128.0f) + RMSEPS);
    float4 w = *(const float4*)(W + lane * 4);
    x.x *= r * w.x; x.y *= r * w.y; x.z *= r * w.z; x.w *= r * w.w;
    uint32_t h0, l0, h1, l1;
    split2(x.x, x.y, h0, l0);
    split2(x.z, x.w, h1, l1);
    *(uint2*)(hi + base) = make_uint2(h0, h1);
    *(uint2*)(lo + base) = make_uint2(l0, l1);
}

// ---------------------------------------------------------------------------
extern "C" void kernel_launch(void* const* d_in, const int* in_sizes, int n_in,
                              void* d_out, int out_size) {
    const float* hidden = (const float*)d_in[0];
    const float* q_w    = (const float*)d_in[2];
    const float* k_w    = (const float*)d_in[3];
    const float* v_w    = (const float*)d_in[4];
    const float* o_w    = (const float*)d_in[5];
    const float* fmq_w1 = (const float*)d_in[6];
    const float* fmq_b1 = (const float*)d_in[7];
    const float* fmq_w2 = (const float*)d_in[8];
    const float* fmq_b2 = (const float*)d_in[9];
    const float* fmk_w1 = (const float*)d_in[10];
    const float* fmk_b1 = (const float*)d_in[11];
    const float* fmk_w2 = (const float*)d_in[12];
    const float* fmk_b2 = (const float*)d_in[13];
    const float* rms_w  = (const float*)d_in[14];
    float* out = (float*)d_out;

    float *o, *kv;
    __nv_bfloat16 *ahi, *alo, *whi, *wlo, *qhi, *qlo, *khi, *klo, *fwhi, *fwlo;
    __nv_bfloat16 *qnh, *qnl, *knh, *knl, *kth, *ktl, *vth, *vtl, *sh, *sl;
    cudaGetSymbolAddress((void**)&o,    g_o);
    cudaGetSymbolAddress((void**)&kv,   g_kv);
    cudaGetSymbolAddress((void**)&ahi,  g_ahi);
    cudaGetSymbolAddress((void**)&alo,  g_alo);
    cudaGetSymbolAddress((void**)&whi,  g_whi);
    cudaGetSymbolAddress((void**)&wlo,  g_wlo);
    cudaGetSymbolAddress((void**)&qhi,  g_qhi);
    cudaGetSymbolAddress((void**)&qlo,  g_qlo);
    cudaGetSymbolAddress((void**)&khi,  g_khi);
    cudaGetSymbolAddress((void**)&klo,  g_klo);
    cudaGetSymbolAddress((void**)&fwhi, g_fwhi);
    cudaGetSymbolAddress((void**)&fwlo, g_fwlo);
    cudaGetSymbolAddress((void**)&qnh,  g_qnh);
    cudaGetSymbolAddress((void**)&qnl,  g_qnl);
    cudaGetSymbolAddress((void**)&knh,  g_knh);
    cudaGetSymbolAddress((void**)&knl,  g_knl);
    cudaGetSymbolAddress((void**)&kth,  g_kth);
    cudaGetSymbolAddress((void**)&ktl,  g_ktl);
    cudaGetSymbolAddress((void**)&vth,  g_vth);
    cudaGetSymbolAddress((void**)&vtl,  g_vtl);
    cudaGetSymbolAddress((void**)&sh,   g_sh);
    cudaGetSymbolAddress((void**)&sl,   g_sl);

    cudaFuncSetAttribute(gemm_mma2, cudaFuncAttributeMaxDynamicSharedMemorySize, GEMM_SMEM_BYTES);
    cudaFuncSetAttribute(featmap_mma, cudaFuncAttributeMaxDynamicSharedMemorySize, FM_SMEM);
    cudaFuncSetAttribute(chunk_kv_mma, cudaFuncAttributeMaxDynamicSharedMemorySize, CKV_SMEM);
    cudaFuncSetAttribute(chunk_attn_mma, cudaFuncAttributeMaxDynamicSharedMemorySize, CA_SMEM);

    const int nA = BT * DMODEL;
    const int nW = DMODEL * DMODEL;
    const int nF = DHD * DHD;

    // Splits
    split_f32<<<nA / 1024, 256>>>(hidden, ahi, alo, nA);
    split_f32<<<nW / 1024, 256>>>(q_w, whi,          wlo,          nW);
    split_f32<<<nW / 1024, 256>>>(k_w, whi + nW,     wlo + nW,     nW);
    split_f32<<<nW / 1024, 256>>>(v_w, whi + 2 * nW, wlo + 2 * nW, nW);
    split_f32<<<nF / 1024, 256>>>(fmq_w1, fwhi,          fwlo,          nF);
    split_f32<<<nF / 1024, 256>>>(fmq_w2, fwhi + nF,     fwlo + nF,     nF);
    split_f32<<<nF / 1024, 256>>>(fmk_w1, fwhi + 2 * nF, fwlo + 2 * nF, nF);
    split_f32<<<nF / 1024, 256>>>(fmk_w2, fwhi + 3 * nF, fwlo + 3 * nF, nF);

    // QKV projection: q/k natural bf16 splits, v -> chunk-transposed VT
    gemm_mma2<<<dim3(24, 128), 256, GEMM_SMEM_BYTES>>>(
        ahi, alo, whi, wlo, qhi, qlo, khi, klo, vth, vtl, nullptr, 0);

    // Feature maps -> chunk-tiled layouts
    dim3 fm_grid(BT / 128, NH, 2);
    featmap_mma<<<fm_grid, 256, FM_SMEM>>>(qhi, qlo, fwhi, fwlo, fwhi + nF, fwlo + nF,
                                           fmq_b1, fmq_b2, qnh, qnl, nullptr, nullptr,
                                           QSCALE, 0);
    featmap_mma<<<fm_grid, 256, FM_SMEM>>>(khi, klo, fwhi + 2 * nF, fwlo + 2 * nF,
                                           fwhi + 3 * nF, fwlo + 3 * nF,
                                           fmk_b1, fmk_b2, knh, knl, kth, ktl,
                                           1.0f, 1);

    // Chunked linear attention (all HMMA)
    chunk_kv_mma<<<NCHTOT, 256, CKV_SMEM>>>(vth, vtl, kth, ktl, kv);
    cumsum_split<<<dim3(NBATCH * NH, 64), 256>>>(kv, sh, sl);
    chunk_attn_mma<<<NCHTOT, 256, CA_SMEM>>>(qnh, qnl, knh, knl, vth, vtl, sh, sl, o);

    // RMSNorm + split, then output projection
    rmsnorm_split<<<(BT * NH) / 8, dim3(32, 8)>>>(o, rms_w, ahi, alo);
    split_f32<<<nW / 1024, 256>>>(o_w, whi, wlo, nW);
    gemm_mma2<<<dim3(8, 128), 256, GEMM_SMEM_BYTES>>>(
        ahi, alo, whi, wlo, nullptr, nullptr, nullptr, nullptr, nullptr, nullptr, out, 1);
}

// round 6
// speedup vs baseline: 2.7847x; 1.3924x over previous
#include <cuda_runtime.h>
#include <cuda_bf16.h>
#include <cstdint>
#include <cstddef>

// Problem constants
#define BT      16384
#define DMODEL  1024
#define NH      8
#define DHD     128
#define CHUNKL  64
#define NCHUNK  128
#define NBATCH  2
#define NCHTOT  2048          // NBATCH*NH*NCHUNK
#define QSCALE  0.08838834764831843f
#define RMSEPS  1e-5f

// Scratch buffers
__device__ float g_o[(size_t)BT * DMODEL];
__device__ float g_kv[(size_t)NCHTOT * 16384];
__device__ __nv_bfloat16 g_ahi[(size_t)BT * DMODEL];
__device__ __nv_bfloat16 g_alo[(size_t)BT * DMODEL];
__device__ __nv_bfloat16 g_whi[(size_t)3 * DMODEL * DMODEL];
__device__ __nv_bfloat16 g_wlo[(size_t)3 * DMODEL * DMODEL];
__device__ __nv_bfloat16 g_qhi[(size_t)BT * DMODEL];   // q projection (featmap input)
__device__ __nv_bfloat16 g_qlo[(size_t)BT * DMODEL];
__device__ __nv_bfloat16 g_khi[(size_t)BT * DMODEL];   // k projection
__device__ __nv_bfloat16 g_klo[(size_t)BT * DMODEL];
__device__ __nv_bfloat16 g_fwhi[4 * DHD * DHD];
__device__ __nv_bfloat16 g_fwlo[4 * DHD * DHD];
// chunk-tiled buffers: chunk id cid = (b*8+h)*128+n
__device__ __nv_bfloat16 g_qnh[(size_t)BT * DMODEL];   // phi_q natural [cid][hk][c][64]
__device__ __nv_bfloat16 g_qnl[(size_t)BT * DMODEL];
__device__ __nv_bfloat16 g_knh[(size_t)BT * DMODEL];   // phi_k natural
__device__ __nv_bfloat16 g_knl[(size_t)BT * DMODEL];
__device__ __nv_bfloat16 g_kth[(size_t)BT * DMODEL];   // phi_k transposed [cid][dk][t]
__device__ __nv_bfloat16 g_ktl[(size_t)BT * DMODEL];
__device__ __nv_bfloat16 g_vth[(size_t)BT * DMODEL];   // v transposed [cid][dv][t]
__device__ __nv_bfloat16 g_vtl[(size_t)BT * DMODEL];
__device__ __nv_bfloat16 g_sh[(size_t)NCHTOT * 16384]; // S_excl hi [cid][hk][dv][64]
__device__ __nv_bfloat16 g_sl[(size_t)NCHTOT * 16384];

#define SWZ(off) ((off) ^ (((off) >> 3) & 0x70))

__device__ __forceinline__ uint32_t smem_u32(const void* p) {
    uint32_t a;
    asm("{ .reg .u64 t; cvta.to.shared.u64 t, %1; cvt.u32.u64 %0, t; }" : "=r"(a) : "l"(p));
    return a;
}

__device__ __forceinline__ void ldsm_x4(uint32_t addr, uint32_t& r0, uint32_t& r1,
                                        uint32_t& r2, uint32_t& r3) {
    asm volatile("ldmatrix.sync.aligned.m8n8.x4.shared.b16 {%0,%1,%2,%3}, [%4];"
                 : "=r"(r0), "=r"(r1), "=r"(r2), "=r"(r3) : "r"(addr));
}

__device__ __forceinline__ void mma_bf16(float* d, const uint32_t* a, const uint32_t* b) {
    asm volatile(
        "mma.sync.aligned.m16n8k16.row.col.f32.bf16.bf16.f32 "
        "{%0,%1,%2,%3}, {%4,%5,%6,%7}, {%8,%9}, {%0,%1,%2,%3};"
        : "+f"(d[0]), "+f"(d[1]), "+f"(d[2]), "+f"(d[3])
        : "r"(a[0]), "r"(a[1]), "r"(a[2]), "r"(a[3]), "r"(b[0]), "r"(b[1]));
}

__device__ __forceinline__ void cp_async16(uint32_t saddr, const void* gaddr) {
    asm volatile("cp.async.cg.shared.global [%0], [%1], 16;" :: "r"(saddr), "l"(gaddr));
}
#define CP_COMMIT() asm volatile("cp.async.commit_group;" ::: "memory")
#define CP_WAIT0()  asm volatile("cp.async.wait_group 0;" ::: "memory")
#define CP_WAIT1()  asm volatile("cp.async.wait_group 1;" ::: "memory")

__device__ __forceinline__ void split2(float a, float b, uint32_t& hi, uint32_t& lo) {
    __nv_bfloat16 ha = __float2bfloat16(a), hb = __float2bfloat16(b);
    __nv_bfloat16 la = __float2bfloat16(a - __bfloat162float(ha));
    __nv_bfloat16 lb = __float2bfloat16(b - __bfloat162float(hb));
    __nv_bfloat162 hp = __halves2bfloat162(ha, hb);
    __nv_bfloat162 lp = __halves2bfloat162(la, lb);
    hi = *(uint32_t*)&hp; lo = *(uint32_t*)&lp;
}

// async tile copy: 128B rows, linear global source, SW128 smem dest
__device__ __forceinline__ void load_tile_async(uint32_t sdst, const void* gsrc,
                                                int slots, int tid) {
    for (int u = tid; u < slots; u += 256) {
        int row = u >> 3, cb = (u & 7) * 16;
        cp_async16(sdst + SWZ((uint32_t)(row * 128 + cb)),
                   (const char*)gsrc + (size_t)u * 16);
    }
}

// ---------------------------------------------------------------------------
__global__ void split_f32(const float* __restrict__ x, __nv_bfloat16* __restrict__ hi,
                          __nv_bfloat16* __restrict__ lo, int n) {
    int i = (blockIdx.x * blockDim.x + threadIdx.x) * 4;
    if (i >= n) return;
    float4 v = *(const float4*)(x + i);
    uint32_t h0, l0, h1, l1;
    split2(v.x, v.y, h0, l0);
    split2(v.z, v.w, h1, l1);
    *(uint2*)(hi + i) = make_uint2(h0, h1);
    *(uint2*)(lo + i) = make_uint2(l0, l1);
}

// ---------------------------------------------------------------------------
// HMMA GEMM, 2-stage cp.async pipeline. 128x128 CTA tile, BK=64, 8 warps.
// mode 0 (QKV): buf0 -> Qhi/Qlo, buf1 -> Khi/Klo (natural [t][1024] bf16 splits),
//               buf2 -> VT hi/lo (chunk-transposed [cid][dv][t])
// mode 1: f32 out to Cout.
// ---------------------------------------------------------------------------
#define GEMM_STAGE   65536
#define GEMM_SMEM_BYTES (2 * GEMM_STAGE + 1024)

__device__ __forceinline__ void gemm_load_stage(uint32_t sdst,
                                                const char* Ah, const char* Al,
                                                const char* Bh, const char* Bl,
                                                size_t kbyte, int tid) {
#pragma unroll
    for (int l = 0; l < 4; l++) {
        int u = tid + 256 * l;
        int row = u >> 3;
        int cb = (u & 7) * 16;
        uint32_t dsw = SWZ((uint32_t)(row * 128 + cb));
        size_t off = (size_t)row * 2048 + kbyte + cb;
        cp_async16(sdst + dsw,         Ah + off);
        cp_async16(sdst + 16384 + dsw, Al + off);
        cp_async16(sdst + 32768 + dsw, Bh + off);
        cp_async16(sdst + 49152 + dsw, Bl + off);
    }
}

__global__ __launch_bounds__(256) void gemm_mma2(
    const __nv_bfloat16* __restrict__ Ahi, const __nv_bfloat16* __restrict__ Alo,
    const __nv_bfloat16* __restrict__ Whi, const __nv_bfloat16* __restrict__ Wlo,
    __nv_bfloat16* __restrict__ Qhi, __nv_bfloat16* __restrict__ Qlo,
    __nv_bfloat16* __restrict__ Khi, __nv_bfloat16* __restrict__ Klo,
    __nv_bfloat16* __restrict__ VTh, __nv_bfloat16* __restrict__ VTl,
    float* __restrict__ Cout, int mode) {
    extern __shared__ char dynraw[];
    char* smem = (char*)(((uintptr_t)dynraw + 1023) & ~(uintptr_t)1023);
    const uint32_t sbase = smem_u32(smem);

    const int tid = threadIdx.x;
    const int wid = tid >> 5;
    const int lane = tid & 31;
    const int n0 = blockIdx.x * 128;
    const int m0 = blockIdx.y * 128;
    const int wm = (wid & 3) * 32;
    const int wn = (wid >> 2) * 64;

    float acc[2][8][4];
#pragma unroll
    for (int i = 0; i < 2; i++)
#pragma unroll
        for (int j = 0; j < 8; j++)
#pragma unroll
            for (int r = 0; r < 4; r++) acc[i][j][r] = 0.f;

    const char* srcA_h = (const char*)(Ahi + (size_t)m0 * 1024);
    const char* srcA_l = (const char*)(Alo + (size_t)m0 * 1024);
    const char* srcB_h = (const char*)(Whi + (size_t)n0 * 1024);
    const char* srcB_l = (const char*)(Wlo + (size_t)n0 * 1024);

    const int mat = lane >> 3;
    const int mrow = lane & 7;

    // prologue: stage 0
    gemm_load_stage(sbase, srcA_h, srcA_l, srcB_h, srcB_l, 0, tid);
    CP_COMMIT();

    for (int kt = 0; kt < 16; kt++) {
        const uint32_t scur = sbase + (uint32_t)(kt & 1) * GEMM_STAGE;
        if (kt < 15) {
            gemm_load_stage(sbase + (uint32_t)((kt + 1) & 1) * GEMM_STAGE,
                            srcA_h, srcA_l, srcB_h, srcB_l,
                            (size_t)(kt + 1) * 128, tid);
            CP_COMMIT();
            CP_WAIT1();
        } else {
            CP_WAIT0();
        }
        __syncthreads();

        const uint32_t sAh = scur;
        const uint32_t sAl = scur + 16384;
        const uint32_t sBh = scur + 32768;
        const uint32_t sBl = scur + 49152;

#pragma unroll
        for (int kc = 0; kc < 4; kc++) {
            const int kb0 = kc * 32;
            uint32_t ah[2][4], al[2][4];
#pragma unroll
            for (int i = 0; i < 2; i++) {
                int arow = wm + i * 16 + (mat & 1) * 8 + mrow;
                int akb = kb0 + (mat >> 1) * 16;
                uint32_t off = SWZ((uint32_t)(arow * 128 + akb));
                ldsm_x4(sAh + off, ah[i][0], ah[i][1], ah[i][2], ah[i][3]);
                ldsm_x4(sAl + off, al[i][0], al[i][1], al[i][2], al[i][3]);
            }
#pragma unroll
            for (int p = 0; p < 4; p++) {
                int brow = wn + p * 16 + (mat >> 1) * 8 + mrow;
                int bkb = kb0 + (mat & 1) * 16;
                uint32_t off = SWZ((uint32_t)(brow * 128 + bkb));
                uint32_t bh[4], bl[4];
                ldsm_x4(sBh + off, bh[0], bh[1], bh[2], bh[3]);
                ldsm_x4(sBl + off, bl[0], bl[1], bl[2], bl[3]);
#pragma unroll
                for (int i = 0; i < 2; i++) {
                    mma_bf16(acc[i][2 * p],     ah[i], &bh[0]);
                    mma_bf16(acc[i][2 * p],     al[i], &bh[0]);
                    mma_bf16(acc[i][2 * p],     ah[i], &bl[0]);
                    mma_bf16(acc[i][2 * p + 1], ah[i], &bh[2]);
                    mma_bf16(acc[i][2 * p + 1], al[i], &bh[2]);
                    mma_bf16(acc[i][2 * p + 1], ah[i], &bl[2]);
                }
            }
        }
        __syncthreads();
    }

    const int crow = lane >> 2;
    const int ccol = (lane & 3) * 2;
    if (mode == 1) {
#pragma unroll
        for (int i = 0; i < 2; i++) {
            int m = m0 + wm + i * 16 + crow;
#pragma unroll
            for (int j = 0; j < 8; j++) {
                int n = n0 + wn + j * 8 + ccol;
                *(float2*)(Cout + (size_t)m * 1024 + n) = make_float2(acc[i][j][0], acc[i][j][1]);
                *(float2*)(Cout + (size_t)(m + 8) * 1024 + n) = make_float2(acc[i][j][2], acc[i][j][3]);
            }
        }
        return;
    }
    int buf = n0 >> 10;
    int ncol0 = n0 & 1023;
    if (buf == 2) {
        // v -> chunk-transposed bf16 hi/lo: VT[cid][dv][t]
#pragma unroll
        for (int i = 0; i < 2; i++) {
            int m = m0 + wm + i * 16 + crow;
            int bb = m >> 13, nn = (m >> 6) & 127, cc = m & 63;
#pragma unroll
            for (int j = 0; j < 8; j++) {
                int ng = ncol0 + wn + j * 8 + ccol;
                int h = ng >> 7, dv = ng & 127;
                size_t base = (((size_t)(bb * 8 + h) * 128 + nn) << 13) + (size_t)dv * 64 + cc;
                uint32_t hi, lo;
                split2(acc[i][j][0], acc[i][j][1], hi, lo);
                __nv_bfloat162 hp = *(__nv_bfloat162*)&hi;
                __nv_bfloat162 lp = *(__nv_bfloat162*)&lo;
                VTh[base] = hp.x; VTh[base + 64] = hp.y;
                VTl[base] = lp.x; VTl[base + 64] = lp.y;
                split2(acc[i][j][2], acc[i][j][3], hi, lo);
                hp = *(__nv_bfloat162*)&hi;
                lp = *(__nv_bfloat162*)&lo;
                VTh[base + 8] = hp.x; VTh[base + 72] = hp.y;
                VTl[base + 8] = lp.x; VTl[base + 72] = lp.y;
            }
        }
    } else {
        __nv_bfloat16* H = buf ? Khi : Qhi;
        __nv_bfloat16* L = buf ? Klo : Qlo;
#pragma unroll
        for (int i = 0; i < 2; i++) {
            int m = m0 + wm + i * 16 + crow;
#pragma unroll
            for (int j = 0; j < 8; j++) {
                int n = ncol0 + wn + j * 8 + ccol;
                uint32_t hi, lo;
                split2(acc[i][j][0], acc[i][j][1], hi, lo);
                *(uint32_t*)(H + (size_t)m * 1024 + n) = hi;
                *(uint32_t*)(L + (size_t)m * 1024 + n) = lo;
                split2(acc[i][j][2], acc[i][j][3], hi, lo);
                *(uint32_t*)(H + (size_t)(m + 8) * 1024 + n) = hi;
                *(uint32_t*)(L + (size_t)(m + 8) * 1024 + n) = lo;
            }
        }
    }
}

// ---------------------------------------------------------------------------
// Feature map via HMMA. Outputs chunk-tiled bf16 hi/lo:
//   natural: ON[cid][z][c][64]  (z = dk half)
//   if isK:  also OT[cid][dk][t]
// ---------------------------------------------------------------------------
#define FM_SMEM (131072 + 1024)

__global__ __launch_bounds__(256) void featmap_mma(
    const __nv_bfloat16* __restrict__ Xhi, const __nv_bfloat16* __restrict__ Xlo,
    const __nv_bfloat16* __restrict__ W1hi, const __nv_bfloat16* __restrict__ W1lo,
    const __nv_bfloat16* __restrict__ W2hi, const __nv_bfloat16* __restrict__ W2lo,
    const float* __restrict__ B1, const float* __restrict__ B2,
    __nv_bfloat16* __restrict__ ONh, __nv_bfloat16* __restrict__ ONl,
    __nv_bfloat16* __restrict__ OTh, __nv_bfloat16* __restrict__ OTl,
    float scale, int isK) {
    extern __shared__ char dynraw[];
    char* smem = (char*)(((uintptr_t)dynraw + 1023) & ~(uintptr_t)1023);
    const uint32_t sbase = smem_u32(smem);

    const int tid = threadIdx.x;
    const int wid = tid >> 5;
    const int lane = tid & 31;
    const int t0 = blockIdx.x * 128;
    const int h = blockIdx.y;
    const int z = blockIdx.z;
    const int wm = (wid & 3) * 32;
    const int wn = (wid >> 2) * 32;

    const __nv_bfloat16* wsel[4] = {W1hi, W1lo, W2hi, W2lo};

#pragma unroll
    for (int t = 0; t < 4; t++) {
        int half = t >> 1, hl = t & 1;
        const char* sp = (const char*)((hl ? Xlo : Xhi) +
                          (size_t)t0 * 1024 + h * 128 + half * 64);
#pragma unroll
        for (int l = 0; l < 4; l++) {
            int s = tid + 256 * l;
            int row = s >> 3, cb = (s & 7) * 16;
            cp_async16(sbase + t * 16384 + SWZ((uint32_t)(row * 128 + cb)),
                       sp + (size_t)row * 2048 + cb);
        }
    }
#pragma unroll
    for (int t = 0; t < 8; t++) {
        int half = t >> 2, wsub = (t >> 1) & 1, hl = t & 1;
        const char* sp = (const char*)wsel[wsub * 2 + hl] +
                         ((size_t)(z * 64) * 128 + half * 64) * 2;
#pragma unroll
        for (int l = 0; l < 2; l++) {
            int s = tid + 256 * l;
            int row = s >> 3, cb = (s & 7) * 16;
            cp_async16(sbase + 65536 + t * 8192 + SWZ((uint32_t)(row * 128 + cb)),
                       sp + (size_t)row * 256 + cb);
        }
    }
    CP_COMMIT();
    CP_WAIT0();
    __syncthreads();

    float acc1[2][4][4], acc2[2][4][4];
#pragma unroll
    for (int i = 0; i < 2; i++)
#pragma unroll
        for (int j = 0; j < 4; j++)
#pragma unroll
            for (int r = 0; r < 4; r++) { acc1[i][j][r] = 0.f; acc2[i][j][r] = 0.f; }

    const int mat = lane >> 3;
    const int mrow = lane & 7;

#pragma unroll
    for (int half = 0; half < 2; half++) {
        const uint32_t sXh = sbase + (half * 2 + 0) * 16384;
        const uint32_t sXl = sbase + (half * 2 + 1) * 16384;
        const uint32_t sW1h = sbase + 65536 + (half * 4 + 0) * 8192;
        const uint32_t sW1l = sbase + 65536 + (half * 4 + 1) * 8192;
        const uint32_t sW2h = sbase + 65536 + (half * 4 + 2) * 8192;
        const uint32_t sW2l = sbase + 65536 + (half * 4 + 3) * 8192;
#pragma unroll
        for (int kc = 0; kc < 4; kc++) {
            const int kb0 = kc * 32;
            uint32_t ah[2][4], al[2][4];
#pragma unroll
            for (int i = 0; i < 2; i++) {
                int arow = wm + i * 16 + (mat & 1) * 8 + mrow;
                int akb = kb0 + (mat >> 1) * 16;
                uint32_t off = SWZ((uint32_t)(arow * 128 + akb));
                ldsm_x4(sXh + off, ah[i][0], ah[i][1], ah[i][2], ah[i][3]);
                ldsm_x4(sXl + off, al[i][0], al[i][1], al[i][2], al[i][3]);
            }
#pragma unroll
            for (int p = 0; p < 2; p++) {
                int brow = wn + p * 16 + (mat >> 1) * 8 + mrow;
                int bkb = kb0 + (mat & 1) * 16;
                uint32_t off = SWZ((uint32_t)(brow * 128 + bkb));
                uint32_t b1h[4], b1l[4], b2h[4], b2l[4];
                ldsm_x4(sW1h + off, b1h[0], b1h[1], b1h[2], b1h[3]);
                ldsm_x4(sW1l + off, b1l[0], b1l[1], b1l[2], b1l[3]);
                ldsm_x4(sW2h + off, b2h[0], b2h[1], b2h[2], b2h[3]);
                ldsm_x4(sW2l + off, b2l[0], b2l[1], b2l[2], b2l[3]);
#pragma unroll
                for (int i = 0; i < 2; i++) {
                    mma_bf16(acc1[i][2 * p],     ah[i], &b1h[0]);
                    mma_bf16(acc1[i][2 * p],     al[i], &b1h[0]);
                    mma_bf16(acc1[i][2 * p],     ah[i], &b1l[0]);
                    mma_bf16(acc1[i][2 * p + 1], ah[i], &b1h[2]);
                    mma_bf16(acc1[i][2 * p + 1], al[i], &b1h[2]);
                    mma_bf16(acc1[i][2 * p + 1], ah[i], &b1l[2]);
                    mma_bf16(acc2[i][2 * p],     ah[i], &b2h[0]);
                    mma_bf16(acc2[i][2 * p],     al[i], &b2h[0]);
                    mma_bf16(acc2[i][2 * p],     ah[i], &b2l[0]);
                    mma_bf16(acc2[i][2 * p + 1], ah[i], &b2h[2]);
                    mma_bf16(acc2[i][2 * p + 1], al[i], &b2h[2]);
                    mma_bf16(acc2[i][2 * p + 1], ah[i], &b2l[2]);
                }
            }
        }
    }

    const int crow = lane >> 2;
    const int ccol = (lane & 3) * 2;
#pragma unroll
    for (int j = 0; j < 4; j++) {
        int d64 = wn + j * 8 + ccol;            // 0..63
        int nl = z * 64 + d64;
        float b1a = B1[nl], b1b = B1[nl + 1];
        float b2a = B2[nl], b2b = B2[nl + 1];
#pragma unroll
        for (int i = 0; i < 2; i++) {
#pragma unroll
            for (int rv = 0; rv < 2; rv++) {
                int m = t0 + wm + i * 16 + crow + rv * 8;
                float p0 = (acc1[i][j][rv * 2 + 0] + b1a) * (acc2[i][j][rv * 2 + 0] + b2a) * scale;
                float p1 = (acc1[i][j][rv * 2 + 1] + b1b) * (acc2[i][j][rv * 2 + 1] + b2b) * scale;
                uint32_t hi, lo;
                split2(p0, p1, hi, lo);
                int bb = m >> 13, nn = (m >> 6) & 127, cc = m & 63;
                size_t cidx = (size_t)(bb * 8 + h) * 128 + nn;
                size_t addrN = ((cidx * 2 + z) << 12) + cc * 64 + d64;
                *(uint32_t*)(ONh + addrN) = hi;
                *(uint32_t*)(ONl + addrN) = lo;
                if (isK) {
                    size_t addrT = (cidx << 13) + (size_t)nl * 64 + cc;
                    __nv_bfloat162 hp = *(__nv_bfloat162*)&hi;
                    __nv_bfloat162 lp = *(__nv_bfloat162*)&lo;
                    OTh[addrT] = hp.x; OTh[addrT + 64] = hp.y;
                    OTl[addrT] = lp.x; OTl[addrT + 64] = lp.y;
                }
            }
        }
    }
}

// ---------------------------------------------------------------------------
// chunk_kv via HMMA: KV^T[dv][dk] = sum_t V[t][dv] * K[t][dk]
// ---------------------------------------------------------------------------
#define CKV_SMEM (65536 + 1024)

__global__ __launch_bounds__(256) void chunk_kv_mma(
    const __nv_bfloat16* __restrict__ VTh, const __nv_bfloat16* __restrict__ VTl,
    const __nv_bfloat16* __restrict__ KTh, const __nv_bfloat16* __restrict__ KTl,
    float* __restrict__ KV) {
    extern __shared__ char dynraw[];
    char* smem = (char*)(((uintptr_t)dynraw + 1023) & ~(uintptr_t)1023);
    const uint32_t sbase = smem_u32(smem);
    const int tid = threadIdx.x;
    const int wid = tid >> 5;
    const int lane = tid & 31;
    const size_t cid = blockIdx.x;
    const int wm = (wid & 3) * 32;       // dv
    const int wn = (wid >> 2) * 64;      // dk

    load_tile_async(sbase + 0,     VTh + (cid << 13), 1024, tid);
    load_tile_async(sbase + 16384, VTl + (cid << 13), 1024, tid);
    load_tile_async(sbase + 32768, KTh + (cid << 13), 1024, tid);
    load_tile_async(sbase + 49152, KTl + (cid << 13), 1024, tid);
    CP_COMMIT();
    CP_WAIT0();
    __syncthreads();

    float acc[2][8][4];
#pragma unroll
    for (int i = 0; i < 2; i++)
#pragma unroll
        for (int j = 0; j < 8; j++)
#pragma unroll
            for (int r = 0; r < 4; r++) acc[i][j][r] = 0.f;

    const int mat = lane >> 3;
    const int mrow = lane & 7;

#pragma unroll
    for (int kc = 0; kc < 4; kc++) {
        const int kb0 = kc * 32;
        uint32_t ah[2][4], al[2][4];
#pragma unroll
        for (int i = 0; i < 2; i++) {
            int arow = wm + i * 16 + (mat & 1) * 8 + mrow;
            int akb = kb0 + (mat >> 1) * 16;
            uint32_t off = SWZ((uint32_t)(arow * 128 + akb));
            ldsm_x4(sbase + off,         ah[i][0], ah[i][1], ah[i][2], ah[i][3]);
            ldsm_x4(sbase + 16384 + off, al[i][0], al[i][1], al[i][2], al[i][3]);
        }
#pragma unroll
        for (int p = 0; p < 4; p++) {
            int brow = wn + p * 16 + (mat >> 1) * 8 + mrow;
            int bkb = kb0 + (mat & 1) * 16;
            uint32_t off = SWZ((uint32_t)(brow * 128 + bkb));
            uint32_t bh[4], bl[4];
            ldsm_x4(sbase + 32768 + off, bh[0], bh[1], bh[2], bh[3]);
            ldsm_x4(sbase + 49152 + off, bl[0], bl[1], bl[2], bl[3]);
#pragma unroll
            for (int i = 0; i < 2; i++) {
                mma_bf16(acc[i][2 * p],     ah[i], &bh[0]);
                mma_bf16(acc[i][2 * p],     al[i], &bh[0]);
                mma_bf16(acc[i][2 * p],     ah[i], &bl[0]);
                mma_bf16(acc[i][2 * p + 1], ah[i], &bh[2]);
                mma_bf16(acc[i][2 * p + 1], al[i], &bh[2]);
                mma_bf16(acc[i][2 * p + 1], ah[i], &bl[2]);
            }
        }
    }

    const int crow = lane >> 2;
    const int ccol = (lane & 3) * 2;
    const int hk = wn >> 6;
#pragma unroll
    for (int i = 0; i < 2; i++) {
#pragma unroll
        for (int rv = 0; rv < 2; rv++) {
            int dv = wm + i * 16 + crow + rv * 8;
#pragma unroll
            for (int j = 0; j < 8; j++) {
                int dk64 = (wn & 63) + j * 8 + ccol;
                size_t addr = (cid << 14) + hk * 8192 + (size_t)dv * 64 + dk64;
                *(float2*)(KV + addr) = make_float2(acc[i][j][rv * 2], acc[i][j][rv * 2 + 1]);
            }
        }
    }
}

// ---------------------------------------------------------------------------
__global__ void cumsum_split(const float* __restrict__ KV,
                             __nv_bfloat16* __restrict__ Sh,
                             __nv_bfloat16* __restrict__ Sl) {
    int bh = blockIdx.x;
    size_t i = blockIdx.y * 256 + threadIdx.x;
    float acc = 0.f;
    for (int n = 0; n < NCHUNK; n++) {
        size_t idx = (((size_t)bh * 128 + n) << 14) + i;
        float v = KV[idx];
        __nv_bfloat16 h = __float2bfloat16(acc);
        Sh[idx] = h;
        Sl[idx] = __float2bfloat16(acc - __bfloat162float(h));
        acc += v;
    }
}

// ---------------------------------------------------------------------------
// chunk attention via HMMA: A = Q K^T (masked), O = A V + Q S_excl.
// ---------------------------------------------------------------------------
#define CA_SMEM (180224 + 1024)

__global__ __launch_bounds__(256) void chunk_attn_mma(
    const __nv_bfloat16* __restrict__ QNh, const __nv_bfloat16* __restrict__ QNl,
    const __nv_bfloat16* __restrict__ KNh, const __nv_bfloat16* __restrict__ KNl,
    const __nv_bfloat16* __restrict__ VTh, const __nv_bfloat16* __restrict__ VTl,
    const __nv_bfloat16* __restrict__ Sh,  const __nv_bfloat16* __restrict__ Sl,
    float* __restrict__ O) {
    extern __shared__ char dynraw[];
    char* smem = (char*)(((uintptr_t)dynraw + 1023) & ~(uintptr_t)1023);
    const uint32_t sQh = smem_u32(smem);
    const uint32_t sQl = sQh + 16384;
    const uint32_t sKh = sQh + 32768;
    const uint32_t sKl = sQh + 49152;
    const uint32_t sVh = sQh + 65536;
    const uint32_t sVl = sQh + 81920;
    const uint32_t sSh = sQh + 98304;
    const uint32_t sSl = sQh + 131072;
    const uint32_t sAh = sQh + 163840;
    const uint32_t sAl = sQh + 172032;

    const int tid = threadIdx.x;
    const int wid = tid >> 5;
    const int lane = tid & 31;
    const size_t cid = blockIdx.x;
    const int n = cid & 127;
    const int h = (cid >> 7) & 7;
    const int b = (int)(cid >> 10);

    // group 1: Q, K
    load_tile_async(sQh, QNh + (cid << 13), 1024, tid);
    load_tile_async(sQl, QNl + (cid << 13), 1024, tid);
    load_tile_async(sKh, KNh + (cid << 13), 1024, tid);
    load_tile_async(sKl, KNl + (cid << 13), 1024, tid);
    CP_COMMIT();
    // group 2: VT, ST
    load_tile_async(sVh, VTh + (cid << 13), 1024, tid);
    load_tile_async(sVl, VTl + (cid << 13), 1024, tid);
    load_tile_async(sSh, Sh + (cid << 14), 2048, tid);
    load_tile_async(sSl, Sl + (cid << 14), 2048, tid);
    CP_COMMIT();
    CP_WAIT1();
    __syncthreads();

    const int mat = lane >> 3;
    const int mrow = lane & 7;
    const int crow = lane >> 2;
    const int ccol = (lane & 3) * 2;

    // ---- Step 1: A = Q K^T, warp tile 32x16
    {
        const int wm1 = (wid & 1) * 32;
        const int wn1 = (wid >> 1) * 16;
        float acc[2][2][4];
#pragma unroll
        for (int i = 0; i < 2; i++)
#pragma unroll
            for (int j = 0; j < 2; j++)
#pragma unroll
                for (int r = 0; r < 4; r++) acc[i][j][r] = 0.f;

#pragma unroll
        for (int kc = 0; kc < 8; kc++) {
            int rbase = (kc >> 2) * 64;
            int kb0 = (kc & 3) * 32;
            uint32_t ah[2][4], al[2][4];
#pragma unroll
            for (int i = 0; i < 2; i++) {
                int arow = rbase + wm1 + i * 16 + (mat & 1) * 8 + mrow;
                int akb = kb0 + (mat >> 1) * 16;
                uint32_t off = SWZ((uint32_t)(arow * 128 + akb));
                ldsm_x4(sQh + off, ah[i][0], ah[i][1], ah[i][2], ah[i][3]);
                ldsm_x4(sQl + off, al[i][0], al[i][1], al[i][2], al[i][3]);
            }
            int brow = rbase + wn1 + (mat >> 1) * 8 + mrow;
            int bkb = kb0 + (mat & 1) * 16;
            uint32_t off = SWZ((uint32_t)(brow * 128 + bkb));
            uint32_t bh[4], bl[4];
            ldsm_x4(sKh + off, bh[0], bh[1], bh[2], bh[3]);
            ldsm_x4(sKl + off, bl[0], bl[1], bl[2], bl[3]);
#pragma unroll
            for (int i = 0; i < 2; i++) {
                mma_bf16(acc[i][0], ah[i], &bh[0]);
                mma_bf16(acc[i][0], al[i], &bh[0]);
                mma_bf16(acc[i][0], ah[i], &bl[0]);
                mma_bf16(acc[i][1], ah[i], &bh[2]);
                mma_bf16(acc[i][1], al[i], &bh[2]);
                mma_bf16(acc[i][1], ah[i], &bl[2]);
            }
        }
        // mask + split + store A
#pragma unroll
        for (int i = 0; i < 2; i++) {
#pragma unroll
            for (int rv = 0; rv < 2; rv++) {
                int c = wm1 + i * 16 + crow + rv * 8;
#pragma unroll
                for (int j = 0; j < 2; j++) {
                    int s = wn1 + j * 8 + ccol;
                    float v0 = (s <= c)     ? acc[i][j][rv * 2 + 0] : 0.f;
                    float v1 = (s + 1 <= c) ? acc[i][j][rv * 2 + 1] : 0.f;
                    uint32_t hi, lo;
                    split2(v0, v1, hi, lo);
                    uint32_t off = SWZ((uint32_t)(c * 128 + s * 2));
                    asm volatile("st.shared.b32 [%0], %1;" :: "r"(sAh + off), "r"(hi));
                    asm volatile("st.shared.b32 [%0], %1;" :: "r"(sAl + off), "r"(lo));
                }
            }
        }
    }
    CP_WAIT0();
    __syncthreads();

    // ---- Step 2: O = A V + Q S, warp tile 32x32
    const int wm2 = (wid & 1) * 32;
    const int wn2 = (wid >> 1) * 32;
    float acc[2][4][4];
#pragma unroll
    for (int i = 0; i < 2; i++)
#pragma unroll
        for (int j = 0; j < 4; j++)
#pragma unroll
            for (int r = 0; r < 4; r++) acc[i][j][r] = 0.f;

    // 2a: A @ V  (K = 64 over s)
#pragma unroll
    for (int kc = 0; kc < 4; kc++) {
        int kb0 = kc * 32;
        uint32_t ah[2][4], al[2][4];
#pragma unroll
        for (int i = 0; i < 2; i++) {
            int arow = wm2 + i * 16 + (mat & 1) * 8 + mrow;
            int akb = kb0 + (mat >> 1) * 16;
            uint32_t off = SWZ((uint32_t)(arow * 128 + akb));
            ldsm_x4(sAh + off, ah[i][0], ah[i][1], ah[i][2], ah[i][3]);
            ldsm_x4(sAl + off, al[i][0], al[i][1], al[i][2], al[i][3]);
        }
#pragma unroll
        for (int p = 0; p < 2; p++) {
            int brow = wn2 + p * 16 + (mat >> 1) * 8 + mrow;
            int bkb = kb0 + (mat & 1) * 16;
            uint32_t off = SWZ((uint32_t)(brow * 128 + bkb));
            uint32_t bh[4], bl[4];
            ldsm_x4(sVh + off, bh[0], bh[1], bh[2], bh[3]);
            ldsm_x4(sVl + off, bl[0], bl[1], bl[2], bl[3]);
#pragma unroll
            for (int i = 0; i < 2; i++) {
                mma_bf16(acc[i][2 * p],     ah[i], &bh[0]);
                mma_bf16(acc[i][2 * p],     al[i], &bh[0]);
                mma_bf16(acc[i][2 * p],     ah[i], &bl[0]);
                mma_bf16(acc[i][2 * p + 1], ah[i], &bh[2]);
                mma_bf16(acc[i][2 * p + 1], al[i], &bh[2]);
                mma_bf16(acc[i][2 * p + 1], ah[i], &bl[2]);
            }
        }
    }
    // 2b: Q @ S  (K = 128 over dk)
#pragma unroll
    for (int kc = 0; kc < 8; kc++) {
        int qrbase = (kc >> 2) * 64;
        int srbase = (kc >> 2) * 128;
        int kb0 = (kc & 3) * 32;
        uint32_t ah[2][4], al[2][4];
#pragma unroll
        for (int i = 0; i < 2; i++) {
            int arow = qrbase + wm2 + i * 16 + (mat & 1) * 8 + mrow;
            int akb = kb0 + (mat >> 1) * 16;
            uint32_t off = SWZ((uint32_t)(arow * 128 + akb));
            ldsm_x4(sQh + off, ah[i][0], ah[i][1], ah[i][2], ah[i][3]);
            ldsm_x4(sQl + off, al[i][0], al[i][1], al[i][2], al[i][3]);
        }
#pragma unroll
        for (int p = 0; p < 2; p++) {
            int brow = srbase + wn2 + p * 16 + (mat >> 1) * 8 + mrow;
            int bkb = kb0 + (mat & 1) * 16;
            uint32_t off = SWZ((uint32_t)(brow * 128 + bkb));
            uint32_t bh[4], bl[4];
            ldsm_x4(sSh + off, bh[0], bh[1], bh[2], bh[3]);
            ldsm_x4(sSl + off, bl[0], bl[1], bl[2], bl[3]);
#pragma unroll
            for (int i = 0; i < 2; i++) {
                mma_bf16(acc[i][2 * p],     ah[i], &bh[0]);
                mma_bf16(acc[i][2 * p],     al[i], &bh[0]);
                mma_bf16(acc[i][2 * p],     ah[i], &bl[0]);
                mma_bf16(acc[i][2 * p + 1], ah[i], &bh[2]);
                mma_bf16(acc[i][2 * p + 1], al[i], &bh[2]);
                mma_bf16(acc[i][2 * p + 1], ah[i], &bl[2]);
            }
        }
    }

    // write O (f32, [t][1024])
    const size_t tbase = (size_t)b * 8192 + (size_t)n * 64;
#pragma unroll
    for (int i = 0; i < 2; i++) {
#pragma unroll
        for (int rv = 0; rv < 2; rv++) {
            size_t t = tbase + wm2 + i * 16 + crow + rv * 8;
#pragma unroll
            for (int j = 0; j < 4; j++) {
                int dv = wn2 + j * 8 + ccol;
                *(float2*)(O + t * 1024 + h * 128 + dv) =
                    make_float2(acc[i][j][rv * 2], acc[i][j][rv * 2 + 1]);
            }
        }
    }
}

// ---------------------------------------------------------------------------
__global__ void rmsnorm_split(const float* __restrict__ O, const float* __restrict__ W,
                              __nv_bfloat16* __restrict__ hi, __nv_bfloat16* __restrict__ lo) {
    int row = blockIdx.x * 8 + threadIdx.y;
    int t = row / NH, h = row % NH;
    int lane = threadIdx.x;
    size_t base = (size_t)t * DMODEL + h * DHD + lane * 4;
    float4 x = *(const float4*)(O + base);
    float ss = x.x * x.x + x.y * x.y + x.z * x.z + x.w * x.w;
#pragma unroll
    for (int off = 16; off > 0; off >>= 1)
        ss += __shfl_xor_sync(0xffffffffu, ss, off);
    float r = rsqrtf(ss * (1.0f / 128.0f) + RMSEPS);
    float4 w = *(const float4*)(W + lane * 4);
    x.x *= r * w.x; x.y *= r * w.y; x.z *= r * w.z; x.w *= r * w.w;
    uint32_t h0, l0, h1, l1;
    split2(x.x, x.y, h0, l0);
    split2(x.z, x.w, h1, l1);
    *(uint2*)(hi + base) = make_uint2(h0, h1);
    *(uint2*)(lo + base) = make_uint2(l0, l1);
}

// ---------------------------------------------------------------------------
extern "C" void kernel_launch(void* const* d_in, const int* in_sizes, int n_in,
                              void* d_out, int out_size) {
    const float* hidden = (const float*)d_in[0];
    const float* q_w    = (const float*)d_in[2];
    const float* k_w    = (const float*)d_in[3];
    const float* v_w    = (const float*)d_in[4];
    const float* o_w    = (const float*)d_in[5];
    const float* fmq_w1 = (const float*)d_in[6];
    const float* fmq_b1 = (const float*)d_in[7];
    const float* fmq_w2 = (const float*)d_in[8];
    const float* fmq_b2 = (const float*)d_in[9];
    const float* fmk_w1 = (const float*)d_in[10];
    const float* fmk_b1 = (const float*)d_in[11];
    const float* fmk_w2 = (const float*)d_in[12];
    const float* fmk_b2 = (const float*)d_in[13];
    const float* rms_w  = (const float*)d_in[14];
    float* out = (float*)d_out;

    float *o, *kv;
    __nv_bfloat16 *ahi, *alo, *whi, *wlo, *qhi, *qlo, *khi, *klo, *fwhi, *fwlo;
    __nv_bfloat16 *qnh, *qnl, *knh, *knl, *kth, *ktl, *vth, *vtl, *sh, *sl;
    cudaGetSymbolAddress((void**)&o,    g_o);
    cudaGetSymbolAddress((void**)&kv,   g_kv);
    cudaGetSymbolAddress((void**)&ahi,  g_ahi);
    cudaGetSymbolAddress((void**)&alo,  g_alo);
    cudaGetSymbolAddress((void**)&whi,  g_whi);
    cudaGetSymbolAddress((void**)&wlo,  g_wlo);
    cudaGetSymbolAddress((void**)&qhi,  g_qhi);
    cudaGetSymbolAddress((void**)&qlo,  g_qlo);
    cudaGetSymbolAddress((void**)&khi,  g_khi);
    cudaGetSymbolAddress((void**)&klo,  g_klo);
    cudaGetSymbolAddress((void**)&fwhi, g_fwhi);
    cudaGetSymbolAddress((void**)&fwlo, g_fwlo);
    cudaGetSymbolAddress((void**)&qnh,  g_qnh);
    cudaGetSymbolAddress((void**)&qnl,  g_qnl);
    cudaGetSymbolAddress((void**)&knh,  g_knh);
    cudaGetSymbolAddress((void**)&knl,  g_knl);
    cudaGetSymbolAddress((void**)&kth,  g_kth);
    cudaGetSymbolAddress((void**)&ktl,  g_ktl);
    cudaGetSymbolAddress((void**)&vth,  g_vth);
    cudaGetSymbolAddress((void**)&vtl,  g_vtl);
    cudaGetSymbolAddress((void**)&sh,   g_sh);
    cudaGetSymbolAddress((void**)&sl,   g_sl);

    cudaFuncSetAttribute(gemm_mma2, cudaFuncAttributeMaxDynamicSharedMemorySize, GEMM_SMEM_BYTES);
    cudaFuncSetAttribute(featmap_mma, cudaFuncAttributeMaxDynamicSharedMemorySize, FM_SMEM);
    cudaFuncSetAttribute(chunk_kv_mma, cudaFuncAttributeMaxDynamicSharedMemorySize, CKV_SMEM);
    cudaFuncSetAttribute(chunk_attn_mma, cudaFuncAttributeMaxDynamicSharedMemorySize, CA_SMEM);

    const int nA = BT * DMODEL;
    const int nW = DMODEL * DMODEL;
    const int nF = DHD * DHD;

    // Splits
    split_f32<<<nA / 1024, 256>>>(hidden, ahi, alo, nA);
    split_f32<<<nW / 1024, 256>>>(q_w, whi,          wlo,          nW);
    split_f32<<<nW / 1024, 256>>>(k_w, whi + nW,     wlo + nW,     nW);
    split_f32<<<nW / 1024, 256>>>(v_w, whi + 2 * nW, wlo + 2 * nW, nW);
    split_f32<<<nF / 1024, 256>>>(fmq_w1, fwhi,          fwlo,          nF);
    split_f32<<<nF / 1024, 256>>>(fmq_w2, fwhi + nF,     fwlo + nF,     nF);
    split_f32<<<nF / 1024, 256>>>(fmk_w1, fwhi + 2 * nF, fwlo + 2 * nF, nF);
    split_f32<<<nF / 1024, 256>>>(fmk_w2, fwhi + 3 * nF, fwlo + 3 * nF, nF);

    // QKV projection: q/k natural bf16 splits, v -> chunk-transposed VT
    gemm_mma2<<<dim3(24, 128), 256, GEMM_SMEM_BYTES>>>(
        ahi, alo, whi, wlo, qhi, qlo, khi, klo, vth, vtl, nullptr, 0);

    // Feature maps -> chunk-tiled layouts
    dim3 fm_grid(BT / 128, NH, 2);
    featmap_mma<<<fm_grid, 256, FM_SMEM>>>(qhi, qlo, fwhi, fwlo, fwhi + nF, fwlo + nF,
                                           fmq_b1, fmq_b2, qnh, qnl, nullptr, nullptr,
                                           QSCALE, 0);
    featmap_mma<<<fm_grid, 256, FM_SMEM>>>(khi, klo, fwhi + 2 * nF, fwlo + 2 * nF,
                                           fwhi + 3 * nF, fwlo + 3 * nF,
                                           fmk_b1, fmk_b2, knh, knl, kth, ktl,
                                           1.0f, 1);

    // Chunked linear attention (all HMMA)
    chunk_kv_mma<<<NCHTOT, 256, CKV_SMEM>>>(vth, vtl, kth, ktl, kv);
    cumsum_split<<<dim3(NBATCH * NH, 64), 256>>>(kv, sh, sl);
    chunk_attn_mma<<<NCHTOT, 256, CA_SMEM>>>(qnh, qnl, knh, knl, vth, vtl, sh, sl, o);

    // RMSNorm + split, then output projection
    rmsnorm_split<<<(BT * NH) / 8, dim3(32, 8)>>>(o, rms_w, ahi, alo);
    split_f32<<<nW / 1024, 256>>>(o_w, whi, wlo, nW);
    gemm_mma2<<<dim3(8, 128), 256, GEMM_SMEM_BYTES>>>(
        ahi, alo, whi, wlo, nullptr, nullptr, nullptr, nullptr, nullptr, nullptr, out, 1);
}

// round 7
// speedup vs baseline: 2.9236x; 1.0499x over previous
#include <cuda_runtime.h>
#include <cuda_bf16.h>
#include <cstdint>
#include <cstddef>

// Problem constants
#define BT      16384
#define DMODEL  1024
#define NH      8
#define DHD     128
#define CHUNKL  64
#define NCHUNK  128
#define NBATCH  2
#define NCHTOT  2048          // NBATCH*NH*NCHUNK
#define QSCALE  0.08838834764831843f
#define RMSEPS  1e-5f

// Scratch buffers
__device__ float g_o[(size_t)BT * DMODEL];
__device__ float g_kv[(size_t)NCHTOT * 16384];
__device__ __nv_bfloat16 g_ahi[(size_t)BT * DMODEL];
__device__ __nv_bfloat16 g_alo[(size_t)BT * DMODEL];
__device__ __nv_bfloat16 g_whi[(size_t)3 * DMODEL * DMODEL];
__device__ __nv_bfloat16 g_wlo[(size_t)3 * DMODEL * DMODEL];
__device__ __nv_bfloat16 g_qhi[(size_t)BT * DMODEL];   // q projection (featmap input)
__device__ __nv_bfloat16 g_qlo[(size_t)BT * DMODEL];
__device__ __nv_bfloat16 g_khi[(size_t)BT * DMODEL];   // k projection
__device__ __nv_bfloat16 g_klo[(size_t)BT * DMODEL];
__device__ __nv_bfloat16 g_fwhi[4 * DHD * DHD];
__device__ __nv_bfloat16 g_fwlo[4 * DHD * DHD];
// chunk-tiled buffers: chunk id cid = (b*8+h)*128+n
__device__ __nv_bfloat16 g_qnh[(size_t)BT * DMODEL];   // phi_q natural [cid][hk][c][64]
__device__ __nv_bfloat16 g_qnl[(size_t)BT * DMODEL];
__device__ __nv_bfloat16 g_knh[(size_t)BT * DMODEL];   // phi_k natural
__device__ __nv_bfloat16 g_knl[(size_t)BT * DMODEL];
__device__ __nv_bfloat16 g_kth[(size_t)BT * DMODEL];   // phi_k transposed [cid][dk][t]
__device__ __nv_bfloat16 g_ktl[(size_t)BT * DMODEL];
__device__ __nv_bfloat16 g_vth[(size_t)BT * DMODEL];   // v transposed [cid][dv][t]
__device__ __nv_bfloat16 g_vtl[(size_t)BT * DMODEL];
__device__ __nv_bfloat16 g_sh[(size_t)NCHTOT * 16384]; // S_excl hi [cid][hk][dv][64]
__device__ __nv_bfloat16 g_sl[(size_t)NCHTOT * 16384];

#define SWZ(off) ((off) ^ (((off) >> 3) & 0x70))

__device__ __forceinline__ uint32_t smem_u32(const void* p) {
    uint32_t a;
    asm("{ .reg .u64 t; cvta.to.shared.u64 t, %1; cvt.u32.u64 %0, t; }" : "=r"(a) : "l"(p));
    return a;
}

__device__ __forceinline__ void ldsm_x4(uint32_t addr, uint32_t& r0, uint32_t& r1,
                                        uint32_t& r2, uint32_t& r3) {
    asm volatile("ldmatrix.sync.aligned.m8n8.x4.shared.b16 {%0,%1,%2,%3}, [%4];"
                 : "=r"(r0), "=r"(r1), "=r"(r2), "=r"(r3) : "r"(addr));
}

__device__ __forceinline__ void mma_bf16(float* d, const uint32_t* a, const uint32_t* b) {
    asm volatile(
        "mma.sync.aligned.m16n8k16.row.col.f32.bf16.bf16.f32 "
        "{%0,%1,%2,%3}, {%4,%5,%6,%7}, {%8,%9}, {%0,%1,%2,%3};"
        : "+f"(d[0]), "+f"(d[1]), "+f"(d[2]), "+f"(d[3])
        : "r"(a[0]), "r"(a[1]), "r"(a[2]), "r"(a[3]), "r"(b[0]), "r"(b[1]));
}

__device__ __forceinline__ void cp_async16(uint32_t saddr, const void* gaddr) {
    asm volatile("cp.async.cg.shared.global [%0], [%1], 16;" :: "r"(saddr), "l"(gaddr));
}
#define CP_COMMIT() asm volatile("cp.async.commit_group;" ::: "memory")
#define CP_WAIT0()  asm volatile("cp.async.wait_group 0;" ::: "memory")
#define CP_WAIT1()  asm volatile("cp.async.wait_group 1;" ::: "memory")

__device__ __forceinline__ void split2(float a, float b, uint32_t& hi, uint32_t& lo) {
    __nv_bfloat16 ha = __float2bfloat16(a), hb = __float2bfloat16(b);
    __nv_bfloat16 la = __float2bfloat16(a - __bfloat162float(ha));
    __nv_bfloat16 lb = __float2bfloat16(b - __bfloat162float(hb));
    __nv_bfloat162 hp = __halves2bfloat162(ha, hb);
    __nv_bfloat162 lp = __halves2bfloat162(la, lb);
    hi = *(uint32_t*)&hp; lo = *(uint32_t*)&lp;
}

// async tile copy: 128B rows, linear global source, SW128 smem dest
__device__ __forceinline__ void load_tile_async(uint32_t sdst, const void* gsrc,
                                                int slots, int tid) {
    for (int u = tid; u < slots; u += 256) {
        int row = u >> 3, cb = (u & 7) * 16;
        cp_async16(sdst + SWZ((uint32_t)(row * 128 + cb)),
                   (const char*)gsrc + (size_t)u * 16);
    }
}

// ---------------------------------------------------------------------------
// fp32 -> (hi, lo) bf16 split: 8 floats / thread, 2 independent load chains
// ---------------------------------------------------------------------------
__global__ void split_f32(const float* __restrict__ x, __nv_bfloat16* __restrict__ hi,
                          __nv_bfloat16* __restrict__ lo, int n) {
    int i = (blockIdx.x * blockDim.x + threadIdx.x) * 8;
    if (i >= n) return;
    float4 v0 = *(const float4*)(x + i);
    float4 v1 = *(const float4*)(x + i + 4);
    uint32_t h0, l0, h1, l1, h2, l2, h3, l3;
    split2(v0.x, v0.y, h0, l0);
    split2(v0.z, v0.w, h1, l1);
    split2(v1.x, v1.y, h2, l2);
    split2(v1.z, v1.w, h3, l3);
    *(uint4*)(hi + i) = make_uint4(h0, h1, h2, h3);
    *(uint4*)(lo + i) = make_uint4(l0, l1, l2, l3);
}

// ---------------------------------------------------------------------------
// HMMA GEMM, 3-stage cp.async pipeline, one sync per K-step.
// 128x128 CTA tile, BK=64, 8 warps.
// mode 0 (QKV): buf0 -> Qhi/Qlo, buf1 -> Khi/Klo, buf2 -> VT hi/lo (transposed)
// mode 1: f32 out to Cout.
// ---------------------------------------------------------------------------
#define GEMM_STAGE   65536
#define GEMM_NSTAGE  3
#define GEMM_SMEM_BYTES (GEMM_NSTAGE * GEMM_STAGE + 1024)

__device__ __forceinline__ void gemm_load_stage(uint32_t sdst,
                                                const char* Ah, const char* Al,
                                                const char* Bh, const char* Bl,
                                                size_t kbyte, int tid) {
#pragma unroll
    for (int l = 0; l < 4; l++) {
        int u = tid + 256 * l;
        int row = u >> 3;
        int cb = (u & 7) * 16;
        uint32_t dsw = SWZ((uint32_t)(row * 128 + cb));
        size_t off = (size_t)row * 2048 + kbyte + cb;
        cp_async16(sdst + dsw,         Ah + off);
        cp_async16(sdst + 16384 + dsw, Al + off);
        cp_async16(sdst + 32768 + dsw, Bh + off);
        cp_async16(sdst + 49152 + dsw, Bl + off);
    }
}

__global__ __launch_bounds__(256) void gemm_mma2(
    const __nv_bfloat16* __restrict__ Ahi, const __nv_bfloat16* __restrict__ Alo,
    const __nv_bfloat16* __restrict__ Whi, const __nv_bfloat16* __restrict__ Wlo,
    __nv_bfloat16* __restrict__ Qhi, __nv_bfloat16* __restrict__ Qlo,
    __nv_bfloat16* __restrict__ Khi, __nv_bfloat16* __restrict__ Klo,
    __nv_bfloat16* __restrict__ VTh, __nv_bfloat16* __restrict__ VTl,
    float* __restrict__ Cout, int mode) {
    extern __shared__ char dynraw[];
    char* smem = (char*)(((uintptr_t)dynraw + 1023) & ~(uintptr_t)1023);
    const uint32_t sbase = smem_u32(smem);

    const int tid = threadIdx.x;
    const int wid = tid >> 5;
    const int lane = tid & 31;
    const int n0 = blockIdx.x * 128;
    const int m0 = blockIdx.y * 128;
    const int wm = (wid & 3) * 32;
    const int wn = (wid >> 2) * 64;

    float acc[2][8][4];
#pragma unroll
    for (int i = 0; i < 2; i++)
#pragma unroll
        for (int j = 0; j < 8; j++)
#pragma unroll
            for (int r = 0; r < 4; r++) acc[i][j][r] = 0.f;

    const char* srcA_h = (const char*)(Ahi + (size_t)m0 * 1024);
    const char* srcA_l = (const char*)(Alo + (size_t)m0 * 1024);
    const char* srcB_h = (const char*)(Whi + (size_t)n0 * 1024);
    const char* srcB_l = (const char*)(Wlo + (size_t)n0 * 1024);

    const int mat = lane >> 3;
    const int mrow = lane & 7;

    // prologue: stages 0, 1
    gemm_load_stage(sbase, srcA_h, srcA_l, srcB_h, srcB_l, 0, tid);
    CP_COMMIT();
    gemm_load_stage(sbase + GEMM_STAGE, srcA_h, srcA_l, srcB_h, srcB_l, 128, tid);
    CP_COMMIT();

    int scur_idx = 0, snext_idx = 2;
    for (int kt = 0; kt < 16; kt++) {
        CP_WAIT1();                 // stage kt has arrived (kt+1 may be in flight)
        __syncthreads();            // everyone done computing kt-1 (buffer (kt+2)%3)

        if (kt + 2 < 16) {
            gemm_load_stage(sbase + (uint32_t)snext_idx * GEMM_STAGE,
                            srcA_h, srcA_l, srcB_h, srcB_l,
                            (size_t)(kt + 2) * 128, tid);
            CP_COMMIT();
        }
        const uint32_t scur = sbase + (uint32_t)scur_idx * GEMM_STAGE;
        scur_idx = (scur_idx + 1) % GEMM_NSTAGE;
        snext_idx = (snext_idx + 1) % GEMM_NSTAGE;

        const uint32_t sAh = scur;
        const uint32_t sAl = scur + 16384;
        const uint32_t sBh = scur + 32768;
        const uint32_t sBl = scur + 49152;

#pragma unroll
        for (int kc = 0; kc < 4; kc++) {
            const int kb0 = kc * 32;
            uint32_t ah[2][4], al[2][4];
#pragma unroll
            for (int i = 0; i < 2; i++) {
                int arow = wm + i * 16 + (mat & 1) * 8 + mrow;
                int akb = kb0 + (mat >> 1) * 16;
                uint32_t off = SWZ((uint32_t)(arow * 128 + akb));
                ldsm_x4(sAh + off, ah[i][0], ah[i][1], ah[i][2], ah[i][3]);
                ldsm_x4(sAl + off, al[i][0], al[i][1], al[i][2], al[i][3]);
            }
#pragma unroll
            for (int p = 0; p < 4; p++) {
                int brow = wn + p * 16 + (mat >> 1) * 8 + mrow;
                int bkb = kb0 + (mat & 1) * 16;
                uint32_t off = SWZ((uint32_t)(brow * 128 + bkb));
                uint32_t bh[4], bl[4];
                ldsm_x4(sBh + off, bh[0], bh[1], bh[2], bh[3]);
                ldsm_x4(sBl + off, bl[0], bl[1], bl[2], bl[3]);
#pragma unroll
                for (int i = 0; i < 2; i++) {
                    mma_bf16(acc[i][2 * p],     ah[i], &bh[0]);
                    mma_bf16(acc[i][2 * p],     al[i], &bh[0]);
                    mma_bf16(acc[i][2 * p],     ah[i], &bl[0]);
                    mma_bf16(acc[i][2 * p + 1], ah[i], &bh[2]);
                    mma_bf16(acc[i][2 * p + 1], al[i], &bh[2]);
                    mma_bf16(acc[i][2 * p + 1], ah[i], &bl[2]);
                }
            }
        }
    }

    const int crow = lane >> 2;
    const int ccol = (lane & 3) * 2;
    if (mode == 1) {
#pragma unroll
        for (int i = 0; i < 2; i++) {
            int m = m0 + wm + i * 16 + crow;
#pragma unroll
            for (int j = 0; j < 8; j++) {
                int n = n0 + wn + j * 8 + ccol;
                *(float2*)(Cout + (size_t)m * 1024 + n) = make_float2(acc[i][j][0], acc[i][j][1]);
                *(float2*)(Cout + (size_t)(m + 8) * 1024 + n) = make_float2(acc[i][j][2], acc[i][j][3]);
            }
        }
        return;
    }
    int buf = n0 >> 10;
    int ncol0 = n0 & 1023;
    if (buf == 2) {
        // v -> chunk-transposed bf16 hi/lo: VT[cid][dv][t]
#pragma unroll
        for (int i = 0; i < 2; i++) {
            int m = m0 + wm + i * 16 + crow;
            int bb = m >> 13, nn = (m >> 6) & 127, cc = m & 63;
#pragma unroll
            for (int j = 0; j < 8; j++) {
                int ng = ncol0 + wn + j * 8 + ccol;
                int h = ng >> 7, dv = ng & 127;
                size_t base = (((size_t)(bb * 8 + h) * 128 + nn) << 13) + (size_t)dv * 64 + cc;
                uint32_t hi, lo;
                split2(acc[i][j][0], acc[i][j][1], hi, lo);
                __nv_bfloat162 hp = *(__nv_bfloat162*)&hi;
                __nv_bfloat162 lp = *(__nv_bfloat162*)&lo;
                VTh[base] = hp.x; VTh[base + 64] = hp.y;
                VTl[base] = lp.x; VTl[base + 64] = lp.y;
                split2(acc[i][j][2], acc[i][j][3], hi, lo);
                hp = *(__nv_bfloat162*)&hi;
                lp = *(__nv_bfloat162*)&lo;
                VTh[base + 8] = hp.x; VTh[base + 72] = hp.y;
                VTl[base + 8] = lp.x; VTl[base + 72] = lp.y;
            }
        }
    } else {
        __nv_bfloat16* H = buf ? Khi : Qhi;
        __nv_bfloat16* L = buf ? Klo : Qlo;
#pragma unroll
        for (int i = 0; i < 2; i++) {
            int m = m0 + wm + i * 16 + crow;
#pragma unroll
            for (int j = 0; j < 8; j++) {
                int n = ncol0 + wn + j * 8 + ccol;
                uint32_t hi, lo;
                split2(acc[i][j][0], acc[i][j][1], hi, lo);
                *(uint32_t*)(H + (size_t)m * 1024 + n) = hi;
                *(uint32_t*)(L + (size_t)m * 1024 + n) = lo;
                split2(acc[i][j][2], acc[i][j][3], hi, lo);
                *(uint32_t*)(H + (size_t)(m + 8) * 1024 + n) = hi;
                *(uint32_t*)(L + (size_t)(m + 8) * 1024 + n) = lo;
            }
        }
    }
}

// ---------------------------------------------------------------------------
// Feature map via HMMA. Outputs chunk-tiled bf16 hi/lo:
//   natural: ON[cid][z][c][64]  (z = dk half)
//   if isK:  also OT[cid][dk][t]
// ---------------------------------------------------------------------------
#define FM_SMEM (131072 + 1024)

__global__ __launch_bounds__(256) void featmap_mma(
    const __nv_bfloat16* __restrict__ Xhi, const __nv_bfloat16* __restrict__ Xlo,
    const __nv_bfloat16* __restrict__ W1hi, const __nv_bfloat16* __restrict__ W1lo,
    const __nv_bfloat16* __restrict__ W2hi, const __nv_bfloat16* __restrict__ W2lo,
    const float* __restrict__ B1, const float* __restrict__ B2,
    __nv_bfloat16* __restrict__ ONh, __nv_bfloat16* __restrict__ ONl,
    __nv_bfloat16* __restrict__ OTh, __nv_bfloat16* __restrict__ OTl,
    float scale, int isK) {
    extern __shared__ char dynraw[];
    char* smem = (char*)(((uintptr_t)dynraw + 1023) & ~(uintptr_t)1023);
    const uint32_t sbase = smem_u32(smem);

    const int tid = threadIdx.x;
    const int wid = tid >> 5;
    const int lane = tid & 31;
    const int t0 = blockIdx.x * 128;
    const int h = blockIdx.y;
    const int z = blockIdx.z;
    const int wm = (wid & 3) * 32;
    const int wn = (wid >> 2) * 32;

    const __nv_bfloat16* wsel[4] = {W1hi, W1lo, W2hi, W2lo};

#pragma unroll
    for (int t = 0; t < 4; t++) {
        int half = t >> 1, hl = t & 1;
        const char* sp = (const char*)((hl ? Xlo : Xhi) +
                          (size_t)t0 * 1024 + h * 128 + half * 64);
#pragma unroll
        for (int l = 0; l < 4; l++) {
            int s = tid + 256 * l;
            int row = s >> 3, cb = (s & 7) * 16;
            cp_async16(sbase + t * 16384 + SWZ((uint32_t)(row * 128 + cb)),
                       sp + (size_t)row * 2048 + cb);
        }
    }
#pragma unroll
    for (int t = 0; t < 8; t++) {
        int half = t >> 2, wsub = (t >> 1) & 1, hl = t & 1;
        const char* sp = (const char*)wsel[wsub * 2 + hl] +
                         ((size_t)(z * 64) * 128 + half * 64) * 2;
#pragma unroll
        for (int l = 0; l < 2; l++) {
            int s = tid + 256 * l;
            int row = s >> 3, cb = (s & 7) * 16;
            cp_async16(sbase + 65536 + t * 8192 + SWZ((uint32_t)(row * 128 + cb)),
                       sp + (size_t)row * 256 + cb);
        }
    }
    CP_COMMIT();
    CP_WAIT0();
    __syncthreads();

    float acc1[2][4][4], acc2[2][4][4];
#pragma unroll
    for (int i = 0; i < 2; i++)
#pragma unroll
        for (int j = 0; j < 4; j++)
#pragma unroll
            for (int r = 0; r < 4; r++) { acc1[i][j][r] = 0.f; acc2[i][j][r] = 0.f; }

    const int mat = lane >> 3;
    const int mrow = lane & 7;

#pragma unroll
    for (int half = 0; half < 2; half++) {
        const uint32_t sXh = sbase + (half * 2 + 0) * 16384;
        const uint32_t sXl = sbase + (half * 2 + 1) * 16384;
        const uint32_t sW1h = sbase + 65536 + (half * 4 + 0) * 8192;
        const uint32_t sW1l = sbase + 65536 + (half * 4 + 1) * 8192;
        const uint32_t sW2h = sbase + 65536 + (half * 4 + 2) * 8192;
        const uint32_t sW2l = sbase + 65536 + (half * 4 + 3) * 8192;
#pragma unroll
        for (int kc = 0; kc < 4; kc++) {
            const int kb0 = kc * 32;
            uint32_t ah[2][4], al[2][4];
#pragma unroll
            for (int i = 0; i < 2; i++) {
                int arow = wm + i * 16 + (mat & 1) * 8 + mrow;
                int akb = kb0 + (mat >> 1) * 16;
                uint32_t off = SWZ((uint32_t)(arow * 128 + akb));
                ldsm_x4(sXh + off, ah[i][0], ah[i][1], ah[i][2], ah[i][3]);
                ldsm_x4(sXl + off, al[i][0], al[i][1], al[i][2], al[i][3]);
            }
#pragma unroll
            for (int p = 0; p < 2; p++) {
                int brow = wn + p * 16 + (mat >> 1) * 8 + mrow;
                int bkb = kb0 + (mat & 1) * 16;
                uint32_t off = SWZ((uint32_t)(brow * 128 + bkb));
                uint32_t b1h[4], b1l[4], b2h[4], b2l[4];
                ldsm_x4(sW1h + off, b1h[0], b1h[1], b1h[2], b1h[3]);
                ldsm_x4(sW1l + off, b1l[0], b1l[1], b1l[2], b1l[3]);
                ldsm_x4(sW2h + off, b2h[0], b2h[1], b2h[2], b2h[3]);
                ldsm_x4(sW2l + off, b2l[0], b2l[1], b2l[2], b2l[3]);
#pragma unroll
                for (int i = 0; i < 2; i++) {
                    mma_bf16(acc1[i][2 * p],     ah[i], &b1h[0]);
                    mma_bf16(acc1[i][2 * p],     al[i], &b1h[0]);
                    mma_bf16(acc1[i][2 * p],     ah[i], &b1l[0]);
                    mma_bf16(acc1[i][2 * p + 1], ah[i], &b1h[2]);
                    mma_bf16(acc1[i][2 * p + 1], al[i], &b1h[2]);
                    mma_bf16(acc1[i][2 * p + 1], ah[i], &b1l[2]);
                    mma_bf16(acc2[i][2 * p],     ah[i], &b2h[0]);
                    mma_bf16(acc2[i][2 * p],     al[i], &b2h[0]);
                    mma_bf16(acc2[i][2 * p],     ah[i], &b2l[0]);
                    mma_bf16(acc2[i][2 * p + 1], ah[i], &b2h[2]);
                    mma_bf16(acc2[i][2 * p + 1], al[i], &b2h[2]);
                    mma_bf16(acc2[i][2 * p + 1], ah[i], &b2l[2]);
                }
            }
        }
    }

    const int crow = lane >> 2;
    const int ccol = (lane & 3) * 2;
#pragma unroll
    for (int j = 0; j < 4; j++) {
        int d64 = wn + j * 8 + ccol;            // 0..63
        int nl = z * 64 + d64;
        float b1a = B1[nl], b1b = B1[nl + 1];
        float b2a = B2[nl], b2b = B2[nl + 1];
#pragma unroll
        for (int i = 0; i < 2; i++) {
#pragma unroll
            for (int rv = 0; rv < 2; rv++) {
                int m = t0 + wm + i * 16 + crow + rv * 8;
                float p0 = (acc1[i][j][rv * 2 + 0] + b1a) * (acc2[i][j][rv * 2 + 0] + b2a) * scale;
                float p1 = (acc1[i][j][rv * 2 + 1] + b1b) * (acc2[i][j][rv * 2 + 1] + b2b) * scale;
                uint32_t hi, lo;
                split2(p0, p1, hi, lo);
                int bb = m >> 13, nn = (m >> 6) & 127, cc = m & 63;
                size_t cidx = (size_t)(bb * 8 + h) * 128 + nn;
                size_t addrN = ((cidx * 2 + z) << 12) + cc * 64 + d64;
                *(uint32_t*)(ONh + addrN) = hi;
                *(uint32_t*)(ONl + addrN) = lo;
                if (isK) {
                    size_t addrT = (cidx << 13) + (size_t)nl * 64 + cc;
                    __nv_bfloat162 hp = *(__nv_bfloat162*)&hi;
                    __nv_bfloat162 lp = *(__nv_bfloat162*)&lo;
                    OTh[addrT] = hp.x; OTh[addrT + 64] = hp.y;
                    OTl[addrT] = lp.x; OTl[addrT + 64] = lp.y;
                }
            }
        }
    }
}

// ---------------------------------------------------------------------------
// chunk_kv via HMMA: KV^T[dv][dk] = sum_t V[t][dv] * K[t][dk]
// ---------------------------------------------------------------------------
#define CKV_SMEM (65536 + 1024)

__global__ __launch_bounds__(256) void chunk_kv_mma(
    const __nv_bfloat16* __restrict__ VTh, const __nv_bfloat16* __restrict__ VTl,
    const __nv_bfloat16* __restrict__ KTh, const __nv_bfloat16* __restrict__ KTl,
    float* __restrict__ KV) {
    extern __shared__ char dynraw[];
    char* smem = (char*)(((uintptr_t)dynraw + 1023) & ~(uintptr_t)1023);
    const uint32_t sbase = smem_u32(smem);
    const int tid = threadIdx.x;
    const int wid = tid >> 5;
    const int lane = tid & 31;
    const size_t cid = blockIdx.x;
    const int wm = (wid & 3) * 32;       // dv
    const int wn = (wid >> 2) * 64;      // dk

    load_tile_async(sbase + 0,     VTh + (cid << 13), 1024, tid);
    load_tile_async(sbase + 16384, VTl + (cid << 13), 1024, tid);
    load_tile_async(sbase + 32768, KTh + (cid << 13), 1024, tid);
    load_tile_async(sbase + 49152, KTl + (cid << 13), 1024, tid);
    CP_COMMIT();
    CP_WAIT0();
    __syncthreads();

    float acc[2][8][4];
#pragma unroll
    for (int i = 0; i < 2; i++)
#pragma unroll
        for (int j = 0; j < 8; j++)
#pragma unroll
            for (int r = 0; r < 4; r++) acc[i][j][r] = 0.f;

    const int mat = lane >> 3;
    const int mrow = lane & 7;

#pragma unroll
    for (int kc = 0; kc < 4; kc++) {
        const int kb0 = kc * 32;
        uint32_t ah[2][4], al[2][4];
#pragma unroll
        for (int i = 0; i < 2; i++) {
            int arow = wm + i * 16 + (mat & 1) * 8 + mrow;
            int akb = kb0 + (mat >> 1) * 16;
            uint32_t off = SWZ((uint32_t)(arow * 128 + akb));
            ldsm_x4(sbase + off,         ah[i][0], ah[i][1], ah[i][2], ah[i][3]);
            ldsm_x4(sbase + 16384 + off, al[i][0], al[i][1], al[i][2], al[i][3]);
        }
#pragma unroll
        for (int p = 0; p < 4; p++) {
            int brow = wn + p * 16 + (mat >> 1) * 8 + mrow;
            int bkb = kb0 + (mat & 1) * 16;
            uint32_t off = SWZ((uint32_t)(brow * 128 + bkb));
            uint32_t bh[4], bl[4];
            ldsm_x4(sbase + 32768 + off, bh[0], bh[1], bh[2], bh[3]);
            ldsm_x4(sbase + 49152 + off, bl[0], bl[1], bl[2], bl[3]);
#pragma unroll
            for (int i = 0; i < 2; i++) {
                mma_bf16(acc[i][2 * p],     ah[i], &bh[0]);
                mma_bf16(acc[i][2 * p],     al[i], &bh[0]);
                mma_bf16(acc[i][2 * p],     ah[i], &bl[0]);
                mma_bf16(acc[i][2 * p + 1], ah[i], &bh[2]);
                mma_bf16(acc[i][2 * p + 1], al[i], &bh[2]);
                mma_bf16(acc[i][2 * p + 1], ah[i], &bl[2]);
            }
        }
    }

    const int crow = lane >> 2;
    const int ccol = (lane & 3) * 2;
    const int hk = wn >> 6;
#pragma unroll
    for (int i = 0; i < 2; i++) {
#pragma unroll
        for (int rv = 0; rv < 2; rv++) {
            int dv = wm + i * 16 + crow + rv * 8;
#pragma unroll
            for (int j = 0; j < 8; j++) {
                int dk64 = (wn & 63) + j * 8 + ccol;
                size_t addr = (cid << 14) + hk * 8192 + (size_t)dv * 64 + dk64;
                *(float2*)(KV + addr) = make_float2(acc[i][j][rv * 2], acc[i][j][rv * 2 + 1]);
            }
        }
    }
}

// ---------------------------------------------------------------------------
__global__ void cumsum_split(const float* __restrict__ KV,
                             __nv_bfloat16* __restrict__ Sh,
                             __nv_bfloat16* __restrict__ Sl) {
    int bh = blockIdx.x;
    size_t i = blockIdx.y * 256 + threadIdx.x;
    float acc = 0.f;
    for (int n = 0; n < NCHUNK; n++) {
        size_t idx = (((size_t)bh * 128 + n) << 14) + i;
        float v = KV[idx];
        __nv_bfloat16 h = __float2bfloat16(acc);
        Sh[idx] = h;
        Sl[idx] = __float2bfloat16(acc - __bfloat162float(h));
        acc += v;
    }
}

// ---------------------------------------------------------------------------
// chunk attention via HMMA: A = Q K^T (masked), O = A V + Q S_excl.
// ---------------------------------------------------------------------------
#define CA_SMEM (180224 + 1024)

__global__ __launch_bounds__(256) void chunk_attn_mma(
    const __nv_bfloat16* __restrict__ QNh, const __nv_bfloat16* __restrict__ QNl,
    const __nv_bfloat16* __restrict__ KNh, const __nv_bfloat16* __restrict__ KNl,
    const __nv_bfloat16* __restrict__ VTh, const __nv_bfloat16* __restrict__ VTl,
    const __nv_bfloat16* __restrict__ Sh,  const __nv_bfloat16* __restrict__ Sl,
    float* __restrict__ O) {
    extern __shared__ char dynraw[];
    char* smem = (char*)(((uintptr_t)dynraw + 1023) & ~(uintptr_t)1023);
    const uint32_t sQh = smem_u32(smem);
    const uint32_t sQl = sQh + 16384;
    const uint32_t sKh = sQh + 32768;
    const uint32_t sKl = sQh + 49152;
    const uint32_t sVh = sQh + 65536;
    const uint32_t sVl = sQh + 81920;
    const uint32_t sSh = sQh + 98304;
    const uint32_t sSl = sQh + 131072;
    const uint32_t sAh = sQh + 163840;
    const uint32_t sAl = sQh + 172032;

    const int tid = threadIdx.x;
    const int wid = tid >> 5;
    const int lane = tid & 31;
    const size_t cid = blockIdx.x;
    const int n = cid & 127;
    const int h = (cid >> 7) & 7;
    const int b = (int)(cid >> 10);

    // group 1: Q, K
    load_tile_async(sQh, QNh + (cid << 13), 1024, tid);
    load_tile_async(sQl, QNl + (cid << 13), 1024, tid);
    load_tile_async(sKh, KNh + (cid << 13), 1024, tid);
    load_tile_async(sKl, KNl + (cid << 13), 1024, tid);
    CP_COMMIT();
    // group 2: VT, ST
    load_tile_async(sVh, VTh + (cid << 13), 1024, tid);
    load_tile_async(sVl, VTl + (cid << 13), 1024, tid);
    load_tile_async(sSh, Sh + (cid << 14), 2048, tid);
    load_tile_async(sSl, Sl + (cid << 14), 2048, tid);
    CP_COMMIT();
    CP_WAIT1();
    __syncthreads();

    const int mat = lane >> 3;
    const int mrow = lane & 7;
    const int crow = lane >> 2;
    const int ccol = (lane & 3) * 2;

    // ---- Step 1: A = Q K^T, warp tile 32x16
    {
        const int wm1 = (wid & 1) * 32;
        const int wn1 = (wid >> 1) * 16;
        float acc[2][2][4];
#pragma unroll
        for (int i = 0; i < 2; i++)
#pragma unroll
            for (int j = 0; j < 2; j++)
#pragma unroll
                for (int r = 0; r < 4; r++) acc[i][j][r] = 0.f;

#pragma unroll
        for (int kc = 0; kc < 8; kc++) {
            int rbase = (kc >> 2) * 64;
            int kb0 = (kc & 3) * 32;
            uint32_t ah[2][4], al[2][4];
#pragma unroll
            for (int i = 0; i < 2; i++) {
                int arow = rbase + wm1 + i * 16 + (mat & 1) * 8 + mrow;
                int akb = kb0 + (mat >> 1) * 16;
                uint32_t off = SWZ((uint32_t)(arow * 128 + akb));
                ldsm_x4(sQh + off, ah[i][0], ah[i][1], ah[i][2], ah[i][3]);
                ldsm_x4(sQl + off, al[i][0], al[i][1], al[i][2], al[i][3]);
            }
            int brow = rbase + wn1 + (mat >> 1) * 8 + mrow;
            int bkb = kb0 + (mat & 1) * 16;
            uint32_t off = SWZ((uint32_t)(brow * 128 + bkb));
            uint32_t bh[4], bl[4];
            ldsm_x4(sKh + off, bh[0], bh[1], bh[2], bh[3]);
            ldsm_x4(sKl + off, bl[0], bl[1], bl[2], bl[3]);
#pragma unroll
            for (int i = 0; i < 2; i++) {
                mma_bf16(acc[i][0], ah[i], &bh[0]);
                mma_bf16(acc[i][0], al[i], &bh[0]);
                mma_bf16(acc[i][0], ah[i], &bl[0]);
                mma_bf16(acc[i][1], ah[i], &bh[2]);
                mma_bf16(acc[i][1], al[i], &bh[2]);
                mma_bf16(acc[i][1], ah[i], &bl[2]);
            }
        }
        // mask + split + store A
#pragma unroll
        for (int i = 0; i < 2; i++) {
#pragma unroll
            for (int rv = 0; rv < 2; rv++) {
                int c = wm1 + i * 16 + crow + rv * 8;
#pragma unroll
                for (int j = 0; j < 2; j++) {
                    int s = wn1 + j * 8 + ccol;
                    float v0 = (s <= c)     ? acc[i][j][rv * 2 + 0] : 0.f;
                    float v1 = (s + 1 <= c) ? acc[i][j][rv * 2 + 1] : 0.f;
                    uint32_t hi, lo;
                    split2(v0, v1, hi, lo);
                    uint32_t off = SWZ((uint32_t)(c * 128 + s * 2));
                    asm volatile("st.shared.b32 [%0], %1;" :: "r"(sAh + off), "r"(hi));
                    asm volatile("st.shared.b32 [%0], %1;" :: "r"(sAl + off), "r"(lo));
                }
            }
        }
    }
    CP_WAIT0();
    __syncthreads();

    // ---- Step 2: O = A V + Q S, warp tile 32x32
    const int wm2 = (wid & 1) * 32;
    const int wn2 = (wid >> 1) * 32;
    float acc[2][4][4];
#pragma unroll
    for (int i = 0; i < 2; i++)
#pragma unroll
        for (int j = 0; j < 4; j++)
#pragma unroll
            for (int r = 0; r < 4; r++) acc[i][j][r] = 0.f;

    // 2a: A @ V  (K = 64 over s)
#pragma unroll
    for (int kc = 0; kc < 4; kc++) {
        int kb0 = kc * 32;
        uint32_t ah[2][4], al[2][4];
#pragma unroll
        for (int i = 0; i < 2; i++) {
            int arow = wm2 + i * 16 + (mat & 1) * 8 + mrow;
            int akb = kb0 + (mat >> 1) * 16;
            uint32_t off = SWZ((uint32_t)(arow * 128 + akb));
            ldsm_x4(sAh + off, ah[i][0], ah[i][1], ah[i][2], ah[i][3]);
            ldsm_x4(sAl + off, al[i][0], al[i][1], al[i][2], al[i][3]);
        }
#pragma unroll
        for (int p = 0; p < 2; p++) {
            int brow = wn2 + p * 16 + (mat >> 1) * 8 + mrow;
            int bkb = kb0 + (mat & 1) * 16;
            uint32_t off = SWZ((uint32_t)(brow * 128 + bkb));
            uint32_t bh[4], bl[4];
            ldsm_x4(sVh + off, bh[0], bh[1], bh[2], bh[3]);
            ldsm_x4(sVl + off, bl[0], bl[1], bl[2], bl[3]);
#pragma unroll
            for (int i = 0; i < 2; i++) {
                mma_bf16(acc[i][2 * p],     ah[i], &bh[0]);
                mma_bf16(acc[i][2 * p],     al[i], &bh[0]);
                mma_bf16(acc[i][2 * p],     ah[i], &bl[0]);
                mma_bf16(acc[i][2 * p + 1], ah[i], &bh[2]);
                mma_bf16(acc[i][2 * p + 1], al[i], &bh[2]);
                mma_bf16(acc[i][2 * p + 1], ah[i], &bl[2]);
            }
        }
    }
    // 2b: Q @ S  (K = 128 over dk)
#pragma unroll
    for (int kc = 0; kc < 8; kc++) {
        int qrbase = (kc >> 2) * 64;
        int srbase = (kc >> 2) * 128;
        int kb0 = (kc & 3) * 32;
        uint32_t ah[2][4], al[2][4];
#pragma unroll
        for (int i = 0; i < 2; i++) {
            int arow = qrbase + wm2 + i * 16 + (mat & 1) * 8 + mrow;
            int akb = kb0 + (mat >> 1) * 16;
            uint32_t off = SWZ((uint32_t)(arow * 128 + akb));
            ldsm_x4(sQh + off, ah[i][0], ah[i][1], ah[i][2], ah[i][3]);
            ldsm_x4(sQl + off, al[i][0], al[i][1], al[i][2], al[i][3]);
        }
#pragma unroll
        for (int p = 0; p < 2; p++) {
            int brow = srbase + wn2 + p * 16 + (mat >> 1) * 8 + mrow;
            int bkb = kb0 + (mat & 1) * 16;
            uint32_t off = SWZ((uint32_t)(brow * 128 + bkb));
            uint32_t bh[4], bl[4];
            ldsm_x4(sSh + off, bh[0], bh[1], bh[2], bh[3]);
            ldsm_x4(sSl + off, bl[0], bl[1], bl[2], bl[3]);
#pragma unroll
            for (int i = 0; i < 2; i++) {
                mma_bf16(acc[i][2 * p],     ah[i], &bh[0]);
                mma_bf16(acc[i][2 * p],     al[i], &bh[0]);
                mma_bf16(acc[i][2 * p],     ah[i], &bl[0]);
                mma_bf16(acc[i][2 * p + 1], ah[i], &bh[2]);
                mma_bf16(acc[i][2 * p + 1], al[i], &bh[2]);
                mma_bf16(acc[i][2 * p + 1], ah[i], &bl[2]);
            }
        }
    }

    // write O (f32, [t][1024])
    const size_t tbase = (size_t)b * 8192 + (size_t)n * 64;
#pragma unroll
    for (int i = 0; i < 2; i++) {
#pragma unroll
        for (int rv = 0; rv < 2; rv++) {
            size_t t = tbase + wm2 + i * 16 + crow + rv * 8;
#pragma unroll
            for (int j = 0; j < 4; j++) {
                int dv = wn2 + j * 8 + ccol;
                *(float2*)(O + t * 1024 + h * 128 + dv) =
                    make_float2(acc[i][j][rv * 2], acc[i][j][rv * 2 + 1]);
            }
        }
    }
}

// ---------------------------------------------------------------------------
__global__ void rmsnorm_split(const float* __restrict__ O, const float* __restrict__ W,
                              __nv_bfloat16* __restrict__ hi, __nv_bfloat16* __restrict__ lo) {
    int row = blockIdx.x * 8 + threadIdx.y;
    int t = row / NH, h = row % NH;
    int lane = threadIdx.x;
    size_t base = (size_t)t * DMODEL + h * DHD + lane * 4;
    float4 x = *(const float4*)(O + base);
    float ss = x.x * x.x + x.y * x.y + x.z * x.z + x.w * x.w;
#pragma unroll
    for (int off = 16; off > 0; off >>= 1)
        ss += __shfl_xor_sync(0xffffffffu, ss, off);
    float r = rsqrtf(ss * (1.0f / 128.0f) + RMSEPS);
    float4 w = *(const float4*)(W + lane * 4);
    x.x *= r * w.x; x.y *= r * w.y; x.z *= r * w.z; x.w *= r * w.w;
    uint32_t h0, l0, h1, l1;
    split2(x.x, x.y, h0, l0);
    split2(x.z, x.w, h1, l1);
    *(uint2*)(hi + base) = make_uint2(h0, h1);
    *(uint2*)(lo + base) = make_uint2(l0, l1);
}

// ---------------------------------------------------------------------------
extern "C" void kernel_launch(void* const* d_in, const int* in_sizes, int n_in,
                              void* d_out, int out_size) {
    const float* hidden = (const float*)d_in[0];
    const float* q_w    = (const float*)d_in[2];
    const float* k_w    = (const float*)d_in[3];
    const float* v_w    = (const float*)d_in[4];
    const float* o_w    = (const float*)d_in[5];
    const float* fmq_w1 = (const float*)d_in[6];
    const float* fmq_b1 = (const float*)d_in[7];
    const float* fmq_w2 = (const float*)d_in[8];
    const float* fmq_b2 = (const float*)d_in[9];
    const float* fmk_w1 = (const float*)d_in[10];
    const float* fmk_b1 = (const float*)d_in[11];
    const float* fmk_w2 = (const float*)d_in[12];
    const float* fmk_b2 = (const float*)d_in[13];
    const float* rms_w  = (const float*)d_in[14];
    float* out = (float*)d_out;

    float *o, *kv;
    __nv_bfloat16 *ahi, *alo, *whi, *wlo, *qhi, *qlo, *khi, *klo, *fwhi, *fwlo;
    __nv_bfloat16 *qnh, *qnl, *knh, *knl, *kth, *ktl, *vth, *vtl, *sh, *sl;
    cudaGetSymbolAddress((void**)&o,    g_o);
    cudaGetSymbolAddress((void**)&kv,   g_kv);
    cudaGetSymbolAddress((void**)&ahi,  g_ahi);
    cudaGetSymbolAddress((void**)&alo,  g_alo);
    cudaGetSymbolAddress((void**)&whi,  g_whi);
    cudaGetSymbolAddress((void**)&wlo,  g_wlo);
    cudaGetSymbolAddress((void**)&qhi,  g_qhi);
    cudaGetSymbolAddress((void**)&qlo,  g_qlo);
    cudaGetSymbolAddress((void**)&khi,  g_khi);
    cudaGetSymbolAddress((void**)&klo,  g_klo);
    cudaGetSymbolAddress((void**)&fwhi, g_fwhi);
    cudaGetSymbolAddress((void**)&fwlo, g_fwlo);
    cudaGetSymbolAddress((void**)&qnh,  g_qnh);
    cudaGetSymbolAddress((void**)&qnl,  g_qnl);
    cudaGetSymbolAddress((void**)&knh,  g_knh);
    cudaGetSymbolAddress((void**)&knl,  g_knl);
    cudaGetSymbolAddress((void**)&kth,  g_kth);
    cudaGetSymbolAddress((void**)&ktl,  g_ktl);
    cudaGetSymbolAddress((void**)&vth,  g_vth);
    cudaGetSymbolAddress((void**)&vtl,  g_vtl);
    cudaGetSymbolAddress((void**)&sh,   g_sh);
    cudaGetSymbolAddress((void**)&sl,   g_sl);

    cudaFuncSetAttribute(gemm_mma2, cudaFuncAttributeMaxDynamicSharedMemorySize, GEMM_SMEM_BYTES);
    cudaFuncSetAttribute(featmap_mma, cudaFuncAttributeMaxDynamicSharedMemorySize, FM_SMEM);
    cudaFuncSetAttribute(chunk_kv_mma, cudaFuncAttributeMaxDynamicSharedMemorySize, CKV_SMEM);
    cudaFuncSetAttribute(chunk_attn_mma, cudaFuncAttributeMaxDynamicSharedMemorySize, CA_SMEM);

    const int nA = BT * DMODEL;
    const int nW = DMODEL * DMODEL;
    const int nF = DHD * DHD;

    // Splits (8 elems/thread)
    split_f32<<<nA / 2048, 256>>>(hidden, ahi, alo, nA);
    split_f32<<<nW / 2048, 256>>>(q_w, whi,          wlo,          nW);
    split_f32<<<nW / 2048, 256>>>(k_w, whi + nW,     wlo + nW,     nW);
    split_f32<<<nW / 2048, 256>>>(v_w, whi + 2 * nW, wlo + 2 * nW, nW);
    split_f32<<<nF / 2048, 256>>>(fmq_w1, fwhi,          fwlo,          nF);
    split_f32<<<nF / 2048, 256>>>(fmq_w2, fwhi + nF,     fwlo + nF,     nF);
    split_f32<<<nF / 2048, 256>>>(fmk_w1, fwhi + 2 * nF, fwlo + 2 * nF, nF);
    split_f32<<<nF / 2048, 256>>>(fmk_w2, fwhi + 3 * nF, fwlo + 3 * nF, nF);

    // QKV projection: q/k natural bf16 splits, v -> chunk-transposed VT
    gemm_mma2<<<dim3(24, 128), 256, GEMM_SMEM_BYTES>>>(
        ahi, alo, whi, wlo, qhi, qlo, khi, klo, vth, vtl, nullptr, 0);

    // Feature maps -> chunk-tiled layouts
    dim3 fm_grid(BT / 128, NH, 2);
    featmap_mma<<<fm_grid, 256, FM_SMEM>>>(qhi, qlo, fwhi, fwlo, fwhi + nF, fwlo + nF,
                                           fmq_b1, fmq_b2, qnh, qnl, nullptr, nullptr,
                                           QSCALE, 0);
    featmap_mma<<<fm_grid, 256, FM_SMEM>>>(khi, klo, fwhi + 2 * nF, fwlo + 2 * nF,
                                           fwhi + 3 * nF, fwlo + 3 * nF,
                                           fmk_b1, fmk_b2, knh, knl, kth, ktl,
                                           1.0f, 1);

    // Chunked linear attention (all HMMA)
    chunk_kv_mma<<<NCHTOT, 256, CKV_SMEM>>>(vth, vtl, kth, ktl, kv);
    cumsum_split<<<dim3(NBATCH * NH, 64), 256>>>(kv, sh, sl);
    chunk_attn_mma<<<NCHTOT, 256, CA_SMEM>>>(qnh, qnl, knh, knl, vth, vtl, sh, sl, o);

    // RMSNorm + split, then output projection
    rmsnorm_split<<<(BT * NH) / 8, dim3(32, 8)>>>(o, rms_w, ahi, alo);
    split_f32<<<nW / 2048, 256>>>(o_w, whi, wlo, nW);
    gemm_mma2<<<dim3(8, 128), 256, GEMM_SMEM_BYTES>>>(
        ahi, alo, whi, wlo, nullptr, nullptr, nullptr, nullptr, nullptr, nullptr, out, 1);
}